// round 1
// baseline (speedup 1.0000x reference)
#include <cuda_runtime.h>
#include <cstdint>

#define SEQ   2048
#define BATCH 2
#define DMODEL 1024
#define NH    16
#define QKVLD 3072

// ---------------- scratch (static device globals; no allocation) -------------
__device__ float g_wqkv[1024u * 3072u];       // repacked [D, 3*D] QKV weight
__device__ float g_qkv [4096u * 3072u];       // fused qkv activations
__device__ float g_o   [4096u * 1024u];       // attention output (concat heads)
__device__ float g_t1  [4096u * 1024u];       // attn_out + x
__device__ float g_x1  [4096u * 1024u];       // LN1 output
__device__ float g_h   [4096u * 4096u];       // FFN hidden
__device__ float g_t2  [4096u * 1024u];       // ffn + x1

// ---------------- repack Wq/Wk/Wv (H,D,64) -> Wqkv[D][3*1024] ----------------
__global__ void repack_qkv(const float* __restrict__ Wq, const float* __restrict__ Wk,
                           const float* __restrict__ Wv, float* __restrict__ Wqkv)
{
    int idx = blockIdx.x * blockDim.x + threadIdx.x;   // 0 .. 3*2^20-1
    int w   = idx >> 20;
    int rem = idx & 1048575;                           // h*65536 + d*64 + k
    int h   = rem >> 16;
    int d   = (rem >> 6) & 1023;
    int k   = rem & 63;
    const float* src = (w == 0) ? Wq : (w == 1) ? Wk : Wv;
    Wqkv[(size_t)d * QKVLD + w * 1024 + h * 64 + k] = src[rem];
}

// ---------------- 128x128x8 SGEMM, 8x8 per thread, fused epilogue ------------
// A [M,K] row-major, B [K,N] row-major, C [M,N] row-major. M,N mult of 128, K mult of 8.
__global__ __launch_bounds__(256) void sgemm128(
    const float* __restrict__ A, const float* __restrict__ B, float* __restrict__ C,
    int M, int N, int K,
    const float* __restrict__ bias, const float* __restrict__ res, int relu)
{
    __shared__ float As[8][128];
    __shared__ float Bs[8][128];

    const int tid = threadIdx.x;
    const int m0  = blockIdx.y * 128;
    const int n0  = blockIdx.x * 128;
    const int row = (tid >> 4) * 8;        // 0..120
    const int col = (tid & 15) * 8;        // 0..120

    const int arow = tid >> 1;             // 0..127
    const int ac4  = (tid & 1) * 4;        // 0 or 4
    const int brow = tid >> 5;             // 0..7
    const int bc4  = (tid & 31) * 4;       // 0..124

    const float* Ap = A + (size_t)(m0 + arow) * K + ac4;
    const float* Bp = B + (size_t)brow * N + n0 + bc4;

    float acc[8][8];
#pragma unroll
    for (int i = 0; i < 8; i++)
#pragma unroll
        for (int j = 0; j < 8; j++) acc[i][j] = 0.f;

    for (int kk = 0; kk < K; kk += 8) {
        float4 av = *(const float4*)(Ap + kk);
        float4 bv = *(const float4*)(Bp + (size_t)kk * N);
        __syncthreads();
        As[ac4 + 0][arow] = av.x;
        As[ac4 + 1][arow] = av.y;
        As[ac4 + 2][arow] = av.z;
        As[ac4 + 3][arow] = av.w;
        *(float4*)&Bs[brow][bc4] = bv;
        __syncthreads();
#pragma unroll
        for (int k = 0; k < 8; k++) {
            float4 a0 = *(const float4*)&As[k][row];
            float4 a1 = *(const float4*)&As[k][row + 4];
            float4 b0 = *(const float4*)&Bs[k][col];
            float4 b1 = *(const float4*)&Bs[k][col + 4];
            float a[8] = {a0.x, a0.y, a0.z, a0.w, a1.x, a1.y, a1.z, a1.w};
            float b[8] = {b0.x, b0.y, b0.z, b0.w, b1.x, b1.y, b1.z, b1.w};
#pragma unroll
            for (int i = 0; i < 8; i++)
#pragma unroll
                for (int j = 0; j < 8; j++) acc[i][j] += a[i] * b[j];
        }
    }

#pragma unroll
    for (int i = 0; i < 8; i++) {
        size_t off = (size_t)(m0 + row + i) * N + n0 + col;
        float v[8];
#pragma unroll
        for (int j = 0; j < 8; j++) {
            float t = acc[i][j];
            if (bias) t += bias[n0 + col + j];
            if (relu) t = fmaxf(t, 0.f);
            if (res)  t += res[off + j];
            v[j] = t;
        }
        *(float4*)&C[off]     = make_float4(v[0], v[1], v[2], v[3]);
        *(float4*)&C[off + 4] = make_float4(v[4], v[5], v[6], v[7]);
    }
}

// ---------------- flash attention: 64q x 64k tiles, online softmax -----------
// qkv layout: [(b*SEQ+s)*3072 + {0,1024,2048} + h*64 + d]; out: [(b*SEQ+s)*1024 + h*64 + v]
__global__ __launch_bounds__(256) void flash_attn(const float* __restrict__ qkv,
                                                  float* __restrict__ out)
{
    __shared__ float Qt[64 * 64];   // Qt[d][q], pre-scaled by 1/8
    __shared__ float Vs[64 * 64];   // Vs[t][v]
    __shared__ float KP[64 * 64];   // Kt[d][t] during S; Ps[q][t] during PV

    const int tid = threadIdx.x;
    const int ty  = tid >> 4;       // 0..15 -> query rows 4*ty..4*ty+3
    const int tx  = tid & 15;       // 0..15 -> cols 4*tx..4*tx+3
    const int qt  = blockIdx.x;
    const int h   = blockIdx.y;
    const int b   = blockIdx.z;
    const int q0  = qt * 64;

    const size_t base  = (size_t)b * SEQ * QKVLD;
    const float* qbase = qkv + base + (size_t)q0 * QKVLD + h * 64;
    const float* kbase = qkv + base + 1024 + h * 64;
    const float* vbase = qkv + base + 2048 + h * 64;

    // load Q transposed + scaled (conflict-free scatter stores)
#pragma unroll
    for (int it = 0; it < 4; it++) {
        int idx = it * 256 + tid;
        int d4 = idx >> 6, r = idx & 63;
        float4 v = *(const float4*)(qbase + (size_t)r * QKVLD + 4 * d4);
        Qt[(4 * d4 + 0) * 64 + r] = v.x * 0.125f;
        Qt[(4 * d4 + 1) * 64 + r] = v.y * 0.125f;
        Qt[(4 * d4 + 2) * 64 + r] = v.z * 0.125f;
        Qt[(4 * d4 + 3) * 64 + r] = v.w * 0.125f;
    }

    float m[4], l[4], acc[4][4];
#pragma unroll
    for (int i = 0; i < 4; i++) {
        m[i] = -1e30f; l[i] = 0.f;
#pragma unroll
        for (int j = 0; j < 4; j++) acc[i][j] = 0.f;
    }

    for (int kt = 0; kt < SEQ / 64; kt++) {
        __syncthreads();   // prev PV done before overwriting KP/Vs
        // K tile -> KP transposed
#pragma unroll
        for (int it = 0; it < 4; it++) {
            int idx = it * 256 + tid;
            int d4 = idx >> 6, r = idx & 63;
            float4 v = *(const float4*)(kbase + (size_t)(kt * 64 + r) * QKVLD + 4 * d4);
            KP[(4 * d4 + 0) * 64 + r] = v.x;
            KP[(4 * d4 + 1) * 64 + r] = v.y;
            KP[(4 * d4 + 2) * 64 + r] = v.z;
            KP[(4 * d4 + 3) * 64 + r] = v.w;
        }
        // V tile -> Vs natural
#pragma unroll
        for (int it = 0; it < 4; it++) {
            int idx = it * 256 + tid;
            int t = idx >> 4, d4 = idx & 15;
            *(float4*)&Vs[t * 64 + 4 * d4] =
                *(const float4*)(vbase + (size_t)(kt * 64 + t) * QKVLD + 4 * d4);
        }
        __syncthreads();

        // S = Q K^T (scaled)
        float s[4][4];
#pragma unroll
        for (int i = 0; i < 4; i++)
#pragma unroll
            for (int j = 0; j < 4; j++) s[i][j] = 0.f;
#pragma unroll 8
        for (int d = 0; d < 64; d++) {
            float4 a  = *(const float4*)&Qt[d * 64 + 4 * ty];
            float4 bf = *(const float4*)&KP[d * 64 + 4 * tx];
            s[0][0] += a.x * bf.x; s[0][1] += a.x * bf.y; s[0][2] += a.x * bf.z; s[0][3] += a.x * bf.w;
            s[1][0] += a.y * bf.x; s[1][1] += a.y * bf.y; s[1][2] += a.y * bf.z; s[1][3] += a.y * bf.w;
            s[2][0] += a.z * bf.x; s[2][1] += a.z * bf.y; s[2][2] += a.z * bf.z; s[2][3] += a.z * bf.w;
            s[3][0] += a.w * bf.x; s[3][1] += a.w * bf.y; s[3][2] += a.w * bf.z; s[3][3] += a.w * bf.w;
        }
        __syncthreads();   // all Kt reads done before Ps overwrites KP

        // online softmax + store P
#pragma unroll
        for (int i = 0; i < 4; i++) {
            float mx = fmaxf(fmaxf(s[i][0], s[i][1]), fmaxf(s[i][2], s[i][3]));
#pragma unroll
            for (int off = 8; off > 0; off >>= 1)
                mx = fmaxf(mx, __shfl_xor_sync(0xffffffffu, mx, off, 16));
            float nm    = fmaxf(m[i], mx);
            float alpha = __expf(m[i] - nm);
            float4 p;
            p.x = __expf(s[i][0] - nm);
            p.y = __expf(s[i][1] - nm);
            p.z = __expf(s[i][2] - nm);
            p.w = __expf(s[i][3] - nm);
            float rs = p.x + p.y + p.z + p.w;
#pragma unroll
            for (int off = 8; off > 0; off >>= 1)
                rs += __shfl_xor_sync(0xffffffffu, rs, off, 16);
            l[i] = l[i] * alpha + rs;
            m[i] = nm;
            acc[i][0] *= alpha; acc[i][1] *= alpha; acc[i][2] *= alpha; acc[i][3] *= alpha;
            *(float4*)&KP[(4 * ty + i) * 64 + 4 * tx] = p;   // Ps[q][t], conflict-free
        }
        __syncthreads();

        // O += P V
#pragma unroll 8
        for (int t = 0; t < 64; t++) {
            float4 bv = *(const float4*)&Vs[t * 64 + 4 * tx];
#pragma unroll
            for (int i = 0; i < 4; i++) {
                float a = KP[(4 * ty + i) * 64 + t];
                acc[i][0] += a * bv.x; acc[i][1] += a * bv.y;
                acc[i][2] += a * bv.z; acc[i][3] += a * bv.w;
            }
        }
    }

#pragma unroll
    for (int i = 0; i < 4; i++) {
        float inv = 1.f / l[i];
        float4 o = make_float4(acc[i][0] * inv, acc[i][1] * inv,
                               acc[i][2] * inv, acc[i][3] * inv);
        *(float4*)&out[(size_t)(b * SEQ + q0 + 4 * ty + i) * 1024 + h * 64 + 4 * tx] = o;
    }
}

// ---------------- layernorm over D=1024 per row ------------------------------
__global__ __launch_bounds__(256) void ln_kernel(const float* __restrict__ in,
                                                 const float* __restrict__ gamma,
                                                 const float* __restrict__ beta,
                                                 float* __restrict__ out)
{
    const int row = blockIdx.x, tid = threadIdx.x;
    const float* p = in + (size_t)row * 1024;
    float4 v = *(const float4*)(p + tid * 4);
    float s  = v.x + v.y + v.z + v.w;
    float ss = v.x * v.x + v.y * v.y + v.z * v.z + v.w * v.w;
#pragma unroll
    for (int off = 16; off > 0; off >>= 1) {
        s  += __shfl_xor_sync(0xffffffffu, s,  off);
        ss += __shfl_xor_sync(0xffffffffu, ss, off);
    }
    __shared__ float sb[8], ssb[8];
    __shared__ float smu, sinv;
    if ((tid & 31) == 0) { sb[tid >> 5] = s; ssb[tid >> 5] = ss; }
    __syncthreads();
    if (tid == 0) {
        float S = 0.f, SS = 0.f;
#pragma unroll
        for (int i = 0; i < 8; i++) { S += sb[i]; SS += ssb[i]; }
        float mu  = S * (1.f / 1024.f);
        float var = SS * (1.f / 1024.f) - mu * mu;
        smu = mu; sinv = rsqrtf(var + 1e-5f);
    }
    __syncthreads();
    float mu = smu, inv = sinv;
    float4 g = *(const float4*)(gamma + tid * 4);
    float4 b = *(const float4*)(beta  + tid * 4);
    float4 o;
    o.x = (v.x - mu) * inv * g.x + b.x;
    o.y = (v.y - mu) * inv * g.y + b.y;
    o.z = (v.z - mu) * inv * g.z + b.z;
    o.w = (v.w - mu) * inv * g.w + b.w;
    *(float4*)&out[(size_t)row * 1024 + tid * 4] = o;
}

// ---------------- launch ------------------------------------------------------
extern "C" void kernel_launch(void* const* d_in, const int* in_sizes, int n_in,
                              void* d_out, int out_size)
{
    const float* x     = (const float*)d_in[0];
    const float* Wq    = (const float*)d_in[1];
    const float* Wk    = (const float*)d_in[2];
    const float* Wv    = (const float*)d_in[3];
    const float* Wo    = (const float*)d_in[4];
    const float* ln1_g = (const float*)d_in[5];
    const float* ln1_b = (const float*)d_in[6];
    const float* W1    = (const float*)d_in[7];
    const float* b1    = (const float*)d_in[8];
    const float* W2    = (const float*)d_in[9];
    const float* b2    = (const float*)d_in[10];
    const float* ln2_g = (const float*)d_in[11];
    const float* ln2_b = (const float*)d_in[12];
    float* out = (float*)d_out;

    float *wqkv, *qkv, *obuf, *t1, *x1, *hbuf, *t2;
    cudaGetSymbolAddress((void**)&wqkv, g_wqkv);
    cudaGetSymbolAddress((void**)&qkv,  g_qkv);
    cudaGetSymbolAddress((void**)&obuf, g_o);
    cudaGetSymbolAddress((void**)&t1,   g_t1);
    cudaGetSymbolAddress((void**)&x1,   g_x1);
    cudaGetSymbolAddress((void**)&hbuf, g_h);
    cudaGetSymbolAddress((void**)&t2,   g_t2);

    // 1. repack QKV weights -> [1024, 3072]
    repack_qkv<<<12288, 256>>>(Wq, Wk, Wv, wqkv);
    // 2. fused QKV projection: [4096,1024] @ [1024,3072]
    sgemm128<<<dim3(24, 32), 256>>>(x, wqkv, qkv, 4096, 3072, 1024, nullptr, nullptr, 0);
    // 3. attention
    flash_attn<<<dim3(32, NH, BATCH), 256>>>(qkv, obuf);
    // 4. output projection + residual x
    sgemm128<<<dim3(8, 32), 256>>>(obuf, Wo, t1, 4096, 1024, 1024, nullptr, x, 0);
    // 5. LN1
    ln_kernel<<<4096, 256>>>(t1, ln1_g, ln1_b, x1);
    // 6. FFN up + bias + relu
    sgemm128<<<dim3(32, 32), 256>>>(x1, W1, hbuf, 4096, 4096, 1024, b1, nullptr, 1);
    // 7. FFN down + bias + residual x1
    sgemm128<<<dim3(8, 32), 256>>>(hbuf, W2, t2, 4096, 1024, 4096, b2, x1, 0);
    // 8. LN2 -> output
    ln_kernel<<<4096, 256>>>(t2, ln2_g, ln2_b, out);
}

// round 3
// speedup vs baseline: 1.8463x; 1.8463x over previous
#include <cuda_runtime.h>
#include <cuda_bf16.h>
#include <cstdint>

#define SEQ    2048
#define BATCH  2
#define NH     16
#define QKVLD  3072
#define STAGES 3
#define STAGE_BYTES 65536
#define GEMM_SMEM (STAGES * STAGE_BYTES + 1024)

// ---------------- scratch (static device globals; no allocation) -------------
__device__ float          g_wqkv [1024u * 3072u];
__device__ __nv_bfloat16  g_wqkvh[3072u * 1024u], g_wqkvl[3072u * 1024u];
__device__ __nv_bfloat16  g_xh   [4096u * 1024u], g_xl   [4096u * 1024u];
__device__ float          g_qkv  [4096u * 3072u];
__device__ __nv_bfloat16  g_oh   [4096u * 1024u], g_ol   [4096u * 1024u];
__device__ __nv_bfloat16  g_woh  [1024u * 1024u], g_wol  [1024u * 1024u];
__device__ float          g_t1   [4096u * 1024u];
__device__ float          g_x1   [4096u * 1024u];
__device__ __nv_bfloat16  g_x1h  [4096u * 1024u], g_x1l  [4096u * 1024u];
__device__ __nv_bfloat16  g_w1h  [4096u * 1024u], g_w1l  [4096u * 1024u];
__device__ __nv_bfloat16  g_hh   [4096u * 4096u], g_hl   [4096u * 4096u];
__device__ __nv_bfloat16  g_w2h  [1024u * 4096u], g_w2l  [1024u * 4096u];
__device__ float          g_t2   [4096u * 1024u];

// ---------------- PTX helpers (sm_80-safe subset only) ------------------------
__device__ __forceinline__ uint32_t smem_u32(const void* p) {
    uint32_t a;
    asm("{ .reg .u64 t; cvta.to.shared.u64 t, %1; cvt.u32.u64 %0, t; }" : "=r"(a) : "l"(p));
    return a;
}
__device__ __forceinline__ void cp16(uint32_t s, const void* g) {
    asm volatile("cp.async.cg.shared.global [%0], [%1], 16;" :: "r"(s), "l"(g));
}
#define CP_COMMIT()  asm volatile("cp.async.commit_group;" ::: "memory")
#define CP_WAIT(n)   asm volatile("cp.async.wait_group %0;" :: "n"(n) : "memory")

__device__ __forceinline__ void ldsm4(uint32_t& r0, uint32_t& r1, uint32_t& r2, uint32_t& r3,
                                      uint32_t addr) {
    asm volatile("ldmatrix.sync.aligned.m8n8.x4.shared.b16 {%0,%1,%2,%3}, [%4];"
                 : "=r"(r0), "=r"(r1), "=r"(r2), "=r"(r3) : "r"(addr));
}
__device__ __forceinline__ void mma16816(float* d, const uint32_t* a, const uint32_t* b) {
    asm volatile(
        "mma.sync.aligned.m16n8k16.row.col.f32.bf16.bf16.f32 "
        "{%0,%1,%2,%3}, {%4,%5,%6,%7}, {%8,%9}, {%0,%1,%2,%3};"
        : "+f"(d[0]), "+f"(d[1]), "+f"(d[2]), "+f"(d[3])
        : "r"(a[0]), "r"(a[1]), "r"(a[2]), "r"(a[3]), "r"(b[0]), "r"(b[1]));
}
__device__ __forceinline__ void bf16split(float v, __nv_bfloat16& h, __nv_bfloat16& l) {
    h = __float2bfloat16(v);
    l = __float2bfloat16(v - __bfloat162float(h));
}

// ---------------- prep kernels -----------------------------------------------
__global__ void repack_qkv(const float* __restrict__ Wq, const float* __restrict__ Wk,
                           const float* __restrict__ Wv, float* __restrict__ Wqkv)
{
    int idx = blockIdx.x * blockDim.x + threadIdx.x;
    int w   = idx >> 20;
    int rem = idx & 1048575;
    int h   = rem >> 16;
    int d   = (rem >> 6) & 1023;
    int k   = rem & 63;
    const float* src = (w == 0) ? Wq : (w == 1) ? Wk : Wv;
    Wqkv[(size_t)d * QKVLD + w * 1024 + h * 64 + k] = src[rem];
}

// in [Rk, Cn] f32 row-major -> out hi/lo [Cn, Rk] bf16
__global__ void transpose_split(const float* __restrict__ in, int Rk, int Cn,
                                __nv_bfloat16* __restrict__ oh, __nv_bfloat16* __restrict__ ol)
{
    __shared__ float t[32][33];
    int c0 = blockIdx.x * 32, r0 = blockIdx.y * 32;
    for (int i = threadIdx.y; i < 32; i += 8)
        t[i][threadIdx.x] = in[(size_t)(r0 + i) * Cn + c0 + threadIdx.x];
    __syncthreads();
    for (int i = threadIdx.y; i < 32; i += 8) {
        float v = t[threadIdx.x][i];
        __nv_bfloat16 hh, ll; bf16split(v, hh, ll);
        size_t o = (size_t)(c0 + i) * Rk + r0 + threadIdx.x;
        oh[o] = hh; ol[o] = ll;
    }
}

__global__ void split_plain(const float* __restrict__ in,
                            __nv_bfloat16* __restrict__ oh, __nv_bfloat16* __restrict__ ol)
{
    int idx = blockIdx.x * blockDim.x + threadIdx.x;
    __nv_bfloat16 hh, ll; bf16split(in[idx], hh, ll);
    oh[idx] = hh; ol[idx] = ll;
}

// ---------------- mma.sync bf16x3 GEMM: C = (Ah+Al)(Bh+Bl)^T ------------------
// A [M,K], B [N,K], bf16 hi/lo. Tile 128x128x64, 8 warps (2m x 4n), warp 64x32.
// Stage layout: Ah[0,16K) Al[16K,32K) Bh[32K,48K) Bl[48K,64K). Rows 128B, 8 16B
// chunks, swizzle chunk ^= (row & 7).
__device__ __forceinline__ void g_load_stage(uint32_t sb,
    const __nv_bfloat16* Ah, const __nv_bfloat16* Al,
    const __nv_bfloat16* Bh, const __nv_bfloat16* Bl,
    int K, int m0, int n0, int k0, int tid)
{
#pragma unroll
    for (int it = 0; it < 4; it++) {
        int idx = it * 256 + tid;          // 0..1023
        int r = idx >> 3, c = idx & 7;
        uint32_t soff = (uint32_t)(r * 128 + ((c ^ (r & 7)) << 4));
        size_t ga = (size_t)(m0 + r) * K + k0 + c * 8;
        size_t gb = (size_t)(n0 + r) * K + k0 + c * 8;
        cp16(sb         + soff, Ah + ga);
        cp16(sb + 16384 + soff, Al + ga);
        cp16(sb + 32768 + soff, Bh + gb);
        cp16(sb + 49152 + soff, Bl + gb);
    }
}

__global__ __launch_bounds__(256, 1) void gemm_mma(
    const __nv_bfloat16* __restrict__ Ah, const __nv_bfloat16* __restrict__ Al,
    const __nv_bfloat16* __restrict__ Bh, const __nv_bfloat16* __restrict__ Bl,
    int M, int N, int K,
    const float* __restrict__ bias, const float* __restrict__ res, int relu,
    float* __restrict__ outF, __nv_bfloat16* __restrict__ outH, __nv_bfloat16* __restrict__ outL)
{
    extern __shared__ char dsm_raw[];
    uint32_t base = (smem_u32(dsm_raw) + 1023) & ~1023u;

    const int tid  = threadIdx.x;
    const int wid  = tid >> 5;
    const int lane = tid & 31;
    const int wm   = wid >> 2;          // 0..1  (64 rows each)
    const int wn   = wid & 3;           // 0..3  (32 cols each)
    const int m0   = blockIdx.y * 128;
    const int n0   = blockIdx.x * 128;
    const int wr   = wm * 64;
    const int wc   = wn * 32;
    const int l15  = lane & 15;
    const int hi16 = lane >> 4;

    // per-thread ldmatrix row bases (relative to array start)
    uint32_t a_row[4], a_sw[4], b_row[2], b_sw[2];
#pragma unroll
    for (int mt = 0; mt < 4; mt++) {
        int r = wr + mt * 16 + l15;
        a_row[mt] = (uint32_t)(r * 128);
        a_sw[mt]  = (uint32_t)(r & 7);
    }
#pragma unroll
    for (int nt = 0; nt < 2; nt++) {
        int r = wc + nt * 16 + l15;
        b_row[nt] = (uint32_t)(r * 128);
        b_sw[nt]  = (uint32_t)(r & 7);
    }

    float acc[4][4][4];
#pragma unroll
    for (int i = 0; i < 4; i++)
#pragma unroll
        for (int j = 0; j < 4; j++)
#pragma unroll
            for (int q = 0; q < 4; q++) acc[i][j][q] = 0.f;

    const int nK = K >> 6;

    // prologue: stages 0..STAGES-2
#pragma unroll
    for (int s = 0; s < STAGES - 1; s++) {
        g_load_stage(base + s * STAGE_BYTES, Ah, Al, Bh, Bl, K, m0, n0, s * 64, tid);
        CP_COMMIT();
    }

    for (int kt = 0; kt < nK; kt++) {
        CP_WAIT(STAGES - 2);
        __syncthreads();

        uint32_t sb = base + (kt % STAGES) * STAGE_BYTES;
#pragma unroll
        for (int kh = 0; kh < 4; kh++) {
            uint32_t ah[4][4], al[4][4], bh[4][2], bl[4][2];
#pragma unroll
            for (int mt = 0; mt < 4; mt++) {
                uint32_t co = (uint32_t)(((2 * kh + hi16) ^ a_sw[mt]) << 4);
                ldsm4(ah[mt][0], ah[mt][1], ah[mt][2], ah[mt][3], sb + a_row[mt] + co);
                ldsm4(al[mt][0], al[mt][1], al[mt][2], al[mt][3], sb + 16384 + a_row[mt] + co);
            }
#pragma unroll
            for (int nt = 0; nt < 2; nt++) {
                uint32_t co = (uint32_t)(((2 * kh + hi16) ^ b_sw[nt]) << 4);
                uint32_t t0, t1, t2, t3;
                ldsm4(t0, t1, t2, t3, sb + 32768 + b_row[nt] + co);
                bh[2 * nt][0] = t0; bh[2 * nt + 1][0] = t1;
                bh[2 * nt][1] = t2; bh[2 * nt + 1][1] = t3;
                ldsm4(t0, t1, t2, t3, sb + 49152 + b_row[nt] + co);
                bl[2 * nt][0] = t0; bl[2 * nt + 1][0] = t1;
                bl[2 * nt][1] = t2; bl[2 * nt + 1][1] = t3;
            }
#pragma unroll
            for (int mt = 0; mt < 4; mt++)
#pragma unroll
                for (int j = 0; j < 4; j++) {
                    mma16816(acc[mt][j], ah[mt], bh[j]);
                    mma16816(acc[mt][j], ah[mt], bl[j]);
                    mma16816(acc[mt][j], al[mt], bh[j]);
                }
        }
        __syncthreads();

        int ls = kt + STAGES - 1;
        if (ls < nK)
            g_load_stage(base + (ls % STAGES) * STAGE_BYTES, Ah, Al, Bh, Bl, K, m0, n0, ls * 64, tid);
        CP_COMMIT();
    }

    // epilogue: acc[mt][n8][d0..d3]; rows lane>>2 (+8), cols (lane&3)*2 (+1)
    const int rq = lane >> 2;
    const int cq = (lane & 3) * 2;
#pragma unroll
    for (int mt = 0; mt < 4; mt++)
#pragma unroll
        for (int half = 0; half < 2; half++) {
            int row = m0 + wr + mt * 16 + rq + half * 8;
            size_t rb = (size_t)row * N;
#pragma unroll
            for (int j = 0; j < 4; j++) {
                int col = n0 + wc + j * 8 + cq;
                float v0 = acc[mt][j][half * 2 + 0];
                float v1 = acc[mt][j][half * 2 + 1];
                if (bias) { v0 += bias[col]; v1 += bias[col + 1]; }
                if (relu) { v0 = fmaxf(v0, 0.f); v1 = fmaxf(v1, 0.f); }
                if (res)  {
                    float2 rr = *(const float2*)&res[rb + col];
                    v0 += rr.x; v1 += rr.y;
                }
                if (outF) *(float2*)&outF[rb + col] = make_float2(v0, v1);
                if (outH) {
                    __nv_bfloat16 h0, l0, h1, l1;
                    bf16split(v0, h0, l0); bf16split(v1, h1, l1);
                    __nv_bfloat162 ph; ph.x = h0; ph.y = h1;
                    __nv_bfloat162 pl; pl.x = l0; pl.y = l1;
                    *reinterpret_cast<__nv_bfloat162*>(outH + rb + col) = ph;
                    *reinterpret_cast<__nv_bfloat162*>(outL + rb + col) = pl;
                }
            }
        }
}

// ---------------- flash attention (fp32), writes bf16 hi/lo output -----------
__global__ __launch_bounds__(256) void flash_attn(const float* __restrict__ qkv,
                                                  __nv_bfloat16* __restrict__ outh,
                                                  __nv_bfloat16* __restrict__ outl)
{
    __shared__ float Qt[64 * 64];
    __shared__ float Vs[64 * 64];
    __shared__ float KP[64 * 64];

    const int tid = threadIdx.x;
    const int ty  = tid >> 4;
    const int tx  = tid & 15;
    const int qt  = blockIdx.x;
    const int h   = blockIdx.y;
    const int b   = blockIdx.z;
    const int q0  = qt * 64;

    const size_t base  = (size_t)b * SEQ * QKVLD;
    const float* qbase = qkv + base + (size_t)q0 * QKVLD + h * 64;
    const float* kbase = qkv + base + 1024 + h * 64;
    const float* vbase = qkv + base + 2048 + h * 64;

#pragma unroll
    for (int it = 0; it < 4; it++) {
        int idx = it * 256 + tid;
        int d4 = idx >> 6, r = idx & 63;
        float4 v = *(const float4*)(qbase + (size_t)r * QKVLD + 4 * d4);
        Qt[(4 * d4 + 0) * 64 + r] = v.x * 0.125f;
        Qt[(4 * d4 + 1) * 64 + r] = v.y * 0.125f;
        Qt[(4 * d4 + 2) * 64 + r] = v.z * 0.125f;
        Qt[(4 * d4 + 3) * 64 + r] = v.w * 0.125f;
    }

    float m[4], l[4], acc[4][4];
#pragma unroll
    for (int i = 0; i < 4; i++) {
        m[i] = -1e30f; l[i] = 0.f;
#pragma unroll
        for (int j = 0; j < 4; j++) acc[i][j] = 0.f;
    }

    for (int kt = 0; kt < SEQ / 64; kt++) {
        __syncthreads();
#pragma unroll
        for (int it = 0; it < 4; it++) {
            int idx = it * 256 + tid;
            int d4 = idx >> 6, r = idx & 63;
            float4 v = *(const float4*)(kbase + (size_t)(kt * 64 + r) * QKVLD + 4 * d4);
            KP[(4 * d4 + 0) * 64 + r] = v.x;
            KP[(4 * d4 + 1) * 64 + r] = v.y;
            KP[(4 * d4 + 2) * 64 + r] = v.z;
            KP[(4 * d4 + 3) * 64 + r] = v.w;
        }
#pragma unroll
        for (int it = 0; it < 4; it++) {
            int idx = it * 256 + tid;
            int t = idx >> 4, d4 = idx & 15;
            *(float4*)&Vs[t * 64 + 4 * d4] =
                *(const float4*)(vbase + (size_t)(kt * 64 + t) * QKVLD + 4 * d4);
        }
        __syncthreads();

        float s[4][4];
#pragma unroll
        for (int i = 0; i < 4; i++)
#pragma unroll
            for (int j = 0; j < 4; j++) s[i][j] = 0.f;
#pragma unroll 8
        for (int d = 0; d < 64; d++) {
            float4 a  = *(const float4*)&Qt[d * 64 + 4 * ty];
            float4 bf = *(const float4*)&KP[d * 64 + 4 * tx];
            s[0][0] += a.x * bf.x; s[0][1] += a.x * bf.y; s[0][2] += a.x * bf.z; s[0][3] += a.x * bf.w;
            s[1][0] += a.y * bf.x; s[1][1] += a.y * bf.y; s[1][2] += a.y * bf.z; s[1][3] += a.y * bf.w;
            s[2][0] += a.z * bf.x; s[2][1] += a.z * bf.y; s[2][2] += a.z * bf.z; s[2][3] += a.z * bf.w;
            s[3][0] += a.w * bf.x; s[3][1] += a.w * bf.y; s[3][2] += a.w * bf.z; s[3][3] += a.w * bf.w;
        }
        __syncthreads();

#pragma unroll
        for (int i = 0; i < 4; i++) {
            float mx = fmaxf(fmaxf(s[i][0], s[i][1]), fmaxf(s[i][2], s[i][3]));
#pragma unroll
            for (int off = 8; off > 0; off >>= 1)
                mx = fmaxf(mx, __shfl_xor_sync(0xffffffffu, mx, off, 16));
            float nm    = fmaxf(m[i], mx);
            float alpha = __expf(m[i] - nm);
            float4 p;
            p.x = __expf(s[i][0] - nm);
            p.y = __expf(s[i][1] - nm);
            p.z = __expf(s[i][2] - nm);
            p.w = __expf(s[i][3] - nm);
            float rs = p.x + p.y + p.z + p.w;
#pragma unroll
            for (int off = 8; off > 0; off >>= 1)
                rs += __shfl_xor_sync(0xffffffffu, rs, off, 16);
            l[i] = l[i] * alpha + rs;
            m[i] = nm;
            acc[i][0] *= alpha; acc[i][1] *= alpha; acc[i][2] *= alpha; acc[i][3] *= alpha;
            *(float4*)&KP[(4 * ty + i) * 64 + 4 * tx] = p;
        }
        __syncthreads();

#pragma unroll 8
        for (int t = 0; t < 64; t++) {
            float4 bv = *(const float4*)&Vs[t * 64 + 4 * tx];
#pragma unroll
            for (int i = 0; i < 4; i++) {
                float a = KP[(4 * ty + i) * 64 + t];
                acc[i][0] += a * bv.x; acc[i][1] += a * bv.y;
                acc[i][2] += a * bv.z; acc[i][3] += a * bv.w;
            }
        }
    }

#pragma unroll
    for (int i = 0; i < 4; i++) {
        float inv = 1.f / l[i];
        size_t o = (size_t)(b * SEQ + q0 + 4 * ty + i) * 1024 + h * 64 + 4 * tx;
        __nv_bfloat16 h0, l0, h1, l1, h2, l2, h3, l3;
        bf16split(acc[i][0] * inv, h0, l0);
        bf16split(acc[i][1] * inv, h1, l1);
        bf16split(acc[i][2] * inv, h2, l2);
        bf16split(acc[i][3] * inv, h3, l3);
        __nv_bfloat162 a01, a23, b01, b23;
        a01.x = h0; a01.y = h1; a23.x = h2; a23.y = h3;
        b01.x = l0; b01.y = l1; b23.x = l2; b23.y = l3;
        *reinterpret_cast<__nv_bfloat162*>(outh + o)     = a01;
        *reinterpret_cast<__nv_bfloat162*>(outh + o + 2) = a23;
        *reinterpret_cast<__nv_bfloat162*>(outl + o)     = b01;
        *reinterpret_cast<__nv_bfloat162*>(outl + o + 2) = b23;
    }
}

// ---------------- layernorm (f32 out + optional bf16 hi/lo out) --------------
__global__ __launch_bounds__(256) void ln_kernel(const float* __restrict__ in,
                                                 const float* __restrict__ gamma,
                                                 const float* __restrict__ beta,
                                                 float* __restrict__ outF,
                                                 __nv_bfloat16* __restrict__ outH,
                                                 __nv_bfloat16* __restrict__ outL)
{
    const int row = blockIdx.x, tid = threadIdx.x;
    const float* p = in + (size_t)row * 1024;
    float4 v = *(const float4*)(p + tid * 4);
    float s  = v.x + v.y + v.z + v.w;
    float ss = v.x * v.x + v.y * v.y + v.z * v.z + v.w * v.w;
#pragma unroll
    for (int off = 16; off > 0; off >>= 1) {
        s  += __shfl_xor_sync(0xffffffffu, s,  off);
        ss += __shfl_xor_sync(0xffffffffu, ss, off);
    }
    __shared__ float sb[8], ssb[8];
    __shared__ float smu, sinv;
    if ((tid & 31) == 0) { sb[tid >> 5] = s; ssb[tid >> 5] = ss; }
    __syncthreads();
    if (tid == 0) {
        float S = 0.f, SS = 0.f;
#pragma unroll
        for (int i = 0; i < 8; i++) { S += sb[i]; SS += ssb[i]; }
        float mu  = S * (1.f / 1024.f);
        float var = SS * (1.f / 1024.f) - mu * mu;
        smu = mu; sinv = rsqrtf(var + 1e-5f);
    }
    __syncthreads();
    float mu = smu, inv = sinv;
    float4 g = *(const float4*)(gamma + tid * 4);
    float4 b = *(const float4*)(beta  + tid * 4);
    float4 o;
    o.x = (v.x - mu) * inv * g.x + b.x;
    o.y = (v.y - mu) * inv * g.y + b.y;
    o.z = (v.z - mu) * inv * g.z + b.z;
    o.w = (v.w - mu) * inv * g.w + b.w;
    size_t idx = (size_t)row * 1024 + tid * 4;
    *(float4*)&outF[idx] = o;
    if (outH) {
        __nv_bfloat16 h0, l0, h1, l1, h2, l2, h3, l3;
        bf16split(o.x, h0, l0); bf16split(o.y, h1, l1);
        bf16split(o.z, h2, l2); bf16split(o.w, h3, l3);
        __nv_bfloat162 a01, a23, b01, b23;
        a01.x = h0; a01.y = h1; a23.x = h2; a23.y = h3;
        b01.x = l0; b01.y = l1; b23.x = l2; b23.y = l3;
        *reinterpret_cast<__nv_bfloat162*>(outH + idx)     = a01;
        *reinterpret_cast<__nv_bfloat162*>(outH + idx + 2) = a23;
        *reinterpret_cast<__nv_bfloat162*>(outL + idx)     = b01;
        *reinterpret_cast<__nv_bfloat162*>(outL + idx + 2) = b23;
    }
}

// ---------------- launch ------------------------------------------------------
extern "C" void kernel_launch(void* const* d_in, const int* in_sizes, int n_in,
                              void* d_out, int out_size)
{
    const float* x     = (const float*)d_in[0];
    const float* Wq    = (const float*)d_in[1];
    const float* Wk    = (const float*)d_in[2];
    const float* Wv    = (const float*)d_in[3];
    const float* Wo    = (const float*)d_in[4];
    const float* ln1_g = (const float*)d_in[5];
    const float* ln1_b = (const float*)d_in[6];
    const float* W1    = (const float*)d_in[7];
    const float* b1    = (const float*)d_in[8];
    const float* W2    = (const float*)d_in[9];
    const float* b2    = (const float*)d_in[10];
    const float* ln2_g = (const float*)d_in[11];
    const float* ln2_b = (const float*)d_in[12];
    float* out = (float*)d_out;

    cudaFuncSetAttribute(gemm_mma, cudaFuncAttributeMaxDynamicSharedMemorySize, GEMM_SMEM);

    float *wqkv, *qkv, *t1, *x1, *t2;
    __nv_bfloat16 *wqkvh, *wqkvl, *xh, *xl, *oh, *ol, *woh, *wol;
    __nv_bfloat16 *x1h, *x1l, *w1h, *w1l, *hh, *hl, *w2h, *w2l;
    cudaGetSymbolAddress((void**)&wqkv,  g_wqkv);
    cudaGetSymbolAddress((void**)&qkv,   g_qkv);
    cudaGetSymbolAddress((void**)&t1,    g_t1);
    cudaGetSymbolAddress((void**)&x1,    g_x1);
    cudaGetSymbolAddress((void**)&t2,    g_t2);
    cudaGetSymbolAddress((void**)&wqkvh, g_wqkvh);
    cudaGetSymbolAddress((void**)&wqkvl, g_wqkvl);
    cudaGetSymbolAddress((void**)&xh,    g_xh);
    cudaGetSymbolAddress((void**)&xl,    g_xl);
    cudaGetSymbolAddress((void**)&oh,    g_oh);
    cudaGetSymbolAddress((void**)&ol,    g_ol);
    cudaGetSymbolAddress((void**)&woh,   g_woh);
    cudaGetSymbolAddress((void**)&wol,   g_wol);
    cudaGetSymbolAddress((void**)&x1h,   g_x1h);
    cudaGetSymbolAddress((void**)&x1l,   g_x1l);
    cudaGetSymbolAddress((void**)&w1h,   g_w1h);
    cudaGetSymbolAddress((void**)&w1l,   g_w1l);
    cudaGetSymbolAddress((void**)&hh,    g_hh);
    cudaGetSymbolAddress((void**)&hl,    g_hl);
    cudaGetSymbolAddress((void**)&w2h,   g_w2h);
    cudaGetSymbolAddress((void**)&w2l,   g_w2l);

    // weight prep
    repack_qkv<<<12288, 256>>>(Wq, Wk, Wv, wqkv);
    transpose_split<<<dim3(96, 32),  dim3(32, 8)>>>(wqkv, 1024, 3072, wqkvh, wqkvl);
    transpose_split<<<dim3(32, 32),  dim3(32, 8)>>>(Wo,   1024, 1024, woh,   wol);
    transpose_split<<<dim3(128, 32), dim3(32, 8)>>>(W1,   1024, 4096, w1h,   w1l);
    transpose_split<<<dim3(32, 128), dim3(32, 8)>>>(W2,   4096, 1024, w2h,   w2l);
    split_plain<<<16384, 256>>>(x, xh, xl);

    // 1. QKV projection: [4096,1024] x [3072,1024]^T -> qkv fp32
    gemm_mma<<<dim3(24, 32), 256, GEMM_SMEM>>>(xh, xl, wqkvh, wqkvl, 4096, 3072, 1024,
                                               nullptr, nullptr, 0, qkv, nullptr, nullptr);
    // 2. attention -> o hi/lo
    flash_attn<<<dim3(32, NH, BATCH), 256>>>(qkv, oh, ol);
    // 3. output projection + residual x -> t1 fp32
    gemm_mma<<<dim3(8, 32), 256, GEMM_SMEM>>>(oh, ol, woh, wol, 4096, 1024, 1024,
                                              nullptr, x, 0, t1, nullptr, nullptr);
    // 4. LN1 -> x1 fp32 + hi/lo
    ln_kernel<<<4096, 256>>>(t1, ln1_g, ln1_b, x1, x1h, x1l);
    // 5. FFN up + bias + relu -> h hi/lo
    gemm_mma<<<dim3(32, 32), 256, GEMM_SMEM>>>(x1h, x1l, w1h, w1l, 4096, 4096, 1024,
                                               b1, nullptr, 1, nullptr, hh, hl);
    // 6. FFN down + bias + residual x1 -> t2 fp32
    gemm_mma<<<dim3(8, 32), 256, GEMM_SMEM>>>(hh, hl, w2h, w2l, 4096, 1024, 4096,
                                              b2, x1, 0, t2, nullptr, nullptr);
    // 7. LN2 -> out
    ln_kernel<<<4096, 256>>>(t2, ln2_g, ln2_b, out, nullptr, nullptr);
}

// round 4
// speedup vs baseline: 2.6972x; 1.4609x over previous
#include <cuda_runtime.h>
#include <cuda_bf16.h>
#include <cstdint>

#define SEQ    2048
#define BATCH  2
#define NH     16
#define QKVLD  3072
#define STAGES 3
#define STAGE_BYTES 65536
#define GEMM_SMEM (STAGES * STAGE_BYTES + 1024)
#define ATT_SMEM  (32768 + 2 * 32768 + 1024)

// ---------------- scratch (static device globals; no allocation) -------------
__device__ float          g_wqkv [1024u * 3072u];
__device__ __nv_bfloat16  g_wqkvh[3072u * 1024u], g_wqkvl[3072u * 1024u];
__device__ __nv_bfloat16  g_xh   [4096u * 1024u], g_xl   [4096u * 1024u];
__device__ __nv_bfloat16  g_qkvh [4096u * 3072u], g_qkvl [4096u * 3072u];
__device__ __nv_bfloat16  g_oh   [4096u * 1024u], g_ol   [4096u * 1024u];
__device__ __nv_bfloat16  g_woh  [1024u * 1024u], g_wol  [1024u * 1024u];
__device__ float          g_t1   [4096u * 1024u];
__device__ float          g_x1   [4096u * 1024u];
__device__ __nv_bfloat16  g_x1h  [4096u * 1024u], g_x1l  [4096u * 1024u];
__device__ __nv_bfloat16  g_w1h  [4096u * 1024u], g_w1l  [4096u * 1024u];
__device__ __nv_bfloat16  g_hh   [4096u * 4096u], g_hl   [4096u * 4096u];
__device__ __nv_bfloat16  g_w2h  [1024u * 4096u], g_w2l  [1024u * 4096u];
__device__ float          g_t2   [4096u * 1024u];

// ---------------- PTX helpers --------------------------------------------------
__device__ __forceinline__ uint32_t smem_u32(const void* p) {
    uint32_t a;
    asm("{ .reg .u64 t; cvta.to.shared.u64 t, %1; cvt.u32.u64 %0, t; }" : "=r"(a) : "l"(p));
    return a;
}
__device__ __forceinline__ void cp16(uint32_t s, const void* g) {
    asm volatile("cp.async.cg.shared.global [%0], [%1], 16;" :: "r"(s), "l"(g));
}
#define CP_COMMIT()  asm volatile("cp.async.commit_group;" ::: "memory")
#define CP_WAIT(n)   asm volatile("cp.async.wait_group %0;" :: "n"(n) : "memory")

__device__ __forceinline__ void ldsm4(uint32_t& r0, uint32_t& r1, uint32_t& r2, uint32_t& r3,
                                      uint32_t addr) {
    asm volatile("ldmatrix.sync.aligned.m8n8.x4.shared.b16 {%0,%1,%2,%3}, [%4];"
                 : "=r"(r0), "=r"(r1), "=r"(r2), "=r"(r3) : "r"(addr));
}
__device__ __forceinline__ void ldsm4t(uint32_t& r0, uint32_t& r1, uint32_t& r2, uint32_t& r3,
                                       uint32_t addr) {
    asm volatile("ldmatrix.sync.aligned.m8n8.x4.trans.shared.b16 {%0,%1,%2,%3}, [%4];"
                 : "=r"(r0), "=r"(r1), "=r"(r2), "=r"(r3) : "r"(addr));
}
__device__ __forceinline__ void mma16816(float* d, const uint32_t* a, const uint32_t* b) {
    asm volatile(
        "mma.sync.aligned.m16n8k16.row.col.f32.bf16.bf16.f32 "
        "{%0,%1,%2,%3}, {%4,%5,%6,%7}, {%8,%9}, {%0,%1,%2,%3};"
        : "+f"(d[0]), "+f"(d[1]), "+f"(d[2]), "+f"(d[3])
        : "r"(a[0]), "r"(a[1]), "r"(a[2]), "r"(a[3]), "r"(b[0]), "r"(b[1]));
}
__device__ __forceinline__ void bf16split(float v, __nv_bfloat16& h, __nv_bfloat16& l) {
    h = __float2bfloat16(v);
    l = __float2bfloat16(v - __bfloat162float(h));
}
// split two floats into packed bf16x2 hi / lo registers (elem0 in low half)
__device__ __forceinline__ void split2(float a, float b, uint32_t& h, uint32_t& l) {
    __nv_bfloat16 ha = __float2bfloat16(a), hb = __float2bfloat16(b);
    __nv_bfloat16 la = __float2bfloat16(a - __bfloat162float(ha));
    __nv_bfloat16 lb = __float2bfloat16(b - __bfloat162float(hb));
    h = (uint32_t)__bfloat16_as_ushort(ha) | ((uint32_t)__bfloat16_as_ushort(hb) << 16);
    l = (uint32_t)__bfloat16_as_ushort(la) | ((uint32_t)__bfloat16_as_ushort(lb) << 16);
}

// ---------------- prep kernels -----------------------------------------------
__global__ void repack_qkv(const float* __restrict__ Wq, const float* __restrict__ Wk,
                           const float* __restrict__ Wv, float* __restrict__ Wqkv)
{
    int idx = blockIdx.x * blockDim.x + threadIdx.x;
    int w   = idx >> 20;
    int rem = idx & 1048575;
    int h   = rem >> 16;
    int d   = (rem >> 6) & 1023;
    int k   = rem & 63;
    const float* src = (w == 0) ? Wq : (w == 1) ? Wk : Wv;
    Wqkv[(size_t)d * QKVLD + w * 1024 + h * 64 + k] = src[rem];
}

__global__ void transpose_split(const float* __restrict__ in, int Rk, int Cn,
                                __nv_bfloat16* __restrict__ oh, __nv_bfloat16* __restrict__ ol)
{
    __shared__ float t[32][33];
    int c0 = blockIdx.x * 32, r0 = blockIdx.y * 32;
    for (int i = threadIdx.y; i < 32; i += 8)
        t[i][threadIdx.x] = in[(size_t)(r0 + i) * Cn + c0 + threadIdx.x];
    __syncthreads();
    for (int i = threadIdx.y; i < 32; i += 8) {
        float v = t[threadIdx.x][i];
        __nv_bfloat16 hh, ll; bf16split(v, hh, ll);
        size_t o = (size_t)(c0 + i) * Rk + r0 + threadIdx.x;
        oh[o] = hh; ol[o] = ll;
    }
}

__global__ void split_plain(const float* __restrict__ in,
                            __nv_bfloat16* __restrict__ oh, __nv_bfloat16* __restrict__ ol)
{
    int idx = blockIdx.x * blockDim.x + threadIdx.x;
    __nv_bfloat16 hh, ll; bf16split(in[idx], hh, ll);
    oh[idx] = hh; ol[idx] = ll;
}

// ---------------- mma.sync bf16x3 GEMM ----------------------------------------
__device__ __forceinline__ void g_load_stage(uint32_t sb,
    const __nv_bfloat16* Ah, const __nv_bfloat16* Al,
    const __nv_bfloat16* Bh, const __nv_bfloat16* Bl,
    int K, int m0, int n0, int k0, int tid)
{
#pragma unroll
    for (int it = 0; it < 4; it++) {
        int idx = it * 256 + tid;
        int r = idx >> 3, c = idx & 7;
        uint32_t soff = (uint32_t)(r * 128 + ((c ^ (r & 7)) << 4));
        size_t ga = (size_t)(m0 + r) * K + k0 + c * 8;
        size_t gb = (size_t)(n0 + r) * K + k0 + c * 8;
        cp16(sb         + soff, Ah + ga);
        cp16(sb + 16384 + soff, Al + ga);
        cp16(sb + 32768 + soff, Bh + gb);
        cp16(sb + 49152 + soff, Bl + gb);
    }
}

__global__ __launch_bounds__(256, 1) void gemm_mma(
    const __nv_bfloat16* __restrict__ Ah, const __nv_bfloat16* __restrict__ Al,
    const __nv_bfloat16* __restrict__ Bh, const __nv_bfloat16* __restrict__ Bl,
    int M, int N, int K,
    const float* __restrict__ bias, const float* __restrict__ res, int relu,
    float* __restrict__ outF, __nv_bfloat16* __restrict__ outH, __nv_bfloat16* __restrict__ outL)
{
    extern __shared__ char dsm_raw[];
    uint32_t base = (smem_u32(dsm_raw) + 1023) & ~1023u;

    const int tid  = threadIdx.x;
    const int wid  = tid >> 5;
    const int lane = tid & 31;
    const int wm   = wid >> 2;
    const int wn   = wid & 3;
    const int m0   = blockIdx.y * 128;
    const int n0   = blockIdx.x * 128;
    const int wr   = wm * 64;
    const int wc   = wn * 32;
    const int l15  = lane & 15;
    const int hi16 = lane >> 4;

    uint32_t a_row[4], a_sw[4], b_row[2], b_sw[2];
#pragma unroll
    for (int mt = 0; mt < 4; mt++) {
        int r = wr + mt * 16 + l15;
        a_row[mt] = (uint32_t)(r * 128);
        a_sw[mt]  = (uint32_t)(r & 7);
    }
#pragma unroll
    for (int nt = 0; nt < 2; nt++) {
        int r = wc + nt * 16 + l15;
        b_row[nt] = (uint32_t)(r * 128);
        b_sw[nt]  = (uint32_t)(r & 7);
    }

    float acc[4][4][4];
#pragma unroll
    for (int i = 0; i < 4; i++)
#pragma unroll
        for (int j = 0; j < 4; j++)
#pragma unroll
            for (int q = 0; q < 4; q++) acc[i][j][q] = 0.f;

    const int nK = K >> 6;

#pragma unroll
    for (int s = 0; s < STAGES - 1; s++) {
        g_load_stage(base + s * STAGE_BYTES, Ah, Al, Bh, Bl, K, m0, n0, s * 64, tid);
        CP_COMMIT();
    }

    for (int kt = 0; kt < nK; kt++) {
        CP_WAIT(STAGES - 2);
        __syncthreads();

        // issue next-stage loads BEFORE compute so transfer overlaps MMA
        int ls = kt + STAGES - 1;
        if (ls < nK)
            g_load_stage(base + (ls % STAGES) * STAGE_BYTES, Ah, Al, Bh, Bl, K, m0, n0, ls * 64, tid);
        CP_COMMIT();

        uint32_t sb = base + (kt % STAGES) * STAGE_BYTES;
#pragma unroll
        for (int kh = 0; kh < 4; kh++) {
            uint32_t ah[4][4], al[4][4], bh[4][2], bl[4][2];
#pragma unroll
            for (int mt = 0; mt < 4; mt++) {
                uint32_t co = (uint32_t)(((2 * kh + hi16) ^ a_sw[mt]) << 4);
                ldsm4(ah[mt][0], ah[mt][1], ah[mt][2], ah[mt][3], sb + a_row[mt] + co);
                ldsm4(al[mt][0], al[mt][1], al[mt][2], al[mt][3], sb + 16384 + a_row[mt] + co);
            }
#pragma unroll
            for (int nt = 0; nt < 2; nt++) {
                uint32_t co = (uint32_t)(((2 * kh + hi16) ^ b_sw[nt]) << 4);
                uint32_t t0, t1, t2, t3;
                ldsm4(t0, t1, t2, t3, sb + 32768 + b_row[nt] + co);
                bh[2 * nt][0] = t0; bh[2 * nt + 1][0] = t1;
                bh[2 * nt][1] = t2; bh[2 * nt + 1][1] = t3;
                ldsm4(t0, t1, t2, t3, sb + 49152 + b_row[nt] + co);
                bl[2 * nt][0] = t0; bl[2 * nt + 1][0] = t1;
                bl[2 * nt][1] = t2; bl[2 * nt + 1][1] = t3;
            }
#pragma unroll
            for (int mt = 0; mt < 4; mt++)
#pragma unroll
                for (int j = 0; j < 4; j++) {
                    mma16816(acc[mt][j], ah[mt], bh[j]);
                    mma16816(acc[mt][j], ah[mt], bl[j]);
                    mma16816(acc[mt][j], al[mt], bh[j]);
                }
        }
        __syncthreads();
    }

    const int rq = lane >> 2;
    const int cq = (lane & 3) * 2;
#pragma unroll
    for (int mt = 0; mt < 4; mt++)
#pragma unroll
        for (int half = 0; half < 2; half++) {
            int row = m0 + wr + mt * 16 + rq + half * 8;
            size_t rb = (size_t)row * N;
#pragma unroll
            for (int j = 0; j < 4; j++) {
                int col = n0 + wc + j * 8 + cq;
                float v0 = acc[mt][j][half * 2 + 0];
                float v1 = acc[mt][j][half * 2 + 1];
                if (bias) { v0 += bias[col]; v1 += bias[col + 1]; }
                if (relu) { v0 = fmaxf(v0, 0.f); v1 = fmaxf(v1, 0.f); }
                if (res)  {
                    float2 rr = *(const float2*)&res[rb + col];
                    v0 += rr.x; v1 += rr.y;
                }
                if (outF) *(float2*)&outF[rb + col] = make_float2(v0, v1);
                if (outH) {
                    uint32_t hh, ll;
                    split2(v0, v1, hh, ll);
                    *reinterpret_cast<uint32_t*>(outH + rb + col) = hh;
                    *reinterpret_cast<uint32_t*>(outL + rb + col) = ll;
                }
            }
        }
}

// ---------------- HMMA flash attention ----------------------------------------
// Q tile 128 x 64 (per (b,h,qtile)), K/V tiles 64 keys, bf16 hi/lo, 3-pass mma.
// smem: QH[0,16K) QL[16K,32K); stage s at 32K+s*32K: KH+0 KL+8K VH+16K VL+24K.
__device__ __forceinline__ void att_load_kv(uint32_t sb,
    const __nv_bfloat16* qh, const __nv_bfloat16* ql,
    size_t tokbase, int h, int kt, int tid)
{
#pragma unroll
    for (int it = 0; it < 2; it++) {
        int idx = it * 256 + tid;
        int r = idx >> 3, c = idx & 7;
        uint32_t sw = (uint32_t)(r * 128 + ((c ^ (r & 7)) << 4));
        size_t gk = (tokbase + kt * 64 + r) * QKVLD + 1024 + h * 64 + c * 8;
        size_t gv = gk + 1024;
        cp16(sb          + sw, qh + gk);
        cp16(sb + 8192   + sw, ql + gk);
        cp16(sb + 16384  + sw, qh + gv);
        cp16(sb + 24576  + sw, ql + gv);
    }
}

__global__ __launch_bounds__(256, 1) void flash_hmma(
    const __nv_bfloat16* __restrict__ qh, const __nv_bfloat16* __restrict__ ql,
    __nv_bfloat16* __restrict__ oh, __nv_bfloat16* __restrict__ ol)
{
    extern __shared__ char smem_raw[];
    uint32_t base = (smem_u32(smem_raw) + 1023) & ~1023u;
    const uint32_t QH = base, QL = base + 16384;

    const int tid  = threadIdx.x;
    const int wq   = tid >> 5;          // warp -> q rows [wq*16, wq*16+16)
    const int lane = tid & 31;
    const int l15  = lane & 15;
    const int hi16 = lane >> 4;
    const int q0   = blockIdx.x * 128;
    const int h    = blockIdx.y;
    const int b    = blockIdx.z;
    const size_t tokbase = (size_t)b * SEQ;

    // Q tile (hi+lo) + K/V stage 0, all in async group 0
#pragma unroll
    for (int it = 0; it < 4; it++) {
        int idx = it * 256 + tid;
        int r = idx >> 3, c = idx & 7;
        uint32_t sw = (uint32_t)(r * 128 + ((c ^ (r & 7)) << 4));
        size_t g = (tokbase + q0 + r) * QKVLD + h * 64 + c * 8;
        cp16(QH + sw, qh + g);
        cp16(QL + sw, ql + g);
    }
    att_load_kv(base + 32768, qh, ql, tokbase, h, 0, tid);
    CP_COMMIT();

    float m2[2] = {-1e30f, -1e30f};
    float l2[2] = {0.f, 0.f};
    float oa[8][4];
#pragma unroll
    for (int j = 0; j < 8; j++)
#pragma unroll
        for (int q = 0; q < 4; q++) oa[j][q] = 0.f;

    const uint32_t qrow = (uint32_t)((wq * 16 + l15) * 128);
    const uint32_t qsw  = (uint32_t)((wq * 16 + l15) & 7);

    for (int kt = 0; kt < SEQ / 64; kt++) {
        CP_WAIT(0);
        __syncthreads();
        if (kt + 1 < SEQ / 64)
            att_load_kv(base + 32768 + ((kt + 1) & 1) * 32768, qh, ql, tokbase, h, kt + 1, tid);
        CP_COMMIT();

        uint32_t sb = base + 32768 + (kt & 1) * 32768;

        // ---- S = Q K^T (3-pass) --------------------------------------------
        float sa[8][4];
#pragma unroll
        for (int j = 0; j < 8; j++)
#pragma unroll
            for (int q = 0; q < 4; q++) sa[j][q] = 0.f;

#pragma unroll
        for (int kc = 0; kc < 4; kc++) {
            uint32_t co_a = (uint32_t)(((2 * kc + hi16) ^ qsw) << 4);
            uint32_t ah[4], al[4];
            ldsm4(ah[0], ah[1], ah[2], ah[3], QH + qrow + co_a);
            ldsm4(al[0], al[1], al[2], al[3], QL + qrow + co_a);

            uint32_t kbh[8][2], kbl[8][2];
#pragma unroll
            for (int nt = 0; nt < 4; nt++) {
                int r = nt * 16 + l15;
                uint32_t co = (uint32_t)(((2 * kc + hi16) ^ (r & 7)) << 4);
                uint32_t t0, t1, t2, t3;
                ldsm4(t0, t1, t2, t3, sb + r * 128 + co);
                kbh[2 * nt][0] = t0; kbh[2 * nt][1] = t2;
                kbh[2 * nt + 1][0] = t1; kbh[2 * nt + 1][1] = t3;
                ldsm4(t0, t1, t2, t3, sb + 8192 + r * 128 + co);
                kbl[2 * nt][0] = t0; kbl[2 * nt][1] = t2;
                kbl[2 * nt + 1][0] = t1; kbl[2 * nt + 1][1] = t3;
            }
#pragma unroll
            for (int j = 0; j < 8; j++) {
                mma16816(sa[j], ah, kbh[j]);
                mma16816(sa[j], al, kbh[j]);
                mma16816(sa[j], ah, kbl[j]);
            }
        }

        // ---- online softmax (rows r = lane>>2 [half 0], +8 [half 1]) --------
#pragma unroll
        for (int half = 0; half < 2; half++) {
            float mx = -1e30f;
#pragma unroll
            for (int j = 0; j < 8; j++) {
                sa[j][2 * half]     *= 0.125f;
                sa[j][2 * half + 1] *= 0.125f;
                mx = fmaxf(mx, fmaxf(sa[j][2 * half], sa[j][2 * half + 1]));
            }
            mx = fmaxf(mx, __shfl_xor_sync(0xffffffffu, mx, 1));
            mx = fmaxf(mx, __shfl_xor_sync(0xffffffffu, mx, 2));
            float nm    = fmaxf(m2[half], mx);
            float alpha = __expf(m2[half] - nm);
            float rs = 0.f;
#pragma unroll
            for (int j = 0; j < 8; j++) {
                sa[j][2 * half]     = __expf(sa[j][2 * half]     - nm);
                sa[j][2 * half + 1] = __expf(sa[j][2 * half + 1] - nm);
                rs += sa[j][2 * half] + sa[j][2 * half + 1];
            }
            rs += __shfl_xor_sync(0xffffffffu, rs, 1);
            rs += __shfl_xor_sync(0xffffffffu, rs, 2);
            l2[half] = l2[half] * alpha + rs;
            m2[half] = nm;
#pragma unroll
            for (int j = 0; j < 8; j++) {
                oa[j][2 * half]     *= alpha;
                oa[j][2 * half + 1] *= alpha;
            }
        }

        // ---- P -> a-frags (hi/lo), in-register ------------------------------
        uint32_t ph[4][4], pl[4][4];
#pragma unroll
        for (int kc = 0; kc < 4; kc++) {
            int j0 = 2 * kc, j1 = 2 * kc + 1;
            split2(sa[j0][0], sa[j0][1], ph[kc][0], pl[kc][0]);
            split2(sa[j0][2], sa[j0][3], ph[kc][1], pl[kc][1]);
            split2(sa[j1][0], sa[j1][1], ph[kc][2], pl[kc][2]);
            split2(sa[j1][2], sa[j1][3], ph[kc][3], pl[kc][3]);
        }

        // ---- O += P V (3-pass), V via ldmatrix.trans -------------------------
#pragma unroll
        for (int kc = 0; kc < 4; kc++) {
            int rowt = kc * 16 + ((lane >> 4) << 3) + (lane & 7);
            uint32_t vbh[8][2], vbl[8][2];
#pragma unroll
            for (int jt = 0; jt < 4; jt++) {
                int c8 = jt * 2 + ((lane >> 3) & 1);
                uint32_t ad = sb + 16384 + rowt * 128 + (uint32_t)(((c8 ^ (rowt & 7))) << 4);
                uint32_t t0, t1, t2, t3;
                ldsm4t(t0, t1, t2, t3, ad);
                vbh[2 * jt][0] = t0; vbh[2 * jt][1] = t2;
                vbh[2 * jt + 1][0] = t1; vbh[2 * jt + 1][1] = t3;
                ldsm4t(t0, t1, t2, t3, ad + 8192);
                vbl[2 * jt][0] = t0; vbl[2 * jt][1] = t2;
                vbl[2 * jt + 1][0] = t1; vbl[2 * jt + 1][1] = t3;
            }
#pragma unroll
            for (int j = 0; j < 8; j++) {
                mma16816(oa[j], ph[kc], vbh[j]);
                mma16816(oa[j], pl[kc], vbh[j]);
                mma16816(oa[j], ph[kc], vbl[j]);
            }
        }
    }

    // ---- epilogue: O /= l, write bf16 hi/lo --------------------------------
    float inv0 = 1.f / l2[0];
    float inv1 = 1.f / l2[1];
    int r0 = q0 + wq * 16 + (lane >> 2);
#pragma unroll
    for (int j = 0; j < 8; j++) {
        int col = h * 64 + j * 8 + (lane & 3) * 2;
        size_t g0 = (tokbase + r0) * 1024 + col;
        size_t g1 = (tokbase + r0 + 8) * 1024 + col;
        uint32_t hh, ll;
        split2(oa[j][0] * inv0, oa[j][1] * inv0, hh, ll);
        *reinterpret_cast<uint32_t*>(oh + g0) = hh;
        *reinterpret_cast<uint32_t*>(ol + g0) = ll;
        split2(oa[j][2] * inv1, oa[j][3] * inv1, hh, ll);
        *reinterpret_cast<uint32_t*>(oh + g1) = hh;
        *reinterpret_cast<uint32_t*>(ol + g1) = ll;
    }
}

// ---------------- layernorm ----------------------------------------------------
__global__ __launch_bounds__(256) void ln_kernel(const float* __restrict__ in,
                                                 const float* __restrict__ gamma,
                                                 const float* __restrict__ beta,
                                                 float* __restrict__ outF,
                                                 __nv_bfloat16* __restrict__ outH,
                                                 __nv_bfloat16* __restrict__ outL)
{
    const int row = blockIdx.x, tid = threadIdx.x;
    const float* p = in + (size_t)row * 1024;
    float4 v = *(const float4*)(p + tid * 4);
    float s  = v.x + v.y + v.z + v.w;
    float ss = v.x * v.x + v.y * v.y + v.z * v.z + v.w * v.w;
#pragma unroll
    for (int off = 16; off > 0; off >>= 1) {
        s  += __shfl_xor_sync(0xffffffffu, s,  off);
        ss += __shfl_xor_sync(0xffffffffu, ss, off);
    }
    __shared__ float sb[8], ssb[8];
    __shared__ float smu, sinv;
    if ((tid & 31) == 0) { sb[tid >> 5] = s; ssb[tid >> 5] = ss; }
    __syncthreads();
    if (tid == 0) {
        float S = 0.f, SS = 0.f;
#pragma unroll
        for (int i = 0; i < 8; i++) { S += sb[i]; SS += ssb[i]; }
        float mu  = S * (1.f / 1024.f);
        float var = SS * (1.f / 1024.f) - mu * mu;
        smu = mu; sinv = rsqrtf(var + 1e-5f);
    }
    __syncthreads();
    float mu = smu, inv = sinv;
    float4 g = *(const float4*)(gamma + tid * 4);
    float4 b = *(const float4*)(beta  + tid * 4);
    float4 o;
    o.x = (v.x - mu) * inv * g.x + b.x;
    o.y = (v.y - mu) * inv * g.y + b.y;
    o.z = (v.z - mu) * inv * g.z + b.z;
    o.w = (v.w - mu) * inv * g.w + b.w;
    size_t idx = (size_t)row * 1024 + tid * 4;
    *(float4*)&outF[idx] = o;
    if (outH) {
        uint32_t h0, l0, h1, l1;
        split2(o.x, o.y, h0, l0);
        split2(o.z, o.w, h1, l1);
        *reinterpret_cast<uint32_t*>(outH + idx)     = h0;
        *reinterpret_cast<uint32_t*>(outH + idx + 2) = h1;
        *reinterpret_cast<uint32_t*>(outL + idx)     = l0;
        *reinterpret_cast<uint32_t*>(outL + idx + 2) = l1;
    }
}

// ---------------- launch --------------------------------------------------------
extern "C" void kernel_launch(void* const* d_in, const int* in_sizes, int n_in,
                              void* d_out, int out_size)
{
    const float* x     = (const float*)d_in[0];
    const float* Wq    = (const float*)d_in[1];
    const float* Wk    = (const float*)d_in[2];
    const float* Wv    = (const float*)d_in[3];
    const float* Wo    = (const float*)d_in[4];
    const float* ln1_g = (const float*)d_in[5];
    const float* ln1_b = (const float*)d_in[6];
    const float* W1    = (const float*)d_in[7];
    const float* b1    = (const float*)d_in[8];
    const float* W2    = (const float*)d_in[9];
    const float* b2    = (const float*)d_in[10];
    const float* ln2_g = (const float*)d_in[11];
    const float* ln2_b = (const float*)d_in[12];
    float* out = (float*)d_out;

    cudaFuncSetAttribute(gemm_mma,  cudaFuncAttributeMaxDynamicSharedMemorySize, GEMM_SMEM);
    cudaFuncSetAttribute(flash_hmma, cudaFuncAttributeMaxDynamicSharedMemorySize, ATT_SMEM);

    float *wqkv, *t1, *x1, *t2;
    __nv_bfloat16 *wqkvh, *wqkvl, *xh, *xl, *qkvh, *qkvl, *oh, *ol, *woh, *wol;
    __nv_bfloat16 *x1h, *x1l, *w1h, *w1l, *hh, *hl, *w2h, *w2l;
    cudaGetSymbolAddress((void**)&wqkv,  g_wqkv);
    cudaGetSymbolAddress((void**)&t1,    g_t1);
    cudaGetSymbolAddress((void**)&x1,    g_x1);
    cudaGetSymbolAddress((void**)&t2,    g_t2);
    cudaGetSymbolAddress((void**)&wqkvh, g_wqkvh);
    cudaGetSymbolAddress((void**)&wqkvl, g_wqkvl);
    cudaGetSymbolAddress((void**)&xh,    g_xh);
    cudaGetSymbolAddress((void**)&xl,    g_xl);
    cudaGetSymbolAddress((void**)&qkvh,  g_qkvh);
    cudaGetSymbolAddress((void**)&qkvl,  g_qkvl);
    cudaGetSymbolAddress((void**)&oh,    g_oh);
    cudaGetSymbolAddress((void**)&ol,    g_ol);
    cudaGetSymbolAddress((void**)&woh,   g_woh);
    cudaGetSymbolAddress((void**)&wol,   g_wol);
    cudaGetSymbolAddress((void**)&x1h,   g_x1h);
    cudaGetSymbolAddress((void**)&x1l,   g_x1l);
    cudaGetSymbolAddress((void**)&w1h,   g_w1h);
    cudaGetSymbolAddress((void**)&w1l,   g_w1l);
    cudaGetSymbolAddress((void**)&hh,    g_hh);
    cudaGetSymbolAddress((void**)&hl,    g_hl);
    cudaGetSymbolAddress((void**)&w2h,   g_w2h);
    cudaGetSymbolAddress((void**)&w2l,   g_w2l);

    // weight prep
    repack_qkv<<<12288, 256>>>(Wq, Wk, Wv, wqkv);
    transpose_split<<<dim3(96, 32),  dim3(32, 8)>>>(wqkv, 1024, 3072, wqkvh, wqkvl);
    transpose_split<<<dim3(32, 32),  dim3(32, 8)>>>(Wo,   1024, 1024, woh,   wol);
    transpose_split<<<dim3(128, 32), dim3(32, 8)>>>(W1,   1024, 4096, w1h,   w1l);
    transpose_split<<<dim3(32, 128), dim3(32, 8)>>>(W2,   4096, 1024, w2h,   w2l);
    split_plain<<<16384, 256>>>(x, xh, xl);

    // 1. QKV projection -> qkv bf16 hi/lo (no fp32 round trip)
    gemm_mma<<<dim3(24, 32), 256, GEMM_SMEM>>>(xh, xl, wqkvh, wqkvl, 4096, 3072, 1024,
                                               nullptr, nullptr, 0, nullptr, qkvh, qkvl);
    // 2. HMMA flash attention -> o hi/lo
    flash_hmma<<<dim3(16, NH, BATCH), 256, ATT_SMEM>>>(qkvh, qkvl, oh, ol);
    // 3. output projection + residual x -> t1 fp32
    gemm_mma<<<dim3(8, 32), 256, GEMM_SMEM>>>(oh, ol, woh, wol, 4096, 1024, 1024,
                                              nullptr, x, 0, t1, nullptr, nullptr);
    // 4. LN1 -> x1 fp32 + hi/lo
    ln_kernel<<<4096, 256>>>(t1, ln1_g, ln1_b, x1, x1h, x1l);
    // 5. FFN up + bias + relu -> h hi/lo
    gemm_mma<<<dim3(32, 32), 256, GEMM_SMEM>>>(x1h, x1l, w1h, w1l, 4096, 4096, 1024,
                                               b1, nullptr, 1, nullptr, hh, hl);
    // 6. FFN down + bias + residual x1 -> t2 fp32
    gemm_mma<<<dim3(8, 32), 256, GEMM_SMEM>>>(hh, hl, w2h, w2l, 4096, 1024, 4096,
                                              b2, x1, 0, t2, nullptr, nullptr);
    // 7. LN2 -> out
    ln_kernel<<<4096, 256>>>(t2, ln2_g, ln2_b, out, nullptr, nullptr);
}

// round 5
// speedup vs baseline: 3.8178x; 1.4154x over previous
#include <cuda_runtime.h>
#include <cuda_fp16.h>
#include <cstdint>

#define SEQ    2048
#define BATCH  2
#define NH     16
#define QKVLD  3072
#define STAGES 4
#define STAGE_BYTES 49152
#define GEMM_SMEM (STAGES * STAGE_BYTES + 1024)
#define ATT_SMEM  (16384 + 2 * 32768 + 1024)

// ---------------- scratch (static device globals; no allocation) -------------
__device__ float   g_wqkv [1024u * 3072u];
__device__ __half  g_wqkvh[3072u * 1024u], g_wqkvl[3072u * 1024u];
__device__ __half  g_xh   [4096u * 1024u];
__device__ __half  g_qkvh [4096u * 3072u], g_qkvl [4096u * 3072u];
__device__ __half  g_oh   [4096u * 1024u];
__device__ __half  g_woh  [1024u * 1024u], g_wol  [1024u * 1024u];
__device__ float   g_t1   [4096u * 1024u];
__device__ float   g_x1   [4096u * 1024u];
__device__ __half  g_x1h  [4096u * 1024u];
__device__ __half  g_w1h  [4096u * 1024u], g_w1l  [4096u * 1024u];
__device__ __half  g_hh   [4096u * 4096u];
__device__ __half  g_w2h  [1024u * 4096u], g_w2l  [1024u * 4096u];
__device__ float   g_t2   [4096u * 1024u];

// ---------------- PTX helpers --------------------------------------------------
__device__ __forceinline__ uint32_t smem_u32(const void* p) {
    uint32_t a;
    asm("{ .reg .u64 t; cvta.to.shared.u64 t, %1; cvt.u32.u64 %0, t; }" : "=r"(a) : "l"(p));
    return a;
}
__device__ __forceinline__ void cp16(uint32_t s, const void* g) {
    asm volatile("cp.async.cg.shared.global [%0], [%1], 16;" :: "r"(s), "l"(g));
}
#define CP_COMMIT()  asm volatile("cp.async.commit_group;" ::: "memory")
#define CP_WAIT(n)   asm volatile("cp.async.wait_group %0;" :: "n"(n) : "memory")

__device__ __forceinline__ void ldsm4(uint32_t& r0, uint32_t& r1, uint32_t& r2, uint32_t& r3,
                                      uint32_t addr) {
    asm volatile("ldmatrix.sync.aligned.m8n8.x4.shared.b16 {%0,%1,%2,%3}, [%4];"
                 : "=r"(r0), "=r"(r1), "=r"(r2), "=r"(r3) : "r"(addr));
}
__device__ __forceinline__ void ldsm4t(uint32_t& r0, uint32_t& r1, uint32_t& r2, uint32_t& r3,
                                       uint32_t addr) {
    asm volatile("ldmatrix.sync.aligned.m8n8.x4.trans.shared.b16 {%0,%1,%2,%3}, [%4];"
                 : "=r"(r0), "=r"(r1), "=r"(r2), "=r"(r3) : "r"(addr));
}
__device__ __forceinline__ void mma16816(float* d, const uint32_t* a, const uint32_t* b) {
    asm volatile(
        "mma.sync.aligned.m16n8k16.row.col.f32.f16.f16.f32 "
        "{%0,%1,%2,%3}, {%4,%5,%6,%7}, {%8,%9}, {%0,%1,%2,%3};"
        : "+f"(d[0]), "+f"(d[1]), "+f"(d[2]), "+f"(d[3])
        : "r"(a[0]), "r"(a[1]), "r"(a[2]), "r"(a[3]), "r"(b[0]), "r"(b[1]));
}
// split two floats into packed fp16x2 hi / lo registers (elem0 in low half)
__device__ __forceinline__ void split2h(float a, float b, uint32_t& h, uint32_t& l) {
    __half ha = __float2half_rn(a), hb = __float2half_rn(b);
    __half la = __float2half_rn(a - __half2float(ha));
    __half lb = __float2half_rn(b - __half2float(hb));
    h = (uint32_t)__half_as_ushort(ha) | ((uint32_t)__half_as_ushort(hb) << 16);
    l = (uint32_t)__half_as_ushort(la) | ((uint32_t)__half_as_ushort(lb) << 16);
}
__device__ __forceinline__ uint32_t pack2h(float a, float b) {
    __half2 p = __floats2half2_rn(a, b);
    return *reinterpret_cast<uint32_t*>(&p);
}

// ---------------- prep kernels -----------------------------------------------
__global__ void repack_qkv(const float* __restrict__ Wq, const float* __restrict__ Wk,
                           const float* __restrict__ Wv, float* __restrict__ Wqkv)
{
    int idx = blockIdx.x * blockDim.x + threadIdx.x;
    int w   = idx >> 20;
    int rem = idx & 1048575;
    int h   = rem >> 16;
    int d   = (rem >> 6) & 1023;
    int k   = rem & 63;
    const float* src = (w == 0) ? Wq : (w == 1) ? Wk : Wv;
    Wqkv[(size_t)d * QKVLD + w * 1024 + h * 64 + k] = src[rem];
}

// in [Rk, Cn] f32 row-major -> out hi/lo [Cn, Rk] fp16
__global__ void transpose_split(const float* __restrict__ in, int Rk, int Cn,
                                __half* __restrict__ oh, __half* __restrict__ ol)
{
    __shared__ float t[32][33];
    int c0 = blockIdx.x * 32, r0 = blockIdx.y * 32;
    for (int i = threadIdx.y; i < 32; i += 8)
        t[i][threadIdx.x] = in[(size_t)(r0 + i) * Cn + c0 + threadIdx.x];
    __syncthreads();
    for (int i = threadIdx.y; i < 32; i += 8) {
        float v = t[threadIdx.x][i];
        __half hh = __float2half_rn(v);
        __half ll = __float2half_rn(v - __half2float(hh));
        size_t o = (size_t)(c0 + i) * Rk + r0 + threadIdx.x;
        oh[o] = hh; ol[o] = ll;
    }
}

__global__ void split_plain(const float* __restrict__ in, __half* __restrict__ oh)
{
    int idx = blockIdx.x * blockDim.x + threadIdx.x;
    oh[idx] = __float2half_rn(in[idx]);
}

// ---------------- mma.sync fp16x2 GEMM: C = A (Bh+Bl)^T -----------------------
// A [M,K] fp16 (rounded), B [N,K] fp16 hi/lo (exact split). Tile 128x128x64.
// Stage layout: A[0,16K) Bh[16K,32K) Bl[32K,48K). Rows 128B, swizzle c^=(r&7).
__device__ __forceinline__ void g_load_stage(uint32_t sb,
    const __half* A, const __half* Bh, const __half* Bl,
    int K, int m0, int n0, int k0, int tid)
{
#pragma unroll
    for (int it = 0; it < 4; it++) {
        int idx = it * 256 + tid;
        int r = idx >> 3, c = idx & 7;
        uint32_t soff = (uint32_t)(r * 128 + ((c ^ (r & 7)) << 4));
        size_t ga = (size_t)(m0 + r) * K + k0 + c * 8;
        size_t gb = (size_t)(n0 + r) * K + k0 + c * 8;
        cp16(sb         + soff, A  + ga);
        cp16(sb + 16384 + soff, Bh + gb);
        cp16(sb + 32768 + soff, Bl + gb);
    }
}

__global__ __launch_bounds__(256, 1) void gemm_mma(
    const __half* __restrict__ A,
    const __half* __restrict__ Bh, const __half* __restrict__ Bl,
    int M, int N, int K,
    const float* __restrict__ bias, const float* __restrict__ res, int relu,
    float* __restrict__ outF, __half* __restrict__ outH, __half* __restrict__ outL)
{
    extern __shared__ char dsm_raw[];
    uint32_t base = (smem_u32(dsm_raw) + 1023) & ~1023u;

    const int tid  = threadIdx.x;
    const int wid  = tid >> 5;
    const int lane = tid & 31;
    const int wm   = wid >> 2;
    const int wn   = wid & 3;
    const int m0   = blockIdx.y * 128;
    const int n0   = blockIdx.x * 128;
    const int wr   = wm * 64;
    const int wc   = wn * 32;
    const int l15  = lane & 15;
    const int hi16 = lane >> 4;

    uint32_t a_row[4], a_sw[4], b_row[2], b_sw[2];
#pragma unroll
    for (int mt = 0; mt < 4; mt++) {
        int r = wr + mt * 16 + l15;
        a_row[mt] = (uint32_t)(r * 128);
        a_sw[mt]  = (uint32_t)(r & 7);
    }
#pragma unroll
    for (int nt = 0; nt < 2; nt++) {
        int r = wc + nt * 16 + l15;
        b_row[nt] = (uint32_t)(r * 128);
        b_sw[nt]  = (uint32_t)(r & 7);
    }

    float acc[4][4][4];
#pragma unroll
    for (int i = 0; i < 4; i++)
#pragma unroll
        for (int j = 0; j < 4; j++)
#pragma unroll
            for (int q = 0; q < 4; q++) acc[i][j][q] = 0.f;

    const int nK = K >> 6;

#pragma unroll
    for (int s = 0; s < STAGES - 1; s++) {
        g_load_stage(base + s * STAGE_BYTES, A, Bh, Bl, K, m0, n0, s * 64, tid);
        CP_COMMIT();
    }

    for (int kt = 0; kt < nK; kt++) {
        CP_WAIT(STAGES - 2);
        __syncthreads();

        int ls = kt + STAGES - 1;
        if (ls < nK)
            g_load_stage(base + (ls % STAGES) * STAGE_BYTES, A, Bh, Bl, K, m0, n0, ls * 64, tid);
        CP_COMMIT();

        uint32_t sb = base + (kt % STAGES) * STAGE_BYTES;
#pragma unroll
        for (int kh = 0; kh < 4; kh++) {
            uint32_t ah[4][4], bh[4][2], bl[4][2];
#pragma unroll
            for (int mt = 0; mt < 4; mt++) {
                uint32_t co = (uint32_t)(((2 * kh + hi16) ^ a_sw[mt]) << 4);
                ldsm4(ah[mt][0], ah[mt][1], ah[mt][2], ah[mt][3], sb + a_row[mt] + co);
            }
#pragma unroll
            for (int nt = 0; nt < 2; nt++) {
                uint32_t co = (uint32_t)(((2 * kh + hi16) ^ b_sw[nt]) << 4);
                uint32_t t0, t1, t2, t3;
                ldsm4(t0, t1, t2, t3, sb + 16384 + b_row[nt] + co);
                bh[2 * nt][0] = t0; bh[2 * nt + 1][0] = t1;
                bh[2 * nt][1] = t2; bh[2 * nt + 1][1] = t3;
                ldsm4(t0, t1, t2, t3, sb + 32768 + b_row[nt] + co);
                bl[2 * nt][0] = t0; bl[2 * nt + 1][0] = t1;
                bl[2 * nt][1] = t2; bl[2 * nt + 1][1] = t3;
            }
#pragma unroll
            for (int mt = 0; mt < 4; mt++)
#pragma unroll
                for (int j = 0; j < 4; j++) {
                    mma16816(acc[mt][j], ah[mt], bh[j]);
                    mma16816(acc[mt][j], ah[mt], bl[j]);
                }
        }
        __syncthreads();
    }

    const int rq = lane >> 2;
    const int cq = (lane & 3) * 2;
#pragma unroll
    for (int mt = 0; mt < 4; mt++)
#pragma unroll
        for (int half = 0; half < 2; half++) {
            int row = m0 + wr + mt * 16 + rq + half * 8;
            size_t rb = (size_t)row * N;
#pragma unroll
            for (int j = 0; j < 4; j++) {
                int col = n0 + wc + j * 8 + cq;
                float v0 = acc[mt][j][half * 2 + 0];
                float v1 = acc[mt][j][half * 2 + 1];
                if (bias) { v0 += bias[col]; v1 += bias[col + 1]; }
                if (relu) { v0 = fmaxf(v0, 0.f); v1 = fmaxf(v1, 0.f); }
                if (res)  {
                    float2 rr = *(const float2*)&res[rb + col];
                    v0 += rr.x; v1 += rr.y;
                }
                if (outF) *(float2*)&outF[rb + col] = make_float2(v0, v1);
                if (outH) {
                    if (outL) {
                        uint32_t hh, ll;
                        split2h(v0, v1, hh, ll);
                        *reinterpret_cast<uint32_t*>(outH + rb + col) = hh;
                        *reinterpret_cast<uint32_t*>(outL + rb + col) = ll;
                    } else {
                        *reinterpret_cast<uint32_t*>(outH + rb + col) = pack2h(v0, v1);
                    }
                }
            }
        }
}

// ---------------- HMMA flash attention (fp16x2) --------------------------------
// Q tile 128x64 fp16 single; K/V hi/lo. smem: Q[0,16K); stage s at 16K+s*32K:
// KH+0 KL+8K VH+16K VL+24K.
__device__ __forceinline__ void att_load_kv(uint32_t sb,
    const __half* qh, const __half* ql, size_t tokbase, int h, int kt, int tid)
{
#pragma unroll
    for (int it = 0; it < 2; it++) {
        int idx = it * 256 + tid;
        int r = idx >> 3, c = idx & 7;
        uint32_t sw = (uint32_t)(r * 128 + ((c ^ (r & 7)) << 4));
        size_t gk = (tokbase + kt * 64 + r) * QKVLD + 1024 + h * 64 + c * 8;
        size_t gv = gk + 1024;
        cp16(sb          + sw, qh + gk);
        cp16(sb + 8192   + sw, ql + gk);
        cp16(sb + 16384  + sw, qh + gv);
        cp16(sb + 24576  + sw, ql + gv);
    }
}

__global__ __launch_bounds__(256, 1) void flash_hmma(
    const __half* __restrict__ qh, const __half* __restrict__ ql,
    __half* __restrict__ oh)
{
    extern __shared__ char smem_raw[];
    uint32_t base = (smem_u32(smem_raw) + 1023) & ~1023u;
    const uint32_t QH = base;

    const int tid  = threadIdx.x;
    const int wq   = tid >> 5;
    const int lane = tid & 31;
    const int l15  = lane & 15;
    const int hi16 = lane >> 4;
    const int q0   = blockIdx.x * 128;
    const int h    = blockIdx.y;
    const int b    = blockIdx.z;
    const size_t tokbase = (size_t)b * SEQ;

    // Q tile (single fp16) + K/V stage 0
#pragma unroll
    for (int it = 0; it < 4; it++) {
        int idx = it * 256 + tid;
        int r = idx >> 3, c = idx & 7;
        uint32_t sw = (uint32_t)(r * 128 + ((c ^ (r & 7)) << 4));
        size_t g = (tokbase + q0 + r) * QKVLD + h * 64 + c * 8;
        cp16(QH + sw, qh + g);
    }
    att_load_kv(base + 16384, qh, ql, tokbase, h, 0, tid);
    CP_COMMIT();

    float m2[2] = {-1e30f, -1e30f};
    float l2[2] = {0.f, 0.f};
    float oa[8][4];
#pragma unroll
    for (int j = 0; j < 8; j++)
#pragma unroll
        for (int q = 0; q < 4; q++) oa[j][q] = 0.f;

    const uint32_t qrow = (uint32_t)((wq * 16 + l15) * 128);
    const uint32_t qsw  = (uint32_t)((wq * 16 + l15) & 7);

    for (int kt = 0; kt < SEQ / 64; kt++) {
        CP_WAIT(0);
        __syncthreads();
        if (kt + 1 < SEQ / 64)
            att_load_kv(base + 16384 + ((kt + 1) & 1) * 32768, qh, ql, tokbase, h, kt + 1, tid);
        CP_COMMIT();

        uint32_t sb = base + 16384 + (kt & 1) * 32768;

        // ---- S = Q K^T (2-pass) ---------------------------------------------
        float sa[8][4];
#pragma unroll
        for (int j = 0; j < 8; j++)
#pragma unroll
            for (int q = 0; q < 4; q++) sa[j][q] = 0.f;

#pragma unroll
        for (int kc = 0; kc < 4; kc++) {
            uint32_t co_a = (uint32_t)(((2 * kc + hi16) ^ qsw) << 4);
            uint32_t ah[4];
            ldsm4(ah[0], ah[1], ah[2], ah[3], QH + qrow + co_a);

            uint32_t kbh[8][2], kbl[8][2];
#pragma unroll
            for (int nt = 0; nt < 4; nt++) {
                int r = nt * 16 + l15;
                uint32_t co = (uint32_t)(((2 * kc + hi16) ^ (r & 7)) << 4);
                uint32_t t0, t1, t2, t3;
                ldsm4(t0, t1, t2, t3, sb + r * 128 + co);
                kbh[2 * nt][0] = t0; kbh[2 * nt][1] = t2;
                kbh[2 * nt + 1][0] = t1; kbh[2 * nt + 1][1] = t3;
                ldsm4(t0, t1, t2, t3, sb + 8192 + r * 128 + co);
                kbl[2 * nt][0] = t0; kbl[2 * nt][1] = t2;
                kbl[2 * nt + 1][0] = t1; kbl[2 * nt + 1][1] = t3;
            }
#pragma unroll
            for (int j = 0; j < 8; j++) {
                mma16816(sa[j], ah, kbh[j]);
                mma16816(sa[j], ah, kbl[j]);
            }
        }

        // ---- online softmax --------------------------------------------------
#pragma unroll
        for (int half = 0; half < 2; half++) {
            float mx = -1e30f;
#pragma unroll
            for (int j = 0; j < 8; j++) {
                sa[j][2 * half]     *= 0.125f;
                sa[j][2 * half + 1] *= 0.125f;
                mx = fmaxf(mx, fmaxf(sa[j][2 * half], sa[j][2 * half + 1]));
            }
            mx = fmaxf(mx, __shfl_xor_sync(0xffffffffu, mx, 1));
            mx = fmaxf(mx, __shfl_xor_sync(0xffffffffu, mx, 2));
            float nm    = fmaxf(m2[half], mx);
            float alpha = __expf(m2[half] - nm);
            float rs = 0.f;
#pragma unroll
            for (int j = 0; j < 8; j++) {
                sa[j][2 * half]     = __expf(sa[j][2 * half]     - nm);
                sa[j][2 * half + 1] = __expf(sa[j][2 * half + 1] - nm);
                rs += sa[j][2 * half] + sa[j][2 * half + 1];
            }
            rs += __shfl_xor_sync(0xffffffffu, rs, 1);
            rs += __shfl_xor_sync(0xffffffffu, rs, 2);
            l2[half] = l2[half] * alpha + rs;
            m2[half] = nm;
#pragma unroll
            for (int j = 0; j < 8; j++) {
                oa[j][2 * half]     *= alpha;
                oa[j][2 * half + 1] *= alpha;
            }
        }

        // ---- P -> fp16 a-frags ------------------------------------------------
        uint32_t ph[4][4];
#pragma unroll
        for (int kc = 0; kc < 4; kc++) {
            int j0 = 2 * kc, j1 = 2 * kc + 1;
            ph[kc][0] = pack2h(sa[j0][0], sa[j0][1]);
            ph[kc][1] = pack2h(sa[j0][2], sa[j0][3]);
            ph[kc][2] = pack2h(sa[j1][0], sa[j1][1]);
            ph[kc][3] = pack2h(sa[j1][2], sa[j1][3]);
        }

        // ---- O += P V (2-pass), V via ldmatrix.trans ---------------------------
#pragma unroll
        for (int kc = 0; kc < 4; kc++) {
            int rowt = kc * 16 + ((lane >> 4) << 3) + (lane & 7);
            uint32_t vbh[8][2], vbl[8][2];
#pragma unroll
            for (int jt = 0; jt < 4; jt++) {
                int c8 = jt * 2 + ((lane >> 3) & 1);
                uint32_t ad = sb + 16384 + rowt * 128 + (uint32_t)(((c8 ^ (rowt & 7))) << 4);
                uint32_t t0, t1, t2, t3;
                ldsm4t(t0, t1, t2, t3, ad);
                vbh[2 * jt][0] = t0; vbh[2 * jt][1] = t2;
                vbh[2 * jt + 1][0] = t1; vbh[2 * jt + 1][1] = t3;
                ldsm4t(t0, t1, t2, t3, ad + 8192);
                vbl[2 * jt][0] = t0; vbl[2 * jt][1] = t2;
                vbl[2 * jt + 1][0] = t1; vbl[2 * jt + 1][1] = t3;
            }
#pragma unroll
            for (int j = 0; j < 8; j++) {
                mma16816(oa[j], ph[kc], vbh[j]);
                mma16816(oa[j], ph[kc], vbl[j]);
            }
        }
    }

    // ---- epilogue -------------------------------------------------------------
    float inv0 = 1.f / l2[0];
    float inv1 = 1.f / l2[1];
    int r0 = q0 + wq * 16 + (lane >> 2);
#pragma unroll
    for (int j = 0; j < 8; j++) {
        int col = h * 64 + j * 8 + (lane & 3) * 2;
        size_t g0 = (tokbase + r0) * 1024 + col;
        size_t g1 = (tokbase + r0 + 8) * 1024 + col;
        *reinterpret_cast<uint32_t*>(oh + g0) = pack2h(oa[j][0] * inv0, oa[j][1] * inv0);
        *reinterpret_cast<uint32_t*>(oh + g1) = pack2h(oa[j][2] * inv1, oa[j][3] * inv1);
    }
}

// ---------------- layernorm ----------------------------------------------------
__global__ __launch_bounds__(256) void ln_kernel(const float* __restrict__ in,
                                                 const float* __restrict__ gamma,
                                                 const float* __restrict__ beta,
                                                 float* __restrict__ outF,
                                                 __half* __restrict__ outH)
{
    const int row = blockIdx.x, tid = threadIdx.x;
    const float* p = in + (size_t)row * 1024;
    float4 v = *(const float4*)(p + tid * 4);
    float s  = v.x + v.y + v.z + v.w;
    float ss = v.x * v.x + v.y * v.y + v.z * v.z + v.w * v.w;
#pragma unroll
    for (int off = 16; off > 0; off >>= 1) {
        s  += __shfl_xor_sync(0xffffffffu, s,  off);
        ss += __shfl_xor_sync(0xffffffffu, ss, off);
    }
    __shared__ float sb[8], ssb[8];
    __shared__ float smu, sinv;
    if ((tid & 31) == 0) { sb[tid >> 5] = s; ssb[tid >> 5] = ss; }
    __syncthreads();
    if (tid == 0) {
        float S = 0.f, SS = 0.f;
#pragma unroll
        for (int i = 0; i < 8; i++) { S += sb[i]; SS += ssb[i]; }
        float mu  = S * (1.f / 1024.f);
        float var = SS * (1.f / 1024.f) - mu * mu;
        smu = mu; sinv = rsqrtf(var + 1e-5f);
    }
    __syncthreads();
    float mu = smu, inv = sinv;
    float4 g = *(const float4*)(gamma + tid * 4);
    float4 b = *(const float4*)(beta  + tid * 4);
    float4 o;
    o.x = (v.x - mu) * inv * g.x + b.x;
    o.y = (v.y - mu) * inv * g.y + b.y;
    o.z = (v.z - mu) * inv * g.z + b.z;
    o.w = (v.w - mu) * inv * g.w + b.w;
    size_t idx = (size_t)row * 1024 + tid * 4;
    *(float4*)&outF[idx] = o;
    if (outH) {
        *reinterpret_cast<uint32_t*>(outH + idx)     = pack2h(o.x, o.y);
        *reinterpret_cast<uint32_t*>(outH + idx + 2) = pack2h(o.z, o.w);
    }
}

// ---------------- launch --------------------------------------------------------
extern "C" void kernel_launch(void* const* d_in, const int* in_sizes, int n_in,
                              void* d_out, int out_size)
{
    const float* x     = (const float*)d_in[0];
    const float* Wq    = (const float*)d_in[1];
    const float* Wk    = (const float*)d_in[2];
    const float* Wv    = (const float*)d_in[3];
    const float* Wo    = (const float*)d_in[4];
    const float* ln1_g = (const float*)d_in[5];
    const float* ln1_b = (const float*)d_in[6];
    const float* W1    = (const float*)d_in[7];
    const float* b1    = (const float*)d_in[8];
    const float* W2    = (const float*)d_in[9];
    const float* b2    = (const float*)d_in[10];
    const float* ln2_g = (const float*)d_in[11];
    const float* ln2_b = (const float*)d_in[12];
    float* out = (float*)d_out;

    cudaFuncSetAttribute(gemm_mma,   cudaFuncAttributeMaxDynamicSharedMemorySize, GEMM_SMEM);
    cudaFuncSetAttribute(flash_hmma, cudaFuncAttributeMaxDynamicSharedMemorySize, ATT_SMEM);

    float *wqkv, *t1, *x1, *t2;
    __half *wqkvh, *wqkvl, *xh, *qkvh, *qkvl, *oh, *woh, *wol;
    __half *x1h, *w1h, *w1l, *hh, *w2h, *w2l;
    cudaGetSymbolAddress((void**)&wqkv,  g_wqkv);
    cudaGetSymbolAddress((void**)&t1,    g_t1);
    cudaGetSymbolAddress((void**)&x1,    g_x1);
    cudaGetSymbolAddress((void**)&t2,    g_t2);
    cudaGetSymbolAddress((void**)&wqkvh, g_wqkvh);
    cudaGetSymbolAddress((void**)&wqkvl, g_wqkvl);
    cudaGetSymbolAddress((void**)&xh,    g_xh);
    cudaGetSymbolAddress((void**)&qkvh,  g_qkvh);
    cudaGetSymbolAddress((void**)&qkvl,  g_qkvl);
    cudaGetSymbolAddress((void**)&oh,    g_oh);
    cudaGetSymbolAddress((void**)&woh,   g_woh);
    cudaGetSymbolAddress((void**)&wol,   g_wol);
    cudaGetSymbolAddress((void**)&x1h,   g_x1h);
    cudaGetSymbolAddress((void**)&w1h,   g_w1h);
    cudaGetSymbolAddress((void**)&w1l,   g_w1l);
    cudaGetSymbolAddress((void**)&hh,    g_hh);
    cudaGetSymbolAddress((void**)&w2h,   g_w2h);
    cudaGetSymbolAddress((void**)&w2l,   g_w2l);

    // weight prep
    repack_qkv<<<12288, 256>>>(Wq, Wk, Wv, wqkv);
    transpose_split<<<dim3(96, 32),  dim3(32, 8)>>>(wqkv, 1024, 3072, wqkvh, wqkvl);
    transpose_split<<<dim3(32, 32),  dim3(32, 8)>>>(Wo,   1024, 1024, woh,   wol);
    transpose_split<<<dim3(128, 32), dim3(32, 8)>>>(W1,   1024, 4096, w1h,   w1l);
    transpose_split<<<dim3(32, 128), dim3(32, 8)>>>(W2,   4096, 1024, w2h,   w2l);
    split_plain<<<16384, 256>>>(x, xh);

    // 1. QKV projection -> qkv fp16 hi/lo
    gemm_mma<<<dim3(24, 32), 256, GEMM_SMEM>>>(xh, wqkvh, wqkvl, 4096, 3072, 1024,
                                               nullptr, nullptr, 0, nullptr, qkvh, qkvl);
    // 2. HMMA flash attention -> o fp16
    flash_hmma<<<dim3(16, NH, BATCH), 256, ATT_SMEM>>>(qkvh, qkvl, oh);
    // 3. output projection + residual x -> t1 fp32
    gemm_mma<<<dim3(8, 32), 256, GEMM_SMEM>>>(oh, woh, wol, 4096, 1024, 1024,
                                              nullptr, x, 0, t1, nullptr, nullptr);
    // 4. LN1 -> x1 fp32 + fp16
    ln_kernel<<<4096, 256>>>(t1, ln1_g, ln1_b, x1, x1h);
    // 5. FFN up + bias + relu -> h fp16
    gemm_mma<<<dim3(32, 32), 256, GEMM_SMEM>>>(x1h, w1h, w1l, 4096, 4096, 1024,
                                               b1, nullptr, 1, nullptr, hh, nullptr);
    // 6. FFN down + bias + residual x1 -> t2 fp32
    gemm_mma<<<dim3(8, 32), 256, GEMM_SMEM>>>(hh, w2h, w2l, 4096, 1024, 4096,
                                              b2, x1, 0, t2, nullptr, nullptr);
    // 7. LN2 -> out
    ln_kernel<<<4096, 256>>>(t2, ln2_g, ln2_b, out, nullptr);
}

// round 6
// speedup vs baseline: 6.0497x; 1.5846x over previous
#include <cuda_runtime.h>
#include <cuda_fp16.h>
#include <cstdint>

#define SEQ    2048
#define BATCH  2
#define NH     16
#define QKVLD  3072
#define STAGES 4
#define STAGE_BYTES 32768
#define GEMM_SMEM (STAGES * STAGE_BYTES + 1024)
#define NSTG   4
#define ATT_SMEM  (16384 + NSTG * 16384 + 1024)

// ---------------- scratch (static device globals; no allocation) -------------
__device__ __half  g_wqkvh[3072u * 1024u];
__device__ __half  g_xh   [4096u * 1024u];
__device__ __half  g_qkvh [4096u * 3072u];
__device__ __half  g_oh   [4096u * 1024u];
__device__ __half  g_woh  [1024u * 1024u];
__device__ float   g_t1   [4096u * 1024u];
__device__ float   g_x1   [4096u * 1024u];
__device__ __half  g_x1h  [4096u * 1024u];
__device__ __half  g_w1h  [4096u * 1024u];
__device__ __half  g_hh   [4096u * 4096u];
__device__ __half  g_w2h  [1024u * 4096u];
__device__ float   g_t2   [4096u * 1024u];

// ---------------- PTX helpers --------------------------------------------------
__device__ __forceinline__ uint32_t smem_u32(const void* p) {
    uint32_t a;
    asm("{ .reg .u64 t; cvta.to.shared.u64 t, %1; cvt.u32.u64 %0, t; }" : "=r"(a) : "l"(p));
    return a;
}
__device__ __forceinline__ void cp16(uint32_t s, const void* g) {
    asm volatile("cp.async.cg.shared.global [%0], [%1], 16;" :: "r"(s), "l"(g));
}
#define CP_COMMIT()  asm volatile("cp.async.commit_group;" ::: "memory")
#define CP_WAIT(n)   asm volatile("cp.async.wait_group %0;" :: "n"(n) : "memory")

__device__ __forceinline__ void ldsm4(uint32_t& r0, uint32_t& r1, uint32_t& r2, uint32_t& r3,
                                      uint32_t addr) {
    asm volatile("ldmatrix.sync.aligned.m8n8.x4.shared.b16 {%0,%1,%2,%3}, [%4];"
                 : "=r"(r0), "=r"(r1), "=r"(r2), "=r"(r3) : "r"(addr));
}
__device__ __forceinline__ void ldsm4t(uint32_t& r0, uint32_t& r1, uint32_t& r2, uint32_t& r3,
                                       uint32_t addr) {
    asm volatile("ldmatrix.sync.aligned.m8n8.x4.trans.shared.b16 {%0,%1,%2,%3}, [%4];"
                 : "=r"(r0), "=r"(r1), "=r"(r2), "=r"(r3) : "r"(addr));
}
__device__ __forceinline__ void mma16816(float* d, const uint32_t* a, const uint32_t* b) {
    asm volatile(
        "mma.sync.aligned.m16n8k16.row.col.f32.f16.f16.f32 "
        "{%0,%1,%2,%3}, {%4,%5,%6,%7}, {%8,%9}, {%0,%1,%2,%3};"
        : "+f"(d[0]), "+f"(d[1]), "+f"(d[2]), "+f"(d[3])
        : "r"(a[0]), "r"(a[1]), "r"(a[2]), "r"(a[3]), "r"(b[0]), "r"(b[1]));
}
__device__ __forceinline__ uint32_t pack2h(float a, float b) {
    __half2 p = __floats2half2_rn(a, b);
    return *reinterpret_cast<uint32_t*>(&p);
}

// ---------------- prep kernels -----------------------------------------------
// Wq/Wk/Wv (16,1024,64) f32 -> Wqkv^T [3072,1024] fp16 (row n = w*1024+h*64+k)
__global__ void wqkv_transpose(const float* __restrict__ Wq, const float* __restrict__ Wk,
                               const float* __restrict__ Wv, __half* __restrict__ outT)
{
    __shared__ float t[32][33];
    int d0 = blockIdx.x * 32;          // col tile (d)
    int n0 = blockIdx.y * 32;          // row tile (n)
    int w  = n0 >> 10;
    int h  = (n0 >> 6) & 15;
    int k0 = n0 & 63;                  // 0 or 32
    const float* src = (w == 0) ? Wq : (w == 1) ? Wk : Wv;
    for (int j = threadIdx.y; j < 32; j += 8)
        t[j][threadIdx.x] = src[h * 65536 + (d0 + j) * 64 + k0 + threadIdx.x];
    __syncthreads();
    for (int j = threadIdx.y; j < 32; j += 8)
        outT[(size_t)(n0 + j) * 1024 + d0 + threadIdx.x] = __float2half_rn(t[threadIdx.x][j]);
}

// in [Rk, Cn] f32 row-major -> out [Cn, Rk] fp16
__global__ void transpose_h(const float* __restrict__ in, int Rk, int Cn,
                            __half* __restrict__ oT)
{
    __shared__ float t[32][33];
    int c0 = blockIdx.x * 32, r0 = blockIdx.y * 32;
    for (int i = threadIdx.y; i < 32; i += 8)
        t[i][threadIdx.x] = in[(size_t)(r0 + i) * Cn + c0 + threadIdx.x];
    __syncthreads();
    for (int i = threadIdx.y; i < 32; i += 8)
        oT[(size_t)(c0 + i) * Rk + r0 + threadIdx.x] = __float2half_rn(t[threadIdx.x][i]);
}

__global__ void split_plain(const float* __restrict__ in, __half* __restrict__ oh)
{
    int idx = blockIdx.x * blockDim.x + threadIdx.x;
    oh[idx] = __float2half_rn(in[idx]);
}

// ---------------- mma.sync fp16 GEMM: C = A B^T -------------------------------
// A [M,K], B [N,K] fp16. Tile 128x128x64. Stage: A[0,16K) B[16K,32K).
__device__ __forceinline__ void g_load_stage(uint32_t sb,
    const __half* A, const __half* B, int K, int m0, int n0, int k0, int tid)
{
#pragma unroll
    for (int it = 0; it < 4; it++) {
        int idx = it * 256 + tid;
        int r = idx >> 3, c = idx & 7;
        uint32_t soff = (uint32_t)(r * 128 + ((c ^ (r & 7)) << 4));
        cp16(sb         + soff, A + (size_t)(m0 + r) * K + k0 + c * 8);
        cp16(sb + 16384 + soff, B + (size_t)(n0 + r) * K + k0 + c * 8);
    }
}

__global__ __launch_bounds__(256, 1) void gemm_mma(
    const __half* __restrict__ A, const __half* __restrict__ B,
    int M, int N, int K,
    const float* __restrict__ bias, const float* __restrict__ res, int relu,
    float* __restrict__ outF, __half* __restrict__ outH)
{
    extern __shared__ char dsm_raw[];
    uint32_t base = (smem_u32(dsm_raw) + 1023) & ~1023u;

    const int tid  = threadIdx.x;
    const int wid  = tid >> 5;
    const int lane = tid & 31;
    const int wm   = wid >> 2;
    const int wn   = wid & 3;
    const int m0   = blockIdx.y * 128;
    const int n0   = blockIdx.x * 128;
    const int wr   = wm * 64;
    const int wc   = wn * 32;
    const int l15  = lane & 15;
    const int hi16 = lane >> 4;

    uint32_t a_row[4], a_sw[4], b_row[2], b_sw[2];
#pragma unroll
    for (int mt = 0; mt < 4; mt++) {
        int r = wr + mt * 16 + l15;
        a_row[mt] = (uint32_t)(r * 128);
        a_sw[mt]  = (uint32_t)(r & 7);
    }
#pragma unroll
    for (int nt = 0; nt < 2; nt++) {
        int r = wc + nt * 16 + l15;
        b_row[nt] = (uint32_t)(r * 128);
        b_sw[nt]  = (uint32_t)(r & 7);
    }

    float acc[4][4][4];
#pragma unroll
    for (int i = 0; i < 4; i++)
#pragma unroll
        for (int j = 0; j < 4; j++)
#pragma unroll
            for (int q = 0; q < 4; q++) acc[i][j][q] = 0.f;

    const int nK = K >> 6;

#pragma unroll
    for (int s = 0; s < STAGES - 1; s++) {
        g_load_stage(base + s * STAGE_BYTES, A, B, K, m0, n0, s * 64, tid);
        CP_COMMIT();
    }

    for (int kt = 0; kt < nK; kt++) {
        CP_WAIT(STAGES - 2);
        __syncthreads();

        int ls = kt + STAGES - 1;
        if (ls < nK)
            g_load_stage(base + (ls % STAGES) * STAGE_BYTES, A, B, K, m0, n0, ls * 64, tid);
        CP_COMMIT();

        uint32_t sb = base + (kt % STAGES) * STAGE_BYTES;
#pragma unroll
        for (int kh = 0; kh < 4; kh++) {
            uint32_t ah[4][4], bh[4][2];
#pragma unroll
            for (int mt = 0; mt < 4; mt++) {
                uint32_t co = (uint32_t)(((2 * kh + hi16) ^ a_sw[mt]) << 4);
                ldsm4(ah[mt][0], ah[mt][1], ah[mt][2], ah[mt][3], sb + a_row[mt] + co);
            }
#pragma unroll
            for (int nt = 0; nt < 2; nt++) {
                uint32_t co = (uint32_t)(((2 * kh + hi16) ^ b_sw[nt]) << 4);
                uint32_t t0, t1, t2, t3;
                ldsm4(t0, t1, t2, t3, sb + 16384 + b_row[nt] + co);
                bh[2 * nt][0] = t0; bh[2 * nt + 1][0] = t1;
                bh[2 * nt][1] = t2; bh[2 * nt + 1][1] = t3;
            }
#pragma unroll
            for (int mt = 0; mt < 4; mt++)
#pragma unroll
                for (int j = 0; j < 4; j++)
                    mma16816(acc[mt][j], ah[mt], bh[j]);
        }
        __syncthreads();
    }

    const int rq = lane >> 2;
    const int cq = (lane & 3) * 2;
#pragma unroll
    for (int mt = 0; mt < 4; mt++)
#pragma unroll
        for (int half = 0; half < 2; half++) {
            int row = m0 + wr + mt * 16 + rq + half * 8;
            size_t rb = (size_t)row * N;
#pragma unroll
            for (int j = 0; j < 4; j++) {
                int col = n0 + wc + j * 8 + cq;
                float v0 = acc[mt][j][half * 2 + 0];
                float v1 = acc[mt][j][half * 2 + 1];
                if (bias) { v0 += bias[col]; v1 += bias[col + 1]; }
                if (relu) { v0 = fmaxf(v0, 0.f); v1 = fmaxf(v1, 0.f); }
                if (res)  {
                    float2 rr = *(const float2*)&res[rb + col];
                    v0 += rr.x; v1 += rr.y;
                }
                if (outF) *(float2*)&outF[rb + col] = make_float2(v0, v1);
                if (outH) *reinterpret_cast<uint32_t*>(outH + rb + col) = pack2h(v0, v1);
            }
        }
}

// ---------------- HMMA flash attention (fp16 single-pass) ----------------------
// Q tile 128x64 at base; KV stage s at base+16K+s*16K: K[0,8K) V[8K,16K).
__device__ __forceinline__ void att_load_kv(uint32_t sb,
    const __half* qkv, size_t tokbase, int h, int kt, int tid)
{
#pragma unroll
    for (int it = 0; it < 2; it++) {
        int idx = it * 256 + tid;
        int r = idx >> 3, c = idx & 7;
        uint32_t sw = (uint32_t)(r * 128 + ((c ^ (r & 7)) << 4));
        size_t gk = (tokbase + kt * 64 + r) * QKVLD + 1024 + h * 64 + c * 8;
        cp16(sb        + sw, qkv + gk);
        cp16(sb + 8192 + sw, qkv + gk + 1024);
    }
}

__global__ __launch_bounds__(256, 1) void flash_hmma(
    const __half* __restrict__ qkv, __half* __restrict__ oh)
{
    extern __shared__ char smem_raw[];
    uint32_t base = (smem_u32(smem_raw) + 1023) & ~1023u;
    const uint32_t QH = base;

    const int tid  = threadIdx.x;
    const int wq   = tid >> 5;
    const int lane = tid & 31;
    const int l15  = lane & 15;
    const int hi16 = lane >> 4;
    const int q0   = blockIdx.x * 128;
    const int h    = blockIdx.y;
    const int b    = blockIdx.z;
    const size_t tokbase = (size_t)b * SEQ;

    // Q tile + KV stage 0 in group 0
#pragma unroll
    for (int it = 0; it < 4; it++) {
        int idx = it * 256 + tid;
        int r = idx >> 3, c = idx & 7;
        uint32_t sw = (uint32_t)(r * 128 + ((c ^ (r & 7)) << 4));
        cp16(QH + sw, qkv + (tokbase + q0 + r) * QKVLD + h * 64 + c * 8);
    }
    att_load_kv(base + 16384, qkv, tokbase, h, 0, tid);
    CP_COMMIT();
#pragma unroll
    for (int s = 1; s < NSTG - 1; s++) {
        att_load_kv(base + 16384 + s * 16384, qkv, tokbase, h, s, tid);
        CP_COMMIT();
    }

    float m2[2] = {-1e30f, -1e30f};
    float l2[2] = {0.f, 0.f};
    float oa[8][4];
#pragma unroll
    for (int j = 0; j < 8; j++)
#pragma unroll
        for (int q = 0; q < 4; q++) oa[j][q] = 0.f;

    const uint32_t qrow = (uint32_t)((wq * 16 + l15) * 128);
    const uint32_t qsw  = (uint32_t)((wq * 16 + l15) & 7);

    for (int kt = 0; kt < SEQ / 64; kt++) {
        CP_WAIT(NSTG - 2);
        __syncthreads();
        int ls = kt + NSTG - 1;
        if (ls < SEQ / 64)
            att_load_kv(base + 16384 + (ls % NSTG) * 16384, qkv, tokbase, h, ls, tid);
        CP_COMMIT();

        uint32_t sb = base + 16384 + (kt % NSTG) * 16384;

        // ---- S = Q K^T -------------------------------------------------------
        float sa[8][4];
#pragma unroll
        for (int j = 0; j < 8; j++)
#pragma unroll
            for (int q = 0; q < 4; q++) sa[j][q] = 0.f;

#pragma unroll
        for (int kc = 0; kc < 4; kc++) {
            uint32_t co_a = (uint32_t)(((2 * kc + hi16) ^ qsw) << 4);
            uint32_t ah[4];
            ldsm4(ah[0], ah[1], ah[2], ah[3], QH + qrow + co_a);

            uint32_t kbh[8][2];
#pragma unroll
            for (int nt = 0; nt < 4; nt++) {
                int r = nt * 16 + l15;
                uint32_t co = (uint32_t)(((2 * kc + hi16) ^ (r & 7)) << 4);
                uint32_t t0, t1, t2, t3;
                ldsm4(t0, t1, t2, t3, sb + r * 128 + co);
                kbh[2 * nt][0] = t0; kbh[2 * nt][1] = t2;
                kbh[2 * nt + 1][0] = t1; kbh[2 * nt + 1][1] = t3;
            }
#pragma unroll
            for (int j = 0; j < 8; j++)
                mma16816(sa[j], ah, kbh[j]);
        }

        // ---- online softmax ---------------------------------------------------
#pragma unroll
        for (int half = 0; half < 2; half++) {
            float mx = -1e30f;
#pragma unroll
            for (int j = 0; j < 8; j++) {
                sa[j][2 * half]     *= 0.125f;
                sa[j][2 * half + 1] *= 0.125f;
                mx = fmaxf(mx, fmaxf(sa[j][2 * half], sa[j][2 * half + 1]));
            }
            mx = fmaxf(mx, __shfl_xor_sync(0xffffffffu, mx, 1));
            mx = fmaxf(mx, __shfl_xor_sync(0xffffffffu, mx, 2));
            float nm    = fmaxf(m2[half], mx);
            float alpha = __expf(m2[half] - nm);
            float rs = 0.f;
#pragma unroll
            for (int j = 0; j < 8; j++) {
                sa[j][2 * half]     = __expf(sa[j][2 * half]     - nm);
                sa[j][2 * half + 1] = __expf(sa[j][2 * half + 1] - nm);
                rs += sa[j][2 * half] + sa[j][2 * half + 1];
            }
            rs += __shfl_xor_sync(0xffffffffu, rs, 1);
            rs += __shfl_xor_sync(0xffffffffu, rs, 2);
            l2[half] = l2[half] * alpha + rs;
            m2[half] = nm;
#pragma unroll
            for (int j = 0; j < 8; j++) {
                oa[j][2 * half]     *= alpha;
                oa[j][2 * half + 1] *= alpha;
            }
        }

        // ---- P -> fp16 a-frags --------------------------------------------------
        uint32_t ph[4][4];
#pragma unroll
        for (int kc = 0; kc < 4; kc++) {
            int j0 = 2 * kc, j1 = 2 * kc + 1;
            ph[kc][0] = pack2h(sa[j0][0], sa[j0][1]);
            ph[kc][1] = pack2h(sa[j0][2], sa[j0][3]);
            ph[kc][2] = pack2h(sa[j1][0], sa[j1][1]);
            ph[kc][3] = pack2h(sa[j1][2], sa[j1][3]);
        }

        // ---- O += P V, V via ldmatrix.trans --------------------------------------
#pragma unroll
        for (int kc = 0; kc < 4; kc++) {
            int rowt = kc * 16 + ((lane >> 4) << 3) + (lane & 7);
            uint32_t vbh[8][2];
#pragma unroll
            for (int jt = 0; jt < 4; jt++) {
                int c8 = jt * 2 + ((lane >> 3) & 1);
                uint32_t ad = sb + 8192 + rowt * 128 + (uint32_t)(((c8 ^ (rowt & 7))) << 4);
                uint32_t t0, t1, t2, t3;
                ldsm4t(t0, t1, t2, t3, ad);
                vbh[2 * jt][0] = t0; vbh[2 * jt][1] = t2;
                vbh[2 * jt + 1][0] = t1; vbh[2 * jt + 1][1] = t3;
            }
#pragma unroll
            for (int j = 0; j < 8; j++)
                mma16816(oa[j], ph[kc], vbh[j]);
        }
    }

    // ---- epilogue ---------------------------------------------------------------
    float inv0 = 1.f / l2[0];
    float inv1 = 1.f / l2[1];
    int r0 = q0 + wq * 16 + (lane >> 2);
#pragma unroll
    for (int j = 0; j < 8; j++) {
        int col = h * 64 + j * 8 + (lane & 3) * 2;
        size_t g0 = (tokbase + r0) * 1024 + col;
        size_t g1 = (tokbase + r0 + 8) * 1024 + col;
        *reinterpret_cast<uint32_t*>(oh + g0) = pack2h(oa[j][0] * inv0, oa[j][1] * inv0);
        *reinterpret_cast<uint32_t*>(oh + g1) = pack2h(oa[j][2] * inv1, oa[j][3] * inv1);
    }
}

// ---------------- layernorm -----------------------------------------------------
__global__ __launch_bounds__(256) void ln_kernel(const float* __restrict__ in,
                                                 const float* __restrict__ gamma,
                                                 const float* __restrict__ beta,
                                                 float* __restrict__ outF,
                                                 __half* __restrict__ outH)
{
    const int row = blockIdx.x, tid = threadIdx.x;
    const float* p = in + (size_t)row * 1024;
    float4 v = *(const float4*)(p + tid * 4);
    float s  = v.x + v.y + v.z + v.w;
    float ss = v.x * v.x + v.y * v.y + v.z * v.z + v.w * v.w;
#pragma unroll
    for (int off = 16; off > 0; off >>= 1) {
        s  += __shfl_xor_sync(0xffffffffu, s,  off);
        ss += __shfl_xor_sync(0xffffffffu, ss, off);
    }
    __shared__ float sb[8], ssb[8];
    __shared__ float smu, sinv;
    if ((tid & 31) == 0) { sb[tid >> 5] = s; ssb[tid >> 5] = ss; }
    __syncthreads();
    if (tid == 0) {
        float S = 0.f, SS = 0.f;
#pragma unroll
        for (int i = 0; i < 8; i++) { S += sb[i]; SS += ssb[i]; }
        float mu  = S * (1.f / 1024.f);
        float var = SS * (1.f / 1024.f) - mu * mu;
        smu = mu; sinv = rsqrtf(var + 1e-5f);
    }
    __syncthreads();
    float mu = smu, inv = sinv;
    float4 g = *(const float4*)(gamma + tid * 4);
    float4 b = *(const float4*)(beta  + tid * 4);
    float4 o;
    o.x = (v.x - mu) * inv * g.x + b.x;
    o.y = (v.y - mu) * inv * g.y + b.y;
    o.z = (v.z - mu) * inv * g.z + b.z;
    o.w = (v.w - mu) * inv * g.w + b.w;
    size_t idx = (size_t)row * 1024 + tid * 4;
    *(float4*)&outF[idx] = o;
    if (outH) {
        *reinterpret_cast<uint32_t*>(outH + idx)     = pack2h(o.x, o.y);
        *reinterpret_cast<uint32_t*>(outH + idx + 2) = pack2h(o.z, o.w);
    }
}

// ---------------- launch ----------------------------------------------------------
extern "C" void kernel_launch(void* const* d_in, const int* in_sizes, int n_in,
                              void* d_out, int out_size)
{
    const float* x     = (const float*)d_in[0];
    const float* Wq    = (const float*)d_in[1];
    const float* Wk    = (const float*)d_in[2];
    const float* Wv    = (const float*)d_in[3];
    const float* Wo    = (const float*)d_in[4];
    const float* ln1_g = (const float*)d_in[5];
    const float* ln1_b = (const float*)d_in[6];
    const float* W1    = (const float*)d_in[7];
    const float* b1    = (const float*)d_in[8];
    const float* W2    = (const float*)d_in[9];
    const float* b2    = (const float*)d_in[10];
    const float* ln2_g = (const float*)d_in[11];
    const float* ln2_b = (const float*)d_in[12];
    float* out = (float*)d_out;

    cudaFuncSetAttribute(gemm_mma,   cudaFuncAttributeMaxDynamicSharedMemorySize, GEMM_SMEM);
    cudaFuncSetAttribute(flash_hmma, cudaFuncAttributeMaxDynamicSharedMemorySize, ATT_SMEM);

    float *t1, *x1, *t2;
    __half *wqkvh, *xh, *qkvh, *oh, *woh, *x1h, *w1h, *hh, *w2h;
    cudaGetSymbolAddress((void**)&t1,    g_t1);
    cudaGetSymbolAddress((void**)&x1,    g_x1);
    cudaGetSymbolAddress((void**)&t2,    g_t2);
    cudaGetSymbolAddress((void**)&wqkvh, g_wqkvh);
    cudaGetSymbolAddress((void**)&xh,    g_xh);
    cudaGetSymbolAddress((void**)&qkvh,  g_qkvh);
    cudaGetSymbolAddress((void**)&oh,    g_oh);
    cudaGetSymbolAddress((void**)&woh,   g_woh);
    cudaGetSymbolAddress((void**)&x1h,   g_x1h);
    cudaGetSymbolAddress((void**)&w1h,   g_w1h);
    cudaGetSymbolAddress((void**)&hh,    g_hh);
    cudaGetSymbolAddress((void**)&w2h,   g_w2h);

    // weight prep (fp16 hi only, direct transposes)
    wqkv_transpose<<<dim3(32, 96),  dim3(32, 8)>>>(Wq, Wk, Wv, wqkvh);
    transpose_h<<<dim3(32, 32),  dim3(32, 8)>>>(Wo, 1024, 1024, woh);
    transpose_h<<<dim3(128, 32), dim3(32, 8)>>>(W1, 1024, 4096, w1h);
    transpose_h<<<dim3(32, 128), dim3(32, 8)>>>(W2, 4096, 1024, w2h);
    split_plain<<<16384, 256>>>(x, xh);

    // 1. QKV projection -> qkv fp16
    gemm_mma<<<dim3(24, 32), 256, GEMM_SMEM>>>(xh, wqkvh, 4096, 3072, 1024,
                                               nullptr, nullptr, 0, nullptr, qkvh);
    // 2. flash attention -> o fp16
    flash_hmma<<<dim3(16, NH, BATCH), 256, ATT_SMEM>>>(qkvh, oh);
    // 3. output projection + residual x -> t1 fp32
    gemm_mma<<<dim3(8, 32), 256, GEMM_SMEM>>>(oh, woh, 4096, 1024, 1024,
                                              nullptr, x, 0, t1, nullptr);
    // 4. LN1 -> x1 fp32 + fp16
    ln_kernel<<<4096, 256>>>(t1, ln1_g, ln1_b, x1, x1h);
    // 5. FFN up + bias + relu -> h fp16
    gemm_mma<<<dim3(32, 32), 256, GEMM_SMEM>>>(x1h, w1h, 4096, 4096, 1024,
                                               b1, nullptr, 1, nullptr, hh);
    // 6. FFN down + bias + residual x1 -> t2 fp32
    gemm_mma<<<dim3(8, 32), 256, GEMM_SMEM>>>(hh, w2h, 4096, 1024, 4096,
                                              b2, x1, 0, t2, nullptr);
    // 7. LN2 -> out
    ln_kernel<<<4096, 256>>>(t2, ln2_g, ln2_b, out, nullptr);
}

// round 7
// speedup vs baseline: 6.3425x; 1.0484x over previous
#include <cuda_runtime.h>
#include <cuda_fp16.h>
#include <cstdint>

#define SEQ    2048
#define BATCH  2
#define NH     16
#define QKVLD  3072
#define STAGES 3
#define STAGE_BYTES 32768
#define GEMM_SMEM (STAGES * STAGE_BYTES + 1024)
#define NSTG   3
#define ATT_SMEM  (16384 + NSTG * 16384 + 1024)

// ---------------- scratch (static device globals; no allocation) -------------
__device__ __half  g_wqkvh[1024u * 3072u];   // [K=1024, N=3072] row-major
__device__ __half  g_xh   [4096u * 1024u];
__device__ __half  g_qkvh [4096u * 3072u];
__device__ __half  g_oh   [4096u * 1024u];
__device__ __half  g_woh  [1024u * 1024u];   // [K,N] native
__device__ float   g_t1   [4096u * 1024u];
__device__ float   g_x1   [4096u * 1024u];
__device__ __half  g_x1h  [4096u * 1024u];
__device__ __half  g_w1h  [1024u * 4096u];   // [K,N] native
__device__ __half  g_hh   [4096u * 4096u];
__device__ __half  g_w2h  [4096u * 1024u];   // [K,N] native
__device__ float   g_t2   [4096u * 1024u];

// ---------------- PTX helpers --------------------------------------------------
__device__ __forceinline__ uint32_t smem_u32(const void* p) {
    uint32_t a;
    asm("{ .reg .u64 t; cvta.to.shared.u64 t, %1; cvt.u32.u64 %0, t; }" : "=r"(a) : "l"(p));
    return a;
}
__device__ __forceinline__ void cp16(uint32_t s, const void* g) {
    asm volatile("cp.async.cg.shared.global [%0], [%1], 16;" :: "r"(s), "l"(g));
}
#define CP_COMMIT()  asm volatile("cp.async.commit_group;" ::: "memory")
#define CP_WAIT(n)   asm volatile("cp.async.wait_group %0;" :: "n"(n) : "memory")

__device__ __forceinline__ void ldsm4(uint32_t& r0, uint32_t& r1, uint32_t& r2, uint32_t& r3,
                                      uint32_t addr) {
    asm volatile("ldmatrix.sync.aligned.m8n8.x4.shared.b16 {%0,%1,%2,%3}, [%4];"
                 : "=r"(r0), "=r"(r1), "=r"(r2), "=r"(r3) : "r"(addr));
}
__device__ __forceinline__ void ldsm4t(uint32_t& r0, uint32_t& r1, uint32_t& r2, uint32_t& r3,
                                       uint32_t addr) {
    asm volatile("ldmatrix.sync.aligned.m8n8.x4.trans.shared.b16 {%0,%1,%2,%3}, [%4];"
                 : "=r"(r0), "=r"(r1), "=r"(r2), "=r"(r3) : "r"(addr));
}
__device__ __forceinline__ void mma16816(float* d, const uint32_t* a, const uint32_t* b) {
    asm volatile(
        "mma.sync.aligned.m16n8k16.row.col.f32.f16.f16.f32 "
        "{%0,%1,%2,%3}, {%4,%5,%6,%7}, {%8,%9}, {%0,%1,%2,%3};"
        : "+f"(d[0]), "+f"(d[1]), "+f"(d[2]), "+f"(d[3])
        : "r"(a[0]), "r"(a[1]), "r"(a[2]), "r"(a[3]), "r"(b[0]), "r"(b[1]));
}
__device__ __forceinline__ uint32_t pack2h(float a, float b) {
    __half2 p = __floats2half2_rn(a, b);
    return *reinterpret_cast<uint32_t*>(&p);
}

// ---------------- prep kernels -----------------------------------------------
// pack Wq/Wk/Wv (H=16, D=1024, 64) f32 -> Wqkv [1024 d][3072 n] fp16 row-major
// n = w*1024 + h*64 + k
__global__ void wqkv_pack(const float* __restrict__ Wq, const float* __restrict__ Wk,
                          const float* __restrict__ Wv, __half* __restrict__ out)
{
    int n = blockIdx.x * 256 + threadIdx.x;   // 0..3071
    int d = blockIdx.y;                       // 0..1023
    int w = n >> 10;
    int h = (n >> 6) & 15;
    int k = n & 63;
    const float* src = (w == 0) ? Wq : (w == 1) ? Wk : Wv;
    out[(size_t)d * QKVLD + n] = __float2half_rn(src[h * 65536 + d * 64 + k]);
}

__global__ void cvt_h(const float* __restrict__ in, __half* __restrict__ oh)
{
    int idx = blockIdx.x * blockDim.x + threadIdx.x;
    oh[idx] = __float2half_rn(in[idx]);
}

// ---------------- mma.sync fp16 GEMM: C = A B ---------------------------------
// A [M,K] fp16 row-major, B [K,N] fp16 row-major (native weight layout).
// Tile 128x128x64. Stage: A[0,16K); B[16K,32K) as two 64-col subtiles of 8KB.
__device__ __forceinline__ void g_load_stage(uint32_t sb,
    const __half* A, const __half* B, int K, int N, int m0, int n0, int k0, int tid)
{
#pragma unroll
    for (int it = 0; it < 4; it++) {         // A: 128 rows x 8 chunks
        int idx = it * 256 + tid;
        int r = idx >> 3, c = idx & 7;
        uint32_t soff = (uint32_t)(r * 128 + ((c ^ (r & 7)) << 4));
        cp16(sb + soff, A + (size_t)(m0 + r) * K + k0 + c * 8);
    }
#pragma unroll
    for (int it = 0; it < 4; it++) {         // B: 64 k-rows x 16 chunks
        int idx = it * 256 + tid;
        int r = idx >> 4, c = idx & 15;
        uint32_t soff = (uint32_t)((c >> 3) * 8192 + r * 128 + (((c & 7) ^ (r & 7)) << 4));
        cp16(sb + 16384 + soff, B + (size_t)(k0 + r) * N + n0 + c * 8);
    }
}

__global__ __launch_bounds__(256, 2) void gemm_mma(
    const __half* __restrict__ A, const __half* __restrict__ B,
    int M, int N, int K,
    const float* __restrict__ bias, const float* __restrict__ res, int relu,
    float* __restrict__ outF, __half* __restrict__ outH)
{
    extern __shared__ char dsm_raw[];
    uint32_t base = (smem_u32(dsm_raw) + 1023) & ~1023u;

    const int tid  = threadIdx.x;
    const int wid  = tid >> 5;
    const int lane = tid & 31;
    const int wm   = wid >> 2;
    const int wn   = wid & 3;
    const int m0   = blockIdx.y * 128;
    const int n0   = blockIdx.x * 128;
    const int wr   = wm * 64;
    const int wc   = wn * 32;
    const int l15  = lane & 15;
    const int hi16 = lane >> 4;

    uint32_t a_row[4], a_sw[4];
#pragma unroll
    for (int mt = 0; mt < 4; mt++) {
        int r = wr + mt * 16 + l15;
        a_row[mt] = (uint32_t)(r * 128);
        a_sw[mt]  = (uint32_t)(r & 7);
    }
    const uint32_t bsub_off = 16384u + (uint32_t)((wc >> 6) * 8192);
    const int base_c8 = (wc & 63) >> 3;           // 0 or 4
    const int b3      = (lane >> 3) & 1;
    const int rsel    = ((lane >> 4) << 3) + (lane & 7);   // 0..15 row within k-chunk

    float acc[4][4][4];
#pragma unroll
    for (int i = 0; i < 4; i++)
#pragma unroll
        for (int j = 0; j < 4; j++)
#pragma unroll
            for (int q = 0; q < 4; q++) acc[i][j][q] = 0.f;

    const int nK = K >> 6;

#pragma unroll
    for (int s = 0; s < STAGES - 1; s++) {
        g_load_stage(base + s * STAGE_BYTES, A, B, K, N, m0, n0, s * 64, tid);
        CP_COMMIT();
    }

    for (int kt = 0; kt < nK; kt++) {
        CP_WAIT(STAGES - 2);
        __syncthreads();

        int ls = kt + STAGES - 1;
        if (ls < nK)
            g_load_stage(base + (ls % STAGES) * STAGE_BYTES, A, B, K, N, m0, n0, ls * 64, tid);
        CP_COMMIT();

        uint32_t sb = base + (kt % STAGES) * STAGE_BYTES;
#pragma unroll
        for (int kh = 0; kh < 4; kh++) {
            uint32_t ah[4][4], bh[4][2];
#pragma unroll
            for (int mt = 0; mt < 4; mt++) {
                uint32_t co = (uint32_t)(((2 * kh + hi16) ^ a_sw[mt]) << 4);
                ldsm4(ah[mt][0], ah[mt][1], ah[mt][2], ah[mt][3], sb + a_row[mt] + co);
            }
            int rowt = kh * 16 + rsel;
#pragma unroll
            for (int jt = 0; jt < 2; jt++) {
                int c8 = base_c8 + jt * 2 + b3;
                uint32_t ad = sb + bsub_off + rowt * 128 + (uint32_t)((c8 ^ (rowt & 7)) << 4);
                uint32_t t0, t1, t2, t3;
                ldsm4t(t0, t1, t2, t3, ad);
                bh[2 * jt][0] = t0; bh[2 * jt][1] = t2;
                bh[2 * jt + 1][0] = t1; bh[2 * jt + 1][1] = t3;
            }
#pragma unroll
            for (int mt = 0; mt < 4; mt++)
#pragma unroll
                for (int j = 0; j < 4; j++)
                    mma16816(acc[mt][j], ah[mt], bh[j]);
        }
        __syncthreads();
    }

    const int rq = lane >> 2;
    const int cq = (lane & 3) * 2;
#pragma unroll
    for (int mt = 0; mt < 4; mt++)
#pragma unroll
        for (int half = 0; half < 2; half++) {
            int row = m0 + wr + mt * 16 + rq + half * 8;
            size_t rb = (size_t)row * N;
#pragma unroll
            for (int j = 0; j < 4; j++) {
                int col = n0 + wc + j * 8 + cq;
                float v0 = acc[mt][j][half * 2 + 0];
                float v1 = acc[mt][j][half * 2 + 1];
                if (bias) { v0 += bias[col]; v1 += bias[col + 1]; }
                if (relu) { v0 = fmaxf(v0, 0.f); v1 = fmaxf(v1, 0.f); }
                if (res)  {
                    float2 rr = *(const float2*)&res[rb + col];
                    v0 += rr.x; v1 += rr.y;
                }
                if (outF) *(float2*)&outF[rb + col] = make_float2(v0, v1);
                if (outH) *reinterpret_cast<uint32_t*>(outH + rb + col) = pack2h(v0, v1);
            }
        }
}

// ---------------- HMMA flash attention (fp16 single-pass) ----------------------
// Q tile 128x64 at base; KV stage s at base+16K+s*16K: K[0,8K) V[8K,16K).
__device__ __forceinline__ void att_load_kv(uint32_t sb,
    const __half* qkv, size_t tokbase, int h, int kt, int tid)
{
#pragma unroll
    for (int it = 0; it < 2; it++) {
        int idx = it * 256 + tid;
        int r = idx >> 3, c = idx & 7;
        uint32_t sw = (uint32_t)(r * 128 + ((c ^ (r & 7)) << 4));
        size_t gk = (tokbase + kt * 64 + r) * QKVLD + 1024 + h * 64 + c * 8;
        cp16(sb        + sw, qkv + gk);
        cp16(sb + 8192 + sw, qkv + gk + 1024);
    }
}

__global__ __launch_bounds__(256, 2) void flash_hmma(
    const __half* __restrict__ qkv, __half* __restrict__ oh)
{
    extern __shared__ char smem_raw[];
    uint32_t base = (smem_u32(smem_raw) + 1023) & ~1023u;
    const uint32_t QH = base;

    const int tid  = threadIdx.x;
    const int wq   = tid >> 5;
    const int lane = tid & 31;
    const int l15  = lane & 15;
    const int hi16 = lane >> 4;
    const int q0   = blockIdx.x * 128;
    const int h    = blockIdx.y;
    const int b    = blockIdx.z;
    const size_t tokbase = (size_t)b * SEQ;

    // Q tile + KV stage 0 in group 0
#pragma unroll
    for (int it = 0; it < 4; it++) {
        int idx = it * 256 + tid;
        int r = idx >> 3, c = idx & 7;
        uint32_t sw = (uint32_t)(r * 128 + ((c ^ (r & 7)) << 4));
        cp16(QH + sw, qkv + (tokbase + q0 + r) * QKVLD + h * 64 + c * 8);
    }
    att_load_kv(base + 16384, qkv, tokbase, h, 0, tid);
    CP_COMMIT();
#pragma unroll
    for (int s = 1; s < NSTG - 1; s++) {
        att_load_kv(base + 16384 + s * 16384, qkv, tokbase, h, s, tid);
        CP_COMMIT();
    }

    float m2[2] = {-1e30f, -1e30f};
    float l2[2] = {0.f, 0.f};
    float oa[8][4];
#pragma unroll
    for (int j = 0; j < 8; j++)
#pragma unroll
        for (int q = 0; q < 4; q++) oa[j][q] = 0.f;

    const uint32_t qrow = (uint32_t)((wq * 16 + l15) * 128);
    const uint32_t qsw  = (uint32_t)((wq * 16 + l15) & 7);

    for (int kt = 0; kt < SEQ / 64; kt++) {
        CP_WAIT(NSTG - 2);
        __syncthreads();
        int ls = kt + NSTG - 1;
        if (ls < SEQ / 64)
            att_load_kv(base + 16384 + (ls % NSTG) * 16384, qkv, tokbase, h, ls, tid);
        CP_COMMIT();

        uint32_t sb = base + 16384 + (kt % NSTG) * 16384;

        // ---- S = Q K^T -------------------------------------------------------
        float sa[8][4];
#pragma unroll
        for (int j = 0; j < 8; j++)
#pragma unroll
            for (int q = 0; q < 4; q++) sa[j][q] = 0.f;

#pragma unroll
        for (int kc = 0; kc < 4; kc++) {
            uint32_t co_a = (uint32_t)(((2 * kc + hi16) ^ qsw) << 4);
            uint32_t ah[4];
            ldsm4(ah[0], ah[1], ah[2], ah[3], QH + qrow + co_a);

            uint32_t kbh[8][2];
#pragma unroll
            for (int nt = 0; nt < 4; nt++) {
                int r = nt * 16 + l15;
                uint32_t co = (uint32_t)(((2 * kc + hi16) ^ (r & 7)) << 4);
                uint32_t t0, t1, t2, t3;
                ldsm4(t0, t1, t2, t3, sb + r * 128 + co);
                kbh[2 * nt][0] = t0; kbh[2 * nt][1] = t2;
                kbh[2 * nt + 1][0] = t1; kbh[2 * nt + 1][1] = t3;
            }
#pragma unroll
            for (int j = 0; j < 8; j++)
                mma16816(sa[j], ah, kbh[j]);
        }

        // ---- online softmax ---------------------------------------------------
#pragma unroll
        for (int half = 0; half < 2; half++) {
            float mx = -1e30f;
#pragma unroll
            for (int j = 0; j < 8; j++) {
                sa[j][2 * half]     *= 0.125f;
                sa[j][2 * half + 1] *= 0.125f;
                mx = fmaxf(mx, fmaxf(sa[j][2 * half], sa[j][2 * half + 1]));
            }
            mx = fmaxf(mx, __shfl_xor_sync(0xffffffffu, mx, 1));
            mx = fmaxf(mx, __shfl_xor_sync(0xffffffffu, mx, 2));
            float nm    = fmaxf(m2[half], mx);
            float alpha = __expf(m2[half] - nm);
            float rs = 0.f;
#pragma unroll
            for (int j = 0; j < 8; j++) {
                sa[j][2 * half]     = __expf(sa[j][2 * half]     - nm);
                sa[j][2 * half + 1] = __expf(sa[j][2 * half + 1] - nm);
                rs += sa[j][2 * half] + sa[j][2 * half + 1];
            }
            rs += __shfl_xor_sync(0xffffffffu, rs, 1);
            rs += __shfl_xor_sync(0xffffffffu, rs, 2);
            l2[half] = l2[half] * alpha + rs;
            m2[half] = nm;
#pragma unroll
            for (int j = 0; j < 8; j++) {
                oa[j][2 * half]     *= alpha;
                oa[j][2 * half + 1] *= alpha;
            }
        }

        // ---- P -> fp16 a-frags --------------------------------------------------
        uint32_t ph[4][4];
#pragma unroll
        for (int kc = 0; kc < 4; kc++) {
            int j0 = 2 * kc, j1 = 2 * kc + 1;
            ph[kc][0] = pack2h(sa[j0][0], sa[j0][1]);
            ph[kc][1] = pack2h(sa[j0][2], sa[j0][3]);
            ph[kc][2] = pack2h(sa[j1][0], sa[j1][1]);
            ph[kc][3] = pack2h(sa[j1][2], sa[j1][3]);
        }

        // ---- O += P V, V via ldmatrix.trans --------------------------------------
#pragma unroll
        for (int kc = 0; kc < 4; kc++) {
            int rowt = kc * 16 + ((lane >> 4) << 3) + (lane & 7);
            uint32_t vbh[8][2];
#pragma unroll
            for (int jt = 0; jt < 4; jt++) {
                int c8 = jt * 2 + ((lane >> 3) & 1);
                uint32_t ad = sb + 8192 + rowt * 128 + (uint32_t)(((c8 ^ (rowt & 7))) << 4);
                uint32_t t0, t1, t2, t3;
                ldsm4t(t0, t1, t2, t3, ad);
                vbh[2 * jt][0] = t0; vbh[2 * jt][1] = t2;
                vbh[2 * jt + 1][0] = t1; vbh[2 * jt + 1][1] = t3;
            }
#pragma unroll
            for (int j = 0; j < 8; j++)
                mma16816(oa[j], ph[kc], vbh[j]);
        }
    }

    // ---- epilogue ---------------------------------------------------------------
    float inv0 = 1.f / l2[0];
    float inv1 = 1.f / l2[1];
    int r0 = q0 + wq * 16 + (lane >> 2);
#pragma unroll
    for (int j = 0; j < 8; j++) {
        int col = h * 64 + j * 8 + (lane & 3) * 2;
        size_t g0 = (tokbase + r0) * 1024 + col;
        size_t g1 = (tokbase + r0 + 8) * 1024 + col;
        *reinterpret_cast<uint32_t*>(oh + g0) = pack2h(oa[j][0] * inv0, oa[j][1] * inv0);
        *reinterpret_cast<uint32_t*>(oh + g1) = pack2h(oa[j][2] * inv1, oa[j][3] * inv1);
    }
}

// ---------------- layernorm -----------------------------------------------------
__global__ __launch_bounds__(256) void ln_kernel(const float* __restrict__ in,
                                                 const float* __restrict__ gamma,
                                                 const float* __restrict__ beta,
                                                 float* __restrict__ outF,
                                                 __half* __restrict__ outH)
{
    const int row = blockIdx.x, tid = threadIdx.x;
    const float* p = in + (size_t)row * 1024;
    float4 v = *(const float4*)(p + tid * 4);
    float s  = v.x + v.y + v.z + v.w;
    float ss = v.x * v.x + v.y * v.y + v.z * v.z + v.w * v.w;
#pragma unroll
    for (int off = 16; off > 0; off >>= 1) {
        s  += __shfl_xor_sync(0xffffffffu, s,  off);
        ss += __shfl_xor_sync(0xffffffffu, ss, off);
    }
    __shared__ float sb[8], ssb[8];
    __shared__ float smu, sinv;
    if ((tid & 31) == 0) { sb[tid >> 5] = s; ssb[tid >> 5] = ss; }
    __syncthreads();
    if (tid == 0) {
        float S = 0.f, SS = 0.f;
#pragma unroll
        for (int i = 0; i < 8; i++) { S += sb[i]; SS += ssb[i]; }
        float mu  = S * (1.f / 1024.f);
        float var = SS * (1.f / 1024.f) - mu * mu;
        smu = mu; sinv = rsqrtf(var + 1e-5f);
    }
    __syncthreads();
    float mu = smu, inv = sinv;
    float4 g = *(const float4*)(gamma + tid * 4);
    float4 b = *(const float4*)(beta  + tid * 4);
    float4 o;
    o.x = (v.x - mu) * inv * g.x + b.x;
    o.y = (v.y - mu) * inv * g.y + b.y;
    o.z = (v.z - mu) * inv * g.z + b.z;
    o.w = (v.w - mu) * inv * g.w + b.w;
    size_t idx = (size_t)row * 1024 + tid * 4;
    *(float4*)&outF[idx] = o;
    if (outH) {
        *reinterpret_cast<uint32_t*>(outH + idx)     = pack2h(o.x, o.y);
        *reinterpret_cast<uint32_t*>(outH + idx + 2) = pack2h(o.z, o.w);
    }
}

// ---------------- launch ----------------------------------------------------------
extern "C" void kernel_launch(void* const* d_in, const int* in_sizes, int n_in,
                              void* d_out, int out_size)
{
    const float* x     = (const float*)d_in[0];
    const float* Wq    = (const float*)d_in[1];
    const float* Wk    = (const float*)d_in[2];
    const float* Wv    = (const float*)d_in[3];
    const float* Wo    = (const float*)d_in[4];
    const float* ln1_g = (const float*)d_in[5];
    const float* ln1_b = (const float*)d_in[6];
    const float* W1    = (const float*)d_in[7];
    const float* b1    = (const float*)d_in[8];
    const float* W2    = (const float*)d_in[9];
    const float* b2    = (const float*)d_in[10];
    const float* ln2_g = (const float*)d_in[11];
    const float* ln2_b = (const float*)d_in[12];
    float* out = (float*)d_out;

    cudaFuncSetAttribute(gemm_mma,   cudaFuncAttributeMaxDynamicSharedMemorySize, GEMM_SMEM);
    cudaFuncSetAttribute(flash_hmma, cudaFuncAttributeMaxDynamicSharedMemorySize, ATT_SMEM);

    float *t1, *x1, *t2;
    __half *wqkvh, *xh, *qkvh, *oh, *woh, *x1h, *w1h, *hh, *w2h;
    cudaGetSymbolAddress((void**)&t1,    g_t1);
    cudaGetSymbolAddress((void**)&x1,    g_x1);
    cudaGetSymbolAddress((void**)&t2,    g_t2);
    cudaGetSymbolAddress((void**)&wqkvh, g_wqkvh);
    cudaGetSymbolAddress((void**)&xh,    g_xh);
    cudaGetSymbolAddress((void**)&qkvh,  g_qkvh);
    cudaGetSymbolAddress((void**)&oh,    g_oh);
    cudaGetSymbolAddress((void**)&woh,   g_woh);
    cudaGetSymbolAddress((void**)&x1h,   g_x1h);
    cudaGetSymbolAddress((void**)&w1h,   g_w1h);
    cudaGetSymbolAddress((void**)&hh,    g_hh);
    cudaGetSymbolAddress((void**)&w2h,   g_w2h);

    // weight prep: native-layout fp16 converts only (no transposes)
    wqkv_pack<<<dim3(12, 1024), 256>>>(Wq, Wk, Wv, wqkvh);
    cvt_h<<<4096,  256>>>(Wo, woh);
    cvt_h<<<16384, 256>>>(W1, w1h);
    cvt_h<<<16384, 256>>>(W2, w2h);
    cvt_h<<<16384, 256>>>(x,  xh);

    // 1. QKV projection -> qkv fp16
    gemm_mma<<<dim3(24, 32), 256, GEMM_SMEM>>>(xh, wqkvh, 4096, 3072, 1024,
                                               nullptr, nullptr, 0, nullptr, qkvh);
    // 2. flash attention -> o fp16
    flash_hmma<<<dim3(16, NH, BATCH), 256, ATT_SMEM>>>(qkvh, oh);
    // 3. output projection + residual x -> t1 fp32
    gemm_mma<<<dim3(8, 32), 256, GEMM_SMEM>>>(oh, woh, 4096, 1024, 1024,
                                              nullptr, x, 0, t1, nullptr);
    // 4. LN1 -> x1 fp32 + fp16
    ln_kernel<<<4096, 256>>>(t1, ln1_g, ln1_b, x1, x1h);
    // 5. FFN up + bias + relu -> h fp16
    gemm_mma<<<dim3(32, 32), 256, GEMM_SMEM>>>(x1h, w1h, 4096, 4096, 1024,
                                               b1, nullptr, 1, nullptr, hh);
    // 6. FFN down + bias + residual x1 -> t2 fp32
    gemm_mma<<<dim3(8, 32), 256, GEMM_SMEM>>>(hh, w2h, 4096, 1024, 4096,
                                              b2, x1, 0, t2, nullptr);
    // 7. LN2 -> out
    ln_kernel<<<4096, 256>>>(t2, ln2_g, ln2_b, out, nullptr);
}

// round 9
// speedup vs baseline: 6.7842x; 1.0696x over previous
#include <cuda_runtime.h>
#include <cuda_fp16.h>
#include <cstdint>

#define SEQ    2048
#define BATCH  2
#define NH     16
#define QKVLD  3072
#define STAGES 3
#define STAGE_BYTES 32768
#define GEMM_SMEM (STAGES * STAGE_BYTES + 1024)
#define NSTG   3
#define ATT_SMEM  (16384 + NSTG * 16384 + 1024)

// ---------------- scratch (static device globals; no allocation) -------------
__device__ __half  g_wqkvh[1024u * 3072u];   // [K=1024, N=3072] row-major
__device__ __half  g_xh   [4096u * 1024u];
__device__ __half  g_qkvh [4096u * 3072u];
__device__ __half  g_oh   [4096u * 1024u];
__device__ __half  g_woh  [1024u * 1024u];   // [K,N] native
__device__ float   g_t1   [4096u * 1024u];
__device__ float   g_x1   [4096u * 1024u];
__device__ __half  g_x1h  [4096u * 1024u];
__device__ __half  g_w1h  [1024u * 4096u];   // [K,N] native
__device__ __half  g_hh   [4096u * 4096u];
__device__ __half  g_w2h  [4096u * 1024u];   // [K,N] native
__device__ float   g_t2   [4096u * 1024u];

// ---------------- PTX helpers --------------------------------------------------
__device__ __forceinline__ uint32_t smem_u32(const void* p) {
    uint32_t a;
    asm("{ .reg .u64 t; cvta.to.shared.u64 t, %1; cvt.u32.u64 %0, t; }" : "=r"(a) : "l"(p));
    return a;
}
__device__ __forceinline__ void cp16(uint32_t s, const void* g) {
    asm volatile("cp.async.cg.shared.global [%0], [%1], 16;" :: "r"(s), "l"(g));
}
#define CP_COMMIT()  asm volatile("cp.async.commit_group;" ::: "memory")
#define CP_WAIT(n)   asm volatile("cp.async.wait_group %0;" :: "n"(n) : "memory")

__device__ __forceinline__ void ldsm4(uint32_t& r0, uint32_t& r1, uint32_t& r2, uint32_t& r3,
                                      uint32_t addr) {
    asm volatile("ldmatrix.sync.aligned.m8n8.x4.shared.b16 {%0,%1,%2,%3}, [%4];"
                 : "=r"(r0), "=r"(r1), "=r"(r2), "=r"(r3) : "r"(addr));
}
__device__ __forceinline__ void ldsm4t(uint32_t& r0, uint32_t& r1, uint32_t& r2, uint32_t& r3,
                                       uint32_t addr) {
    asm volatile("ldmatrix.sync.aligned.m8n8.x4.trans.shared.b16 {%0,%1,%2,%3}, [%4];"
                 : "=r"(r0), "=r"(r1), "=r"(r2), "=r"(r3) : "r"(addr));
}
__device__ __forceinline__ void mma16816(float* d, const uint32_t* a, uint32_t b0, uint32_t b1) {
    asm volatile(
        "mma.sync.aligned.m16n8k16.row.col.f32.f16.f16.f32 "
        "{%0,%1,%2,%3}, {%4,%5,%6,%7}, {%8,%9}, {%0,%1,%2,%3};"
        : "+f"(d[0]), "+f"(d[1]), "+f"(d[2]), "+f"(d[3])
        : "r"(a[0]), "r"(a[1]), "r"(a[2]), "r"(a[3]), "r"(b0), "r"(b1));
}
__device__ __forceinline__ uint32_t pack2h(float a, float b) {
    __half2 p = __floats2half2_rn(a, b);
    return *reinterpret_cast<uint32_t*>(&p);
}

// ---------------- prep kernels -----------------------------------------------
// pack Wq/Wk/Wv (H=16, D=1024, 64) f32 -> Wqkv [1024 d][3072 n] fp16 row-major
// n = w*1024 + h*64 + k; 2 elems/thread. NOTE: 3072 is NOT a power of two —
// use exact div/mod decomposition (round-8 bug was a &(3071) mask here).
__global__ void wqkv_pack(const float* __restrict__ Wq, const float* __restrict__ Wk,
                          const float* __restrict__ Wv, __half* __restrict__ out)
{
    int t  = blockIdx.x * 256 + threadIdx.x;   // 0 .. 1572863
    int d  = t / (QKVLD / 2);                  // 0..1023
    int n  = (t - d * (QKVLD / 2)) * 2;        // even n within row, 0..3070
    int w  = n >> 10;
    int h  = (n >> 6) & 15;
    int k  = n & 63;
    const float* src = (w == 0) ? Wq : (w == 1) ? Wk : Wv;
    float2 v = *(const float2*)&src[h * 65536 + d * 64 + k];
    *reinterpret_cast<uint32_t*>(&out[(size_t)d * QKVLD + n]) = pack2h(v.x, v.y);
}

// fp32 -> fp16, 8 elements per thread
__global__ void cvt_h(const float* __restrict__ in, __half* __restrict__ oh)
{
    size_t idx = ((size_t)blockIdx.x * 256 + threadIdx.x) * 8;
    float4 a = *(const float4*)&in[idx];
    float4 b = *(const float4*)&in[idx + 4];
    uint4 o;
    o.x = pack2h(a.x, a.y); o.y = pack2h(a.z, a.w);
    o.z = pack2h(b.x, b.y); o.w = pack2h(b.z, b.w);
    *(uint4*)&oh[idx] = o;
}

// ---------------- mma.sync fp16 GEMM: C = A B ---------------------------------
// A [M,K] fp16 row-major, B [K,N] fp16 row-major (native weight layout).
// Tile 128x128x64. Stage: A[0,16K); B[16K,32K) as two 64-col subtiles of 8KB.
__device__ __forceinline__ void g_load_stage(uint32_t sb,
    const __half* A, const __half* B, int K, int N, int m0, int n0, int k0, int tid)
{
#pragma unroll
    for (int it = 0; it < 4; it++) {         // A: 128 rows x 8 chunks
        int idx = it * 256 + tid;
        int r = idx >> 3, c = idx & 7;
        uint32_t soff = (uint32_t)(r * 128 + ((c ^ (r & 7)) << 4));
        cp16(sb + soff, A + (size_t)(m0 + r) * K + k0 + c * 8);
    }
#pragma unroll
    for (int it = 0; it < 4; it++) {         // B: 64 k-rows x 16 chunks
        int idx = it * 256 + tid;
        int r = idx >> 4, c = idx & 15;
        uint32_t soff = (uint32_t)((c >> 3) * 8192 + r * 128 + (((c & 7) ^ (r & 7)) << 4));
        cp16(sb + 16384 + soff, B + (size_t)(k0 + r) * N + n0 + c * 8);
    }
}

__global__ __launch_bounds__(256, 2) void gemm_mma(
    const __half* __restrict__ A, const __half* __restrict__ B,
    int M, int N, int K,
    const float* __restrict__ bias, const float* __restrict__ res, int relu,
    float* __restrict__ outF, __half* __restrict__ outH)
{
    extern __shared__ char dsm_raw[];
    uint32_t base = (smem_u32(dsm_raw) + 1023) & ~1023u;

    const int tid  = threadIdx.x;
    const int wid  = tid >> 5;
    const int lane = tid & 31;
    const int wm   = wid >> 2;
    const int wn   = wid & 3;
    const int m0   = blockIdx.y * 128;
    const int n0   = blockIdx.x * 128;
    const int wr   = wm * 64;
    const int wc   = wn * 32;
    const int l15  = lane & 15;
    const int hi16 = lane >> 4;

    uint32_t a_row[4], a_sw[4];
#pragma unroll
    for (int mt = 0; mt < 4; mt++) {
        int r = wr + mt * 16 + l15;
        a_row[mt] = (uint32_t)(r * 128);
        a_sw[mt]  = (uint32_t)(r & 7);
    }
    const uint32_t bsub_off = 16384u + (uint32_t)((wc >> 6) * 8192);
    const int base_c8 = (wc & 63) >> 3;           // 0 or 4
    const int b3      = (lane >> 3) & 1;
    const int rsel    = ((lane >> 4) << 3) + (lane & 7);   // 0..15 row in k-chunk

    float acc[4][4][4];
#pragma unroll
    for (int i = 0; i < 4; i++)
#pragma unroll
        for (int j = 0; j < 4; j++)
#pragma unroll
            for (int q = 0; q < 4; q++) acc[i][j][q] = 0.f;

    const int nK = K >> 6;

#pragma unroll
    for (int s = 0; s < STAGES - 1; s++) {
        g_load_stage(base + s * STAGE_BYTES, A, B, K, N, m0, n0, s * 64, tid);
        CP_COMMIT();
    }

    for (int kt = 0; kt < nK; kt++) {
        CP_WAIT(STAGES - 2);
        __syncthreads();    // also orders reuse of stage (kt+2)%3 == (kt-1)%3

        int ls = kt + STAGES - 1;
        if (ls < nK)
            g_load_stage(base + (ls % STAGES) * STAGE_BYTES, A, B, K, N, m0, n0, ls * 64, tid);
        CP_COMMIT();

        uint32_t sb = base + (kt % STAGES) * STAGE_BYTES;
#pragma unroll
        for (int kh = 0; kh < 4; kh++) {
            uint32_t ah[4][4];
#pragma unroll
            for (int mt = 0; mt < 4; mt++) {
                uint32_t co = (uint32_t)(((2 * kh + hi16) ^ a_sw[mt]) << 4);
                ldsm4(ah[mt][0], ah[mt][1], ah[mt][2], ah[mt][3], sb + a_row[mt] + co);
            }
            int rowt = kh * 16 + rsel;
#pragma unroll
            for (int jt = 0; jt < 2; jt++) {   // consume B frags immediately
                int c8 = base_c8 + jt * 2 + b3;
                uint32_t ad = sb + bsub_off + rowt * 128 + (uint32_t)((c8 ^ (rowt & 7)) << 4);
                uint32_t t0, t1, t2, t3;
                ldsm4t(t0, t1, t2, t3, ad);
#pragma unroll
                for (int mt = 0; mt < 4; mt++) {
                    mma16816(acc[mt][2 * jt],     ah[mt], t0, t2);
                    mma16816(acc[mt][2 * jt + 1], ah[mt], t1, t3);
                }
            }
        }
    }
    __syncthreads();

    const int rq = lane >> 2;
    const int cq = (lane & 3) * 2;
#pragma unroll
    for (int mt = 0; mt < 4; mt++)
#pragma unroll
        for (int half = 0; half < 2; half++) {
            int row = m0 + wr + mt * 16 + rq + half * 8;
            size_t rb = (size_t)row * N;
#pragma unroll
            for (int j = 0; j < 4; j++) {
                int col = n0 + wc + j * 8 + cq;
                float v0 = acc[mt][j][half * 2 + 0];
                float v1 = acc[mt][j][half * 2 + 1];
                if (bias) { v0 += bias[col]; v1 += bias[col + 1]; }
                if (relu) { v0 = fmaxf(v0, 0.f); v1 = fmaxf(v1, 0.f); }
                if (res)  {
                    float2 rr = *(const float2*)&res[rb + col];
                    v0 += rr.x; v1 += rr.y;
                }
                if (outF) *(float2*)&outF[rb + col] = make_float2(v0, v1);
                if (outH) *reinterpret_cast<uint32_t*>(outH + rb + col) = pack2h(v0, v1);
            }
        }
}

// ---------------- HMMA flash attention (fp16 single-pass) ----------------------
// Q tile 128x64 at base; KV stage s at base+16K+s*16K: K[0,8K) V[8K,16K).
__device__ __forceinline__ void att_load_kv(uint32_t sb,
    const __half* qkv, size_t tokbase, int h, int kt, int tid)
{
#pragma unroll
    for (int it = 0; it < 2; it++) {
        int idx = it * 256 + tid;
        int r = idx >> 3, c = idx & 7;
        uint32_t sw = (uint32_t)(r * 128 + ((c ^ (r & 7)) << 4));
        size_t gk = (tokbase + kt * 64 + r) * QKVLD + 1024 + h * 64 + c * 8;
        cp16(sb        + sw, qkv + gk);
        cp16(sb + 8192 + sw, qkv + gk + 1024);
    }
}

__global__ __launch_bounds__(256, 2) void flash_hmma(
    const __half* __restrict__ qkv, __half* __restrict__ oh)
{
    extern __shared__ char smem_raw[];
    uint32_t base = (smem_u32(smem_raw) + 1023) & ~1023u;
    const uint32_t QH = base;

    const int tid  = threadIdx.x;
    const int wq   = tid >> 5;
    const int lane = tid & 31;
    const int l15  = lane & 15;
    const int hi16 = lane >> 4;
    const int q0   = blockIdx.x * 128;
    const int h    = blockIdx.y;
    const int b    = blockIdx.z;
    const size_t tokbase = (size_t)b * SEQ;

    // Q tile + KV stage 0 in group 0
#pragma unroll
    for (int it = 0; it < 4; it++) {
        int idx = it * 256 + tid;
        int r = idx >> 3, c = idx & 7;
        uint32_t sw = (uint32_t)(r * 128 + ((c ^ (r & 7)) << 4));
        cp16(QH + sw, qkv + (tokbase + q0 + r) * QKVLD + h * 64 + c * 8);
    }
    att_load_kv(base + 16384, qkv, tokbase, h, 0, tid);
    CP_COMMIT();
#pragma unroll
    for (int s = 1; s < NSTG - 1; s++) {
        att_load_kv(base + 16384 + s * 16384, qkv, tokbase, h, s, tid);
        CP_COMMIT();
    }

    float m2[2] = {-1e30f, -1e30f};
    float l2[2] = {0.f, 0.f};
    float oa[8][4];
#pragma unroll
    for (int j = 0; j < 8; j++)
#pragma unroll
        for (int q = 0; q < 4; q++) oa[j][q] = 0.f;

    const uint32_t qrow = (uint32_t)((wq * 16 + l15) * 128);
    const uint32_t qsw  = (uint32_t)((wq * 16 + l15) & 7);
    const int rsel = ((lane >> 4) << 3) + (lane & 7);
    const int b3   = (lane >> 3) & 1;

    for (int kt = 0; kt < SEQ / 64; kt++) {
        CP_WAIT(NSTG - 2);
        __syncthreads();
        int ls = kt + NSTG - 1;
        if (ls < SEQ / 64)
            att_load_kv(base + 16384 + (ls % NSTG) * 16384, qkv, tokbase, h, ls, tid);
        CP_COMMIT();

        uint32_t sb = base + 16384 + (kt % NSTG) * 16384;

        // ---- S = Q K^T -------------------------------------------------------
        float sa[8][4];
#pragma unroll
        for (int j = 0; j < 8; j++)
#pragma unroll
            for (int q = 0; q < 4; q++) sa[j][q] = 0.f;

#pragma unroll
        for (int kc = 0; kc < 4; kc++) {
            uint32_t co_a = (uint32_t)(((2 * kc + hi16) ^ qsw) << 4);
            uint32_t ah[4];
            ldsm4(ah[0], ah[1], ah[2], ah[3], QH + qrow + co_a);
#pragma unroll
            for (int nt = 0; nt < 4; nt++) {   // consume K frags immediately
                int r = nt * 16 + l15;
                uint32_t co = (uint32_t)(((2 * kc + hi16) ^ (r & 7)) << 4);
                uint32_t t0, t1, t2, t3;
                ldsm4(t0, t1, t2, t3, sb + r * 128 + co);
                mma16816(sa[2 * nt],     ah, t0, t2);
                mma16816(sa[2 * nt + 1], ah, t1, t3);
            }
        }

        // ---- online softmax ---------------------------------------------------
#pragma unroll
        for (int half = 0; half < 2; half++) {
            float mx = -1e30f;
#pragma unroll
            for (int j = 0; j < 8; j++) {
                sa[j][2 * half]     *= 0.125f;
                sa[j][2 * half + 1] *= 0.125f;
                mx = fmaxf(mx, fmaxf(sa[j][2 * half], sa[j][2 * half + 1]));
            }
            mx = fmaxf(mx, __shfl_xor_sync(0xffffffffu, mx, 1));
            mx = fmaxf(mx, __shfl_xor_sync(0xffffffffu, mx, 2));
            float nm    = fmaxf(m2[half], mx);
            float alpha = __expf(m2[half] - nm);
            float rs = 0.f;
#pragma unroll
            for (int j = 0; j < 8; j++) {
                sa[j][2 * half]     = __expf(sa[j][2 * half]     - nm);
                sa[j][2 * half + 1] = __expf(sa[j][2 * half + 1] - nm);
                rs += sa[j][2 * half] + sa[j][2 * half + 1];
            }
            rs += __shfl_xor_sync(0xffffffffu, rs, 1);
            rs += __shfl_xor_sync(0xffffffffu, rs, 2);
            l2[half] = l2[half] * alpha + rs;
            m2[half] = nm;
#pragma unroll
            for (int j = 0; j < 8; j++) {
                oa[j][2 * half]     *= alpha;
                oa[j][2 * half + 1] *= alpha;
            }
        }

        // ---- O += P V; P frags built per-kc, V frags consumed immediately -------
#pragma unroll
        for (int kc = 0; kc < 4; kc++) {
            uint32_t ph[4];
            int j0 = 2 * kc, j1 = 2 * kc + 1;
            ph[0] = pack2h(sa[j0][0], sa[j0][1]);
            ph[1] = pack2h(sa[j0][2], sa[j0][3]);
            ph[2] = pack2h(sa[j1][0], sa[j1][1]);
            ph[3] = pack2h(sa[j1][2], sa[j1][3]);
            int rowt = kc * 16 + rsel;
#pragma unroll
            for (int jt = 0; jt < 4; jt++) {
                int c8 = jt * 2 + b3;
                uint32_t ad = sb + 8192 + rowt * 128 + (uint32_t)((c8 ^ (rowt & 7)) << 4);
                uint32_t t0, t1, t2, t3;
                ldsm4t(t0, t1, t2, t3, ad);
                mma16816(oa[2 * jt],     ph, t0, t2);
                mma16816(oa[2 * jt + 1], ph, t1, t3);
            }
        }
    }

    // ---- epilogue ---------------------------------------------------------------
    float inv0 = 1.f / l2[0];
    float inv1 = 1.f / l2[1];
    int r0 = q0 + wq * 16 + (lane >> 2);
#pragma unroll
    for (int j = 0; j < 8; j++) {
        int col = h * 64 + j * 8 + (lane & 3) * 2;
        size_t g0 = (tokbase + r0) * 1024 + col;
        size_t g1 = (tokbase + r0 + 8) * 1024 + col;
        *reinterpret_cast<uint32_t*>(oh + g0) = pack2h(oa[j][0] * inv0, oa[j][1] * inv0);
        *reinterpret_cast<uint32_t*>(oh + g1) = pack2h(oa[j][2] * inv1, oa[j][3] * inv1);
    }
}

// ---------------- layernorm -----------------------------------------------------
__global__ __launch_bounds__(256) void ln_kernel(const float* __restrict__ in,
                                                 const float* __restrict__ gamma,
                                                 const float* __restrict__ beta,
                                                 float* __restrict__ outF,
                                                 __half* __restrict__ outH)
{
    const int row = blockIdx.x, tid = threadIdx.x;
    const float* p = in + (size_t)row * 1024;
    float4 v = *(const float4*)(p + tid * 4);
    float s  = v.x + v.y + v.z + v.w;
    float ss = v.x * v.x + v.y * v.y + v.z * v.z + v.w * v.w;
#pragma unroll
    for (int off = 16; off > 0; off >>= 1) {
        s  += __shfl_xor_sync(0xffffffffu, s,  off);
        ss += __shfl_xor_sync(0xffffffffu, ss, off);
    }
    __shared__ float sb[8], ssb[8];
    __shared__ float smu, sinv;
    if ((tid & 31) == 0) { sb[tid >> 5] = s; ssb[tid >> 5] = ss; }
    __syncthreads();
    if (tid == 0) {
        float S = 0.f, SS = 0.f;
#pragma unroll
        for (int i = 0; i < 8; i++) { S += sb[i]; SS += ssb[i]; }
        float mu  = S * (1.f / 1024.f);
        float var = SS * (1.f / 1024.f) - mu * mu;
        smu = mu; sinv = rsqrtf(var + 1e-5f);
    }
    __syncthreads();
    float mu = smu, inv = sinv;
    float4 g = *(const float4*)(gamma + tid * 4);
    float4 b = *(const float4*)(beta  + tid * 4);
    float4 o;
    o.x = (v.x - mu) * inv * g.x + b.x;
    o.y = (v.y - mu) * inv * g.y + b.y;
    o.z = (v.z - mu) * inv * g.z + b.z;
    o.w = (v.w - mu) * inv * g.w + b.w;
    size_t idx = (size_t)row * 1024 + tid * 4;
    *(float4*)&outF[idx] = o;
    if (outH) {
        *reinterpret_cast<uint32_t*>(outH + idx)     = pack2h(o.x, o.y);
        *reinterpret_cast<uint32_t*>(outH + idx + 2) = pack2h(o.z, o.w);
    }
}

// ---------------- launch ----------------------------------------------------------
extern "C" void kernel_launch(void* const* d_in, const int* in_sizes, int n_in,
                              void* d_out, int out_size)
{
    const float* x     = (const float*)d_in[0];
    const float* Wq    = (const float*)d_in[1];
    const float* Wk    = (const float*)d_in[2];
    const float* Wv    = (const float*)d_in[3];
    const float* Wo    = (const float*)d_in[4];
    const float* ln1_g = (const float*)d_in[5];
    const float* ln1_b = (const float*)d_in[6];
    const float* W1    = (const float*)d_in[7];
    const float* b1    = (const float*)d_in[8];
    const float* W2    = (const float*)d_in[9];
    const float* b2    = (const float*)d_in[10];
    const float* ln2_g = (const float*)d_in[11];
    const float* ln2_b = (const float*)d_in[12];
    float* out = (float*)d_out;

    cudaFuncSetAttribute(gemm_mma,   cudaFuncAttributeMaxDynamicSharedMemorySize, GEMM_SMEM);
    cudaFuncSetAttribute(flash_hmma, cudaFuncAttributeMaxDynamicSharedMemorySize, ATT_SMEM);

    float *t1, *x1, *t2;
    __half *wqkvh, *xh, *qkvh, *oh, *woh, *x1h, *w1h, *hh, *w2h;
    cudaGetSymbolAddress((void**)&t1,    g_t1);
    cudaGetSymbolAddress((void**)&x1,    g_x1);
    cudaGetSymbolAddress((void**)&t2,    g_t2);
    cudaGetSymbolAddress((void**)&wqkvh, g_wqkvh);
    cudaGetSymbolAddress((void**)&xh,    g_xh);
    cudaGetSymbolAddress((void**)&qkvh,  g_qkvh);
    cudaGetSymbolAddress((void**)&oh,    g_oh);
    cudaGetSymbolAddress((void**)&woh,   g_woh);
    cudaGetSymbolAddress((void**)&x1h,   g_x1h);
    cudaGetSymbolAddress((void**)&w1h,   g_w1h);
    cudaGetSymbolAddress((void**)&hh,    g_hh);
    cudaGetSymbolAddress((void**)&w2h,   g_w2h);

    // weight prep: native-layout fp16 converts only (vectorized)
    wqkv_pack<<<6144, 256>>>(Wq, Wk, Wv, wqkvh);
    cvt_h<<<512,  256>>>(Wo, woh);
    cvt_h<<<2048, 256>>>(W1, w1h);
    cvt_h<<<2048, 256>>>(W2, w2h);
    cvt_h<<<2048, 256>>>(x,  xh);

    // 1. QKV projection -> qkv fp16
    gemm_mma<<<dim3(24, 32), 256, GEMM_SMEM>>>(xh, wqkvh, 4096, 3072, 1024,
                                               nullptr, nullptr, 0, nullptr, qkvh);
    // 2. flash attention -> o fp16
    flash_hmma<<<dim3(16, NH, BATCH), 256, ATT_SMEM>>>(qkvh, oh);
    // 3. output projection + residual x -> t1 fp32
    gemm_mma<<<dim3(8, 32), 256, GEMM_SMEM>>>(oh, woh, 4096, 1024, 1024,
                                              nullptr, x, 0, t1, nullptr);
    // 4. LN1 -> x1 fp32 + fp16
    ln_kernel<<<4096, 256>>>(t1, ln1_g, ln1_b, x1, x1h);
    // 5. FFN up + bias + relu -> h fp16
    gemm_mma<<<dim3(32, 32), 256, GEMM_SMEM>>>(x1h, w1h, 4096, 4096, 1024,
                                               b1, nullptr, 1, nullptr, hh);
    // 6. FFN down + bias + residual x1 -> t2 fp32
    gemm_mma<<<dim3(8, 32), 256, GEMM_SMEM>>>(hh, w2h, 4096, 1024, 4096,
                                              b2, x1, 0, t2, nullptr);
    // 7. LN2 -> out
    ln_kernel<<<4096, 256>>>(t2, ln2_g, ln2_b, out, nullptr);
}

// round 10
// speedup vs baseline: 7.1355x; 1.0518x over previous
#include <cuda_runtime.h>
#include <cuda_fp16.h>
#include <cstdint>

#define SEQ    2048
#define BATCH  2
#define NH     16
#define QKVLD  3072
#define STAGES 3
#define STAGE_BYTES 32768
#define GEMM_SMEM (STAGES * STAGE_BYTES + 1024)
#define NSTG   2
#define ATT_SMEM  (8192 + NSTG * 16384 + 1024)

// ---------------- scratch (static device globals; no allocation) -------------
__device__ __half  g_wqkvh[1024u * 3072u];   // [K=1024, N=3072] row-major
__device__ __half  g_xh   [4096u * 1024u];
__device__ __half  g_qkvh [4096u * 3072u];
__device__ __half  g_oh   [4096u * 1024u];
__device__ __half  g_woh  [1024u * 1024u];   // [K,N] native
__device__ float   g_t1   [4096u * 1024u];
__device__ float   g_x1   [4096u * 1024u];
__device__ __half  g_x1h  [4096u * 1024u];
__device__ __half  g_w1h  [1024u * 4096u];   // [K,N] native
__device__ __half  g_hh   [4096u * 4096u];
__device__ __half  g_w2h  [4096u * 1024u];   // [K,N] native
__device__ float   g_t2   [4096u * 1024u];

// ---------------- PTX helpers --------------------------------------------------
__device__ __forceinline__ uint32_t smem_u32(const void* p) {
    uint32_t a;
    asm("{ .reg .u64 t; cvta.to.shared.u64 t, %1; cvt.u32.u64 %0, t; }" : "=r"(a) : "l"(p));
    return a;
}
__device__ __forceinline__ void cp16(uint32_t s, const void* g) {
    asm volatile("cp.async.cg.shared.global [%0], [%1], 16;" :: "r"(s), "l"(g));
}
#define CP_COMMIT()  asm volatile("cp.async.commit_group;" ::: "memory")
#define CP_WAIT(n)   asm volatile("cp.async.wait_group %0;" :: "n"(n) : "memory")

__device__ __forceinline__ void ldsm4(uint32_t& r0, uint32_t& r1, uint32_t& r2, uint32_t& r3,
                                      uint32_t addr) {
    asm volatile("ldmatrix.sync.aligned.m8n8.x4.shared.b16 {%0,%1,%2,%3}, [%4];"
                 : "=r"(r0), "=r"(r1), "=r"(r2), "=r"(r3) : "r"(addr));
}
__device__ __forceinline__ void ldsm4t(uint32_t& r0, uint32_t& r1, uint32_t& r2, uint32_t& r3,
                                       uint32_t addr) {
    asm volatile("ldmatrix.sync.aligned.m8n8.x4.trans.shared.b16 {%0,%1,%2,%3}, [%4];"
                 : "=r"(r0), "=r"(r1), "=r"(r2), "=r"(r3) : "r"(addr));
}
__device__ __forceinline__ void mma16816(float* d, const uint32_t* a, uint32_t b0, uint32_t b1) {
    asm volatile(
        "mma.sync.aligned.m16n8k16.row.col.f32.f16.f16.f32 "
        "{%0,%1,%2,%3}, {%4,%5,%6,%7}, {%8,%9}, {%0,%1,%2,%3};"
        : "+f"(d[0]), "+f"(d[1]), "+f"(d[2]), "+f"(d[3])
        : "r"(a[0]), "r"(a[1]), "r"(a[2]), "r"(a[3]), "r"(b0), "r"(b1));
}
__device__ __forceinline__ uint32_t pack2h(float a, float b) {
    __half2 p = __floats2half2_rn(a, b);
    return *reinterpret_cast<uint32_t*>(&p);
}

// ---------------- fused prep kernel --------------------------------------------
// blocks [0,6144): wqkv gather-pack (2 elems/thread)
// blocks [6144,6656): Wo cvt; [6656,8704): W1; [8704,10752): W2; [10752,12800): x
__global__ void prep_all(const float* __restrict__ Wq, const float* __restrict__ Wk,
                         const float* __restrict__ Wv, __half* __restrict__ wqkv,
                         const float* __restrict__ Wo, __half* __restrict__ woh,
                         const float* __restrict__ W1, __half* __restrict__ w1h,
                         const float* __restrict__ W2, __half* __restrict__ w2h,
                         const float* __restrict__ x,  __half* __restrict__ xh)
{
    int blk = blockIdx.x;
    if (blk < 6144) {
        int t  = blk * 256 + threadIdx.x;          // 0 .. 1572863
        int d  = t / (QKVLD / 2);                  // 0..1023 (3072 NOT pow2 -> div)
        int n  = (t - d * (QKVLD / 2)) * 2;        // even n in row
        int w  = n >> 10;
        int h  = (n >> 6) & 15;
        int k  = n & 63;
        const float* src = (w == 0) ? Wq : (w == 1) ? Wk : Wv;
        float2 v = *(const float2*)&src[h * 65536 + d * 64 + k];
        *reinterpret_cast<uint32_t*>(&wqkv[(size_t)d * QKVLD + n]) = pack2h(v.x, v.y);
        return;
    }
    const float* in; __half* oh;
    int rel;
    if (blk < 6656)       { in = Wo; oh = woh; rel = blk - 6144; }
    else if (blk < 8704)  { in = W1; oh = w1h; rel = blk - 6656; }
    else if (blk < 10752) { in = W2; oh = w2h; rel = blk - 8704; }
    else                  { in = x;  oh = xh;  rel = blk - 10752; }
    size_t idx = ((size_t)rel * 256 + threadIdx.x) * 8;
    float4 a = *(const float4*)&in[idx];
    float4 b = *(const float4*)&in[idx + 4];
    uint4 o;
    o.x = pack2h(a.x, a.y); o.y = pack2h(a.z, a.w);
    o.z = pack2h(b.x, b.y); o.w = pack2h(b.z, b.w);
    *(uint4*)&oh[idx] = o;
}

// ---------------- mma.sync fp16 GEMM: C = A B ---------------------------------
// A [M,K] fp16 row-major, B [K,N] fp16 row-major (native weight layout).
// Tile 128x128x64. Stage: A[0,16K); B[16K,32K) as two 64-col subtiles of 8KB.
__device__ __forceinline__ void g_load_stage(uint32_t sb,
    const __half* A, const __half* B, int K, int N, int m0, int n0, int k0, int tid)
{
#pragma unroll
    for (int it = 0; it < 4; it++) {         // A: 128 rows x 8 chunks
        int idx = it * 256 + tid;
        int r = idx >> 3, c = idx & 7;
        uint32_t soff = (uint32_t)(r * 128 + ((c ^ (r & 7)) << 4));
        cp16(sb + soff, A + (size_t)(m0 + r) * K + k0 + c * 8);
    }
#pragma unroll
    for (int it = 0; it < 4; it++) {         // B: 64 k-rows x 16 chunks
        int idx = it * 256 + tid;
        int r = idx >> 4, c = idx & 15;
        uint32_t soff = (uint32_t)((c >> 3) * 8192 + r * 128 + (((c & 7) ^ (r & 7)) << 4));
        cp16(sb + 16384 + soff, B + (size_t)(k0 + r) * N + n0 + c * 8);
    }
}

__global__ __launch_bounds__(256, 2) void gemm_mma(
    const __half* __restrict__ A, const __half* __restrict__ B,
    int M, int N, int K,
    const float* __restrict__ bias, const float* __restrict__ res, int relu,
    float* __restrict__ outF, __half* __restrict__ outH)
{
    extern __shared__ char dsm_raw[];
    uint32_t base = (smem_u32(dsm_raw) + 1023) & ~1023u;

    const int tid  = threadIdx.x;
    const int wid  = tid >> 5;
    const int lane = tid & 31;
    const int wm   = wid >> 2;
    const int wn   = wid & 3;
    const int m0   = blockIdx.y * 128;
    const int n0   = blockIdx.x * 128;
    const int wr   = wm * 64;
    const int wc   = wn * 32;
    const int l15  = lane & 15;
    const int hi16 = lane >> 4;

    uint32_t a_row[4], a_sw[4];
#pragma unroll
    for (int mt = 0; mt < 4; mt++) {
        int r = wr + mt * 16 + l15;
        a_row[mt] = (uint32_t)(r * 128);
        a_sw[mt]  = (uint32_t)(r & 7);
    }
    const uint32_t bsub_off = 16384u + (uint32_t)((wc >> 6) * 8192);
    const int base_c8 = (wc & 63) >> 3;           // 0 or 4
    const int b3      = (lane >> 3) & 1;
    const int rsel    = ((lane >> 4) << 3) + (lane & 7);   // 0..15 row in k-chunk

    float acc[4][4][4];
#pragma unroll
    for (int i = 0; i < 4; i++)
#pragma unroll
        for (int j = 0; j < 4; j++)
#pragma unroll
            for (int q = 0; q < 4; q++) acc[i][j][q] = 0.f;

    const int nK = K >> 6;

#pragma unroll
    for (int s = 0; s < STAGES - 1; s++) {
        g_load_stage(base + s * STAGE_BYTES, A, B, K, N, m0, n0, s * 64, tid);
        CP_COMMIT();
    }

    for (int kt = 0; kt < nK; kt++) {
        CP_WAIT(STAGES - 2);
        __syncthreads();    // also orders reuse of stage (kt+2)%3 == (kt-1)%3

        int ls = kt + STAGES - 1;
        if (ls < nK)
            g_load_stage(base + (ls % STAGES) * STAGE_BYTES, A, B, K, N, m0, n0, ls * 64, tid);
        CP_COMMIT();

        uint32_t sb = base + (kt % STAGES) * STAGE_BYTES;
#pragma unroll
        for (int kh = 0; kh < 4; kh++) {
            uint32_t ah[4][4];
#pragma unroll
            for (int mt = 0; mt < 4; mt++) {
                uint32_t co = (uint32_t)(((2 * kh + hi16) ^ a_sw[mt]) << 4);
                ldsm4(ah[mt][0], ah[mt][1], ah[mt][2], ah[mt][3], sb + a_row[mt] + co);
            }
            int rowt = kh * 16 + rsel;
#pragma unroll
            for (int jt = 0; jt < 2; jt++) {   // consume B frags immediately
                int c8 = base_c8 + jt * 2 + b3;
                uint32_t ad = sb + bsub_off + rowt * 128 + (uint32_t)((c8 ^ (rowt & 7)) << 4);
                uint32_t t0, t1, t2, t3;
                ldsm4t(t0, t1, t2, t3, ad);
#pragma unroll
                for (int mt = 0; mt < 4; mt++) {
                    mma16816(acc[mt][2 * jt],     ah[mt], t0, t2);
                    mma16816(acc[mt][2 * jt + 1], ah[mt], t1, t3);
                }
            }
        }
    }
    __syncthreads();

    const int rq = lane >> 2;
    const int cq = (lane & 3) * 2;
#pragma unroll
    for (int mt = 0; mt < 4; mt++)
#pragma unroll
        for (int half = 0; half < 2; half++) {
            int row = m0 + wr + mt * 16 + rq + half * 8;
            size_t rb = (size_t)row * N;
#pragma unroll
            for (int j = 0; j < 4; j++) {
                int col = n0 + wc + j * 8 + cq;
                float v0 = acc[mt][j][half * 2 + 0];
                float v1 = acc[mt][j][half * 2 + 1];
                if (bias) { v0 += bias[col]; v1 += bias[col + 1]; }
                if (relu) { v0 = fmaxf(v0, 0.f); v1 = fmaxf(v1, 0.f); }
                if (res)  {
                    float2 rr = *(const float2*)&res[rb + col];
                    v0 += rr.x; v1 += rr.y;
                }
                if (outF) *(float2*)&outF[rb + col] = make_float2(v0, v1);
                if (outH) *reinterpret_cast<uint32_t*>(outH + rb + col) = pack2h(v0, v1);
            }
        }
}

// ---------------- HMMA flash attention -----------------------------------------
// 64-row Q tiles, 128 threads (4 warps x 16 q-rows), 2 KV stages, occ 4.
// smem: Q[0,8K); KV stage s at 8K+s*16K: K[0,8K) V[8K,16K).
__device__ __forceinline__ void att_load_kv(uint32_t sb,
    const __half* qkv, size_t tokbase, int h, int kt, int tid)
{
#pragma unroll
    for (int it = 0; it < 4; it++) {
        int idx = it * 128 + tid;       // 0..511 : 64 rows x 8 chunks
        int r = idx >> 3, c = idx & 7;
        uint32_t sw = (uint32_t)(r * 128 + ((c ^ (r & 7)) << 4));
        size_t gk = (tokbase + kt * 64 + r) * QKVLD + 1024 + h * 64 + c * 8;
        cp16(sb        + sw, qkv + gk);
        cp16(sb + 8192 + sw, qkv + gk + 1024);
    }
}

__global__ __launch_bounds__(128, 4) void flash_hmma(
    const __half* __restrict__ qkv, __half* __restrict__ oh)
{
    extern __shared__ char smem_raw[];
    uint32_t base = (smem_u32(smem_raw) + 1023) & ~1023u;
    const uint32_t QH = base;

    const int tid  = threadIdx.x;
    const int wq   = tid >> 5;           // 0..3
    const int lane = tid & 31;
    const int l15  = lane & 15;
    const int hi16 = lane >> 4;
    const int q0   = blockIdx.x * 64;
    const int h    = blockIdx.y;
    const int b    = blockIdx.z;
    const size_t tokbase = (size_t)b * SEQ;

    // Q tile (64 rows) + KV stage 0 in group 0
#pragma unroll
    for (int it = 0; it < 4; it++) {
        int idx = it * 128 + tid;        // 0..511
        int r = idx >> 3, c = idx & 7;
        uint32_t sw = (uint32_t)(r * 128 + ((c ^ (r & 7)) << 4));
        cp16(QH + sw, qkv + (tokbase + q0 + r) * QKVLD + h * 64 + c * 8);
    }
    att_load_kv(base + 8192, qkv, tokbase, h, 0, tid);
    CP_COMMIT();

    float m2[2] = {-1e30f, -1e30f};
    float l2[2] = {0.f, 0.f};
    float oa[8][4];
#pragma unroll
    for (int j = 0; j < 8; j++)
#pragma unroll
        for (int q = 0; q < 4; q++) oa[j][q] = 0.f;

    const uint32_t qrow = (uint32_t)((wq * 16 + l15) * 128);
    const uint32_t qsw  = (uint32_t)((wq * 16 + l15) & 7);
    const int rsel = ((lane >> 4) << 3) + (lane & 7);
    const int b3   = (lane >> 3) & 1;

    for (int kt = 0; kt < SEQ / 64; kt++) {
        CP_WAIT(0);
        __syncthreads();
        int ls = kt + 1;
        if (ls < SEQ / 64)
            att_load_kv(base + 8192 + (ls & 1) * 16384, qkv, tokbase, h, ls, tid);
        CP_COMMIT();

        uint32_t sb = base + 8192 + (kt & 1) * 16384;

        // ---- S = Q K^T -------------------------------------------------------
        float sa[8][4];
#pragma unroll
        for (int j = 0; j < 8; j++)
#pragma unroll
            for (int q = 0; q < 4; q++) sa[j][q] = 0.f;

#pragma unroll
        for (int kc = 0; kc < 4; kc++) {
            uint32_t co_a = (uint32_t)(((2 * kc + hi16) ^ qsw) << 4);
            uint32_t ah[4];
            ldsm4(ah[0], ah[1], ah[2], ah[3], QH + qrow + co_a);
#pragma unroll
            for (int nt = 0; nt < 4; nt++) {   // consume K frags immediately
                int r = nt * 16 + l15;
                uint32_t co = (uint32_t)(((2 * kc + hi16) ^ (r & 7)) << 4);
                uint32_t t0, t1, t2, t3;
                ldsm4(t0, t1, t2, t3, sb + r * 128 + co);
                mma16816(sa[2 * nt],     ah, t0, t2);
                mma16816(sa[2 * nt + 1], ah, t1, t3);
            }
        }

        // ---- online softmax ---------------------------------------------------
#pragma unroll
        for (int half = 0; half < 2; half++) {
            float mx = -1e30f;
#pragma unroll
            for (int j = 0; j < 8; j++) {
                sa[j][2 * half]     *= 0.125f;
                sa[j][2 * half + 1] *= 0.125f;
                mx = fmaxf(mx, fmaxf(sa[j][2 * half], sa[j][2 * half + 1]));
            }
            mx = fmaxf(mx, __shfl_xor_sync(0xffffffffu, mx, 1));
            mx = fmaxf(mx, __shfl_xor_sync(0xffffffffu, mx, 2));
            float nm    = fmaxf(m2[half], mx);
            float alpha = __expf(m2[half] - nm);
            float rs = 0.f;
#pragma unroll
            for (int j = 0; j < 8; j++) {
                sa[j][2 * half]     = __expf(sa[j][2 * half]     - nm);
                sa[j][2 * half + 1] = __expf(sa[j][2 * half + 1] - nm);
                rs += sa[j][2 * half] + sa[j][2 * half + 1];
            }
            rs += __shfl_xor_sync(0xffffffffu, rs, 1);
            rs += __shfl_xor_sync(0xffffffffu, rs, 2);
            l2[half] = l2[half] * alpha + rs;
            m2[half] = nm;
#pragma unroll
            for (int j = 0; j < 8; j++) {
                oa[j][2 * half]     *= alpha;
                oa[j][2 * half + 1] *= alpha;
            }
        }

        // ---- O += P V; P frags built per-kc, V frags consumed immediately -------
#pragma unroll
        for (int kc = 0; kc < 4; kc++) {
            uint32_t ph[4];
            int j0 = 2 * kc, j1 = 2 * kc + 1;
            ph[0] = pack2h(sa[j0][0], sa[j0][1]);
            ph[1] = pack2h(sa[j0][2], sa[j0][3]);
            ph[2] = pack2h(sa[j1][0], sa[j1][1]);
            ph[3] = pack2h(sa[j1][2], sa[j1][3]);
            int rowt = kc * 16 + rsel;
#pragma unroll
            for (int jt = 0; jt < 4; jt++) {
                int c8 = jt * 2 + b3;
                uint32_t ad = sb + 8192 + rowt * 128 + (uint32_t)((c8 ^ (rowt & 7)) << 4);
                uint32_t t0, t1, t2, t3;
                ldsm4t(t0, t1, t2, t3, ad);
                mma16816(oa[2 * jt],     ph, t0, t2);
                mma16816(oa[2 * jt + 1], ph, t1, t3);
            }
        }
    }

    // ---- epilogue ---------------------------------------------------------------
    float inv0 = 1.f / l2[0];
    float inv1 = 1.f / l2[1];
    int r0 = q0 + wq * 16 + (lane >> 2);
#pragma unroll
    for (int j = 0; j < 8; j++) {
        int col = h * 64 + j * 8 + (lane & 3) * 2;
        size_t g0 = (tokbase + r0) * 1024 + col;
        size_t g1 = (tokbase + r0 + 8) * 1024 + col;
        *reinterpret_cast<uint32_t*>(oh + g0) = pack2h(oa[j][0] * inv0, oa[j][1] * inv0);
        *reinterpret_cast<uint32_t*>(oh + g1) = pack2h(oa[j][2] * inv1, oa[j][3] * inv1);
    }
}

// ---------------- layernorm -----------------------------------------------------
__global__ __launch_bounds__(256) void ln_kernel(const float* __restrict__ in,
                                                 const float* __restrict__ gamma,
                                                 const float* __restrict__ beta,
                                                 float* __restrict__ outF,
                                                 __half* __restrict__ outH)
{
    const int row = blockIdx.x, tid = threadIdx.x;
    const float* p = in + (size_t)row * 1024;
    float4 v = *(const float4*)(p + tid * 4);
    float s  = v.x + v.y + v.z + v.w;
    float ss = v.x * v.x + v.y * v.y + v.z * v.z + v.w * v.w;
#pragma unroll
    for (int off = 16; off > 0; off >>= 1) {
        s  += __shfl_xor_sync(0xffffffffu, s,  off);
        ss += __shfl_xor_sync(0xffffffffu, ss, off);
    }
    __shared__ float sb[8], ssb[8];
    __shared__ float smu, sinv;
    if ((tid & 31) == 0) { sb[tid >> 5] = s; ssb[tid >> 5] = ss; }
    __syncthreads();
    if (tid == 0) {
        float S = 0.f, SS = 0.f;
#pragma unroll
        for (int i = 0; i < 8; i++) { S += sb[i]; SS += ssb[i]; }
        float mu  = S * (1.f / 1024.f);
        float var = SS * (1.f / 1024.f) - mu * mu;
        smu = mu; sinv = rsqrtf(var + 1e-5f);
    }
    __syncthreads();
    float mu = smu, inv = sinv;
    float4 g = *(const float4*)(gamma + tid * 4);
    float4 b = *(const float4*)(beta  + tid * 4);
    float4 o;
    o.x = (v.x - mu) * inv * g.x + b.x;
    o.y = (v.y - mu) * inv * g.y + b.y;
    o.z = (v.z - mu) * inv * g.z + b.z;
    o.w = (v.w - mu) * inv * g.w + b.w;
    size_t idx = (size_t)row * 1024 + tid * 4;
    *(float4*)&outF[idx] = o;
    if (outH) {
        *reinterpret_cast<uint32_t*>(outH + idx)     = pack2h(o.x, o.y);
        *reinterpret_cast<uint32_t*>(outH + idx + 2) = pack2h(o.z, o.w);
    }
}

// ---------------- launch ----------------------------------------------------------
extern "C" void kernel_launch(void* const* d_in, const int* in_sizes, int n_in,
                              void* d_out, int out_size)
{
    const float* x     = (const float*)d_in[0];
    const float* Wq    = (const float*)d_in[1];
    const float* Wk    = (const float*)d_in[2];
    const float* Wv    = (const float*)d_in[3];
    const float* Wo    = (const float*)d_in[4];
    const float* ln1_g = (const float*)d_in[5];
    const float* ln1_b = (const float*)d_in[6];
    const float* W1    = (const float*)d_in[7];
    const float* b1    = (const float*)d_in[8];
    const float* W2    = (const float*)d_in[9];
    const float* b2    = (const float*)d_in[10];
    const float* ln2_g = (const float*)d_in[11];
    const float* ln2_b = (const float*)d_in[12];
    float* out = (float*)d_out;

    cudaFuncSetAttribute(gemm_mma,   cudaFuncAttributeMaxDynamicSharedMemorySize, GEMM_SMEM);
    cudaFuncSetAttribute(flash_hmma, cudaFuncAttributeMaxDynamicSharedMemorySize, ATT_SMEM);

    float *t1, *x1, *t2;
    __half *wqkvh, *xh, *qkvh, *oh, *woh, *x1h, *w1h, *hh, *w2h;
    cudaGetSymbolAddress((void**)&t1,    g_t1);
    cudaGetSymbolAddress((void**)&x1,    g_x1);
    cudaGetSymbolAddress((void**)&t2,    g_t2);
    cudaGetSymbolAddress((void**)&wqkvh, g_wqkvh);
    cudaGetSymbolAddress((void**)&xh,    g_xh);
    cudaGetSymbolAddress((void**)&qkvh,  g_qkvh);
    cudaGetSymbolAddress((void**)&oh,    g_oh);
    cudaGetSymbolAddress((void**)&woh,   g_woh);
    cudaGetSymbolAddress((void**)&x1h,   g_x1h);
    cudaGetSymbolAddress((void**)&w1h,   g_w1h);
    cudaGetSymbolAddress((void**)&hh,    g_hh);
    cudaGetSymbolAddress((void**)&w2h,   g_w2h);

    // 0. fused weight/activation prep (one launch)
    prep_all<<<12800, 256>>>(Wq, Wk, Wv, wqkvh, Wo, woh, W1, w1h, W2, w2h, x, xh);

    // 1. QKV projection -> qkv fp16
    gemm_mma<<<dim3(24, 32), 256, GEMM_SMEM>>>(xh, wqkvh, 4096, 3072, 1024,
                                               nullptr, nullptr, 0, nullptr, qkvh);
    // 2. flash attention -> o fp16 (64-row Q tiles, occ4)
    flash_hmma<<<dim3(32, NH, BATCH), 128, ATT_SMEM>>>(qkvh, oh);
    // 3. output projection + residual x -> t1 fp32
    gemm_mma<<<dim3(8, 32), 256, GEMM_SMEM>>>(oh, woh, 4096, 1024, 1024,
                                              nullptr, x, 0, t1, nullptr);
    // 4. LN1 -> x1 fp32 + fp16
    ln_kernel<<<4096, 256>>>(t1, ln1_g, ln1_b, x1, x1h);
    // 5. FFN up + bias + relu -> h fp16
    gemm_mma<<<dim3(32, 32), 256, GEMM_SMEM>>>(x1h, w1h, 4096, 4096, 1024,
                                               b1, nullptr, 1, nullptr, hh);
    // 6. FFN down + bias + residual x1 -> t2 fp32
    gemm_mma<<<dim3(8, 32), 256, GEMM_SMEM>>>(hh, w2h, 4096, 1024, 4096,
                                              b2, x1, 0, t2, nullptr);
    // 7. LN2 -> out
    ln_kernel<<<4096, 256>>>(t2, ln2_g, ln2_b, out, nullptr);
}

// round 11
// speedup vs baseline: 7.4426x; 1.0430x over previous
#include <cuda_runtime.h>
#include <cuda_fp16.h>
#include <cstdint>

#define SEQ    2048
#define BATCH  2
#define NH     16
#define QKVLD  3072
#define STAGES 3
#define STAGE_BYTES 32768
#define GEMM_SMEM (STAGES * STAGE_BYTES + 1024)
#define NSTG   2
#define ATT_SMEM  (8192 + NSTG * 16384 + 1024)

// ---------------- scratch (static device globals; no allocation) -------------
__device__ __half  g_wqkvh[1024u * 3072u];   // [K=1024, N=3072] row-major
__device__ __half  g_xh   [4096u * 1024u];
__device__ __half  g_qkvh [4096u * 3072u];
__device__ __half  g_oh   [4096u * 1024u];
__device__ __half  g_woh  [1024u * 1024u];   // [K,N] native
__device__ float   g_t1   [4096u * 1024u];
__device__ float   g_x1   [4096u * 1024u];
__device__ __half  g_x1h  [4096u * 1024u];
__device__ __half  g_w1h  [1024u * 4096u];   // [K,N] native
__device__ __half  g_hh   [4096u * 4096u];
__device__ __half  g_w2h  [4096u * 1024u];   // [K,N] native
__device__ float   g_t2   [4096u * 1024u];

// ---------------- PTX helpers --------------------------------------------------
__device__ __forceinline__ uint32_t smem_u32(const void* p) {
    uint32_t a;
    asm("{ .reg .u64 t; cvta.to.shared.u64 t, %1; cvt.u32.u64 %0, t; }" : "=r"(a) : "l"(p));
    return a;
}
__device__ __forceinline__ void cp16(uint32_t s, const void* g) {
    asm volatile("cp.async.cg.shared.global [%0], [%1], 16;" :: "r"(s), "l"(g));
}
#define CP_COMMIT()  asm volatile("cp.async.commit_group;" ::: "memory")
#define CP_WAIT(n)   asm volatile("cp.async.wait_group %0;" :: "n"(n) : "memory")

__device__ __forceinline__ void ldsm4(uint32_t& r0, uint32_t& r1, uint32_t& r2, uint32_t& r3,
                                      uint32_t addr) {
    asm volatile("ldmatrix.sync.aligned.m8n8.x4.shared.b16 {%0,%1,%2,%3}, [%4];"
                 : "=r"(r0), "=r"(r1), "=r"(r2), "=r"(r3) : "r"(addr));
}
__device__ __forceinline__ void ldsm4t(uint32_t& r0, uint32_t& r1, uint32_t& r2, uint32_t& r3,
                                       uint32_t addr) {
    asm volatile("ldmatrix.sync.aligned.m8n8.x4.trans.shared.b16 {%0,%1,%2,%3}, [%4];"
                 : "=r"(r0), "=r"(r1), "=r"(r2), "=r"(r3) : "r"(addr));
}
__device__ __forceinline__ void mma16816(float* d, const uint32_t* a, uint32_t b0, uint32_t b1) {
    asm volatile(
        "mma.sync.aligned.m16n8k16.row.col.f32.f16.f16.f32 "
        "{%0,%1,%2,%3}, {%4,%5,%6,%7}, {%8,%9}, {%0,%1,%2,%3};"
        : "+f"(d[0]), "+f"(d[1]), "+f"(d[2]), "+f"(d[3])
        : "r"(a[0]), "r"(a[1]), "r"(a[2]), "r"(a[3]), "r"(b0), "r"(b1));
}
__device__ __forceinline__ uint32_t pack2h(float a, float b) {
    __half2 p = __floats2half2_rn(a, b);
    return *reinterpret_cast<uint32_t*>(&p);
}

// ---------------- fused prep kernel --------------------------------------------
__global__ void prep_all(const float* __restrict__ Wq, const float* __restrict__ Wk,
                         const float* __restrict__ Wv, __half* __restrict__ wqkv,
                         const float* __restrict__ Wo, __half* __restrict__ woh,
                         const float* __restrict__ W1, __half* __restrict__ w1h,
                         const float* __restrict__ W2, __half* __restrict__ w2h,
                         const float* __restrict__ x,  __half* __restrict__ xh)
{
    int blk = blockIdx.x;
    if (blk < 6144) {
        int t  = blk * 256 + threadIdx.x;          // 0 .. 1572863
        int d  = t / (QKVLD / 2);                  // 0..1023 (3072 NOT pow2 -> div)
        int n  = (t - d * (QKVLD / 2)) * 2;        // even n in row
        int w  = n >> 10;
        int h  = (n >> 6) & 15;
        int k  = n & 63;
        const float* src = (w == 0) ? Wq : (w == 1) ? Wk : Wv;
        float2 v = *(const float2*)&src[h * 65536 + d * 64 + k];
        *reinterpret_cast<uint32_t*>(&wqkv[(size_t)d * QKVLD + n]) = pack2h(v.x, v.y);
        return;
    }
    const float* in; __half* oh;
    int rel;
    if (blk < 6656)       { in = Wo; oh = woh; rel = blk - 6144; }
    else if (blk < 8704)  { in = W1; oh = w1h; rel = blk - 6656; }
    else if (blk < 10752) { in = W2; oh = w2h; rel = blk - 8704; }
    else                  { in = x;  oh = xh;  rel = blk - 10752; }
    size_t idx = ((size_t)rel * 256 + threadIdx.x) * 8;
    float4 a = *(const float4*)&in[idx];
    float4 b = *(const float4*)&in[idx + 4];
    uint4 o;
    o.x = pack2h(a.x, a.y); o.y = pack2h(a.z, a.w);
    o.z = pack2h(b.x, b.y); o.w = pack2h(b.z, b.w);
    *(uint4*)&oh[idx] = o;
}

// ---------------- mma.sync fp16 GEMM: C = A B ---------------------------------
// A [M,K] fp16 row-major, B [K,N] fp16 row-major (native weight layout).
// Tile 128x128x64, 8 warps as 4m x 2n, warp tile 32x64 (6 ldsm : 16 mma per kh).
// Stage: A[0,16K); B[16K,32K) as two 64-col subtiles of 8KB.
__device__ __forceinline__ void g_load_stage(uint32_t sb,
    const __half* A, const __half* B, int K, int N, int m0, int n0, int k0, int tid)
{
#pragma unroll
    for (int it = 0; it < 4; it++) {         // A: 128 rows x 8 chunks
        int idx = it * 256 + tid;
        int r = idx >> 3, c = idx & 7;
        uint32_t soff = (uint32_t)(r * 128 + ((c ^ (r & 7)) << 4));
        cp16(sb + soff, A + (size_t)(m0 + r) * K + k0 + c * 8);
    }
#pragma unroll
    for (int it = 0; it < 4; it++) {         // B: 64 k-rows x 16 chunks
        int idx = it * 256 + tid;
        int r = idx >> 4, c = idx & 15;
        uint32_t soff = (uint32_t)((c >> 3) * 8192 + r * 128 + (((c & 7) ^ (r & 7)) << 4));
        cp16(sb + 16384 + soff, B + (size_t)(k0 + r) * N + n0 + c * 8);
    }
}

__global__ __launch_bounds__(256, 2) void gemm_mma(
    const __half* __restrict__ A, const __half* __restrict__ B,
    int M, int N, int K,
    const float* __restrict__ bias, const float* __restrict__ res, int relu,
    float* __restrict__ outF, __half* __restrict__ outH)
{
    extern __shared__ char dsm_raw[];
    uint32_t base = (smem_u32(dsm_raw) + 1023) & ~1023u;

    const int tid  = threadIdx.x;
    const int wid  = tid >> 5;
    const int lane = tid & 31;
    const int wm   = wid >> 1;          // 0..3  (32 rows each)
    const int wn   = wid & 1;           // 0..1  (64 cols each)
    const int m0   = blockIdx.y * 128;
    const int n0   = blockIdx.x * 128;
    const int wr   = wm * 32;
    const int wc   = wn * 64;
    const int l15  = lane & 15;
    const int hi16 = lane >> 4;

    uint32_t a_row[2], a_sw[2];
#pragma unroll
    for (int mt = 0; mt < 2; mt++) {
        int r = wr + mt * 16 + l15;
        a_row[mt] = (uint32_t)(r * 128);
        a_sw[mt]  = (uint32_t)(r & 7);
    }
    const uint32_t bsub_off = 16384u + (uint32_t)(wn * 8192);
    const int b3   = (lane >> 3) & 1;
    const int rsel = ((lane >> 4) << 3) + (lane & 7);   // 0..15 row in k-chunk

    float acc[2][8][4];
#pragma unroll
    for (int i = 0; i < 2; i++)
#pragma unroll
        for (int j = 0; j < 8; j++)
#pragma unroll
            for (int q = 0; q < 4; q++) acc[i][j][q] = 0.f;

    const int nK = K >> 6;

#pragma unroll
    for (int s = 0; s < STAGES - 1; s++) {
        g_load_stage(base + s * STAGE_BYTES, A, B, K, N, m0, n0, s * 64, tid);
        CP_COMMIT();
    }

    for (int kt = 0; kt < nK; kt++) {
        CP_WAIT(STAGES - 2);
        __syncthreads();    // also orders reuse of stage (kt+2)%3 == (kt-1)%3

        int ls = kt + STAGES - 1;
        if (ls < nK)
            g_load_stage(base + (ls % STAGES) * STAGE_BYTES, A, B, K, N, m0, n0, ls * 64, tid);
        CP_COMMIT();

        uint32_t sb = base + (kt % STAGES) * STAGE_BYTES;
#pragma unroll
        for (int kh = 0; kh < 4; kh++) {
            uint32_t ah[2][4];
#pragma unroll
            for (int mt = 0; mt < 2; mt++) {
                uint32_t co = (uint32_t)(((2 * kh + hi16) ^ a_sw[mt]) << 4);
                ldsm4(ah[mt][0], ah[mt][1], ah[mt][2], ah[mt][3], sb + a_row[mt] + co);
            }
            int rowt = kh * 16 + rsel;
#pragma unroll
            for (int jt = 0; jt < 4; jt++) {   // 4 ldsm4t covering 64 cols; 4 MMAs each
                int c8 = jt * 2 + b3;
                uint32_t ad = sb + bsub_off + rowt * 128 + (uint32_t)((c8 ^ (rowt & 7)) << 4);
                uint32_t t0, t1, t2, t3;
                ldsm4t(t0, t1, t2, t3, ad);
#pragma unroll
                for (int mt = 0; mt < 2; mt++) {
                    mma16816(acc[mt][2 * jt],     ah[mt], t0, t2);
                    mma16816(acc[mt][2 * jt + 1], ah[mt], t1, t3);
                }
            }
        }
    }
    __syncthreads();

    const int rq = lane >> 2;
    const int cq = (lane & 3) * 2;
#pragma unroll
    for (int mt = 0; mt < 2; mt++)
#pragma unroll
        for (int half = 0; half < 2; half++) {
            int row = m0 + wr + mt * 16 + rq + half * 8;
            size_t rb = (size_t)row * N;
#pragma unroll
            for (int j = 0; j < 8; j++) {
                int col = n0 + wc + j * 8 + cq;
                float v0 = acc[mt][j][half * 2 + 0];
                float v1 = acc[mt][j][half * 2 + 1];
                if (bias) { v0 += bias[col]; v1 += bias[col + 1]; }
                if (relu) { v0 = fmaxf(v0, 0.f); v1 = fmaxf(v1, 0.f); }
                if (res)  {
                    float2 rr = *(const float2*)&res[rb + col];
                    v0 += rr.x; v1 += rr.y;
                }
                if (outF) *(float2*)&outF[rb + col] = make_float2(v0, v1);
                if (outH) *reinterpret_cast<uint32_t*>(outH + rb + col) = pack2h(v0, v1);
            }
        }
}

// ---------------- HMMA flash attention -----------------------------------------
// 64-row Q tiles, 128 threads (4 warps x 16 q-rows), 2 KV stages, occ 4.
// smem: Q[0,8K); KV stage s at 8K+s*16K: K[0,8K) V[8K,16K).
__device__ __forceinline__ void att_load_kv(uint32_t sb,
    const __half* qkv, size_t tokbase, int h, int kt, int tid)
{
#pragma unroll
    for (int it = 0; it < 4; it++) {
        int idx = it * 128 + tid;       // 0..511 : 64 rows x 8 chunks
        int r = idx >> 3, c = idx & 7;
        uint32_t sw = (uint32_t)(r * 128 + ((c ^ (r & 7)) << 4));
        size_t gk = (tokbase + kt * 64 + r) * QKVLD + 1024 + h * 64 + c * 8;
        cp16(sb        + sw, qkv + gk);
        cp16(sb + 8192 + sw, qkv + gk + 1024);
    }
}

__global__ __launch_bounds__(128, 4) void flash_hmma(
    const __half* __restrict__ qkv, __half* __restrict__ oh)
{
    extern __shared__ char smem_raw[];
    uint32_t base = (smem_u32(smem_raw) + 1023) & ~1023u;
    const uint32_t QH = base;

    const int tid  = threadIdx.x;
    const int wq   = tid >> 5;           // 0..3
    const int lane = tid & 31;
    const int l15  = lane & 15;
    const int hi16 = lane >> 4;
    const int q0   = blockIdx.x * 64;
    const int h    = blockIdx.y;
    const int b    = blockIdx.z;
    const size_t tokbase = (size_t)b * SEQ;

    // Q tile (64 rows) + KV stage 0 in group 0
#pragma unroll
    for (int it = 0; it < 4; it++) {
        int idx = it * 128 + tid;        // 0..511
        int r = idx >> 3, c = idx & 7;
        uint32_t sw = (uint32_t)(r * 128 + ((c ^ (r & 7)) << 4));
        cp16(QH + sw, qkv + (tokbase + q0 + r) * QKVLD + h * 64 + c * 8);
    }
    att_load_kv(base + 8192, qkv, tokbase, h, 0, tid);
    CP_COMMIT();

    float m2[2] = {-1e30f, -1e30f};
    float l2[2] = {0.f, 0.f};
    float oa[8][4];
#pragma unroll
    for (int j = 0; j < 8; j++)
#pragma unroll
        for (int q = 0; q < 4; q++) oa[j][q] = 0.f;

    const uint32_t qrow = (uint32_t)((wq * 16 + l15) * 128);
    const uint32_t qsw  = (uint32_t)((wq * 16 + l15) & 7);
    const int rsel = ((lane >> 4) << 3) + (lane & 7);
    const int b3   = (lane >> 3) & 1;

    for (int kt = 0; kt < SEQ / 64; kt++) {
        CP_WAIT(0);
        __syncthreads();
        int ls = kt + 1;
        if (ls < SEQ / 64)
            att_load_kv(base + 8192 + (ls & 1) * 16384, qkv, tokbase, h, ls, tid);
        CP_COMMIT();

        uint32_t sb = base + 8192 + (kt & 1) * 16384;

        // ---- S = Q K^T -------------------------------------------------------
        float sa[8][4];
#pragma unroll
        for (int j = 0; j < 8; j++)
#pragma unroll
            for (int q = 0; q < 4; q++) sa[j][q] = 0.f;

#pragma unroll
        for (int kc = 0; kc < 4; kc++) {
            uint32_t co_a = (uint32_t)(((2 * kc + hi16) ^ qsw) << 4);
            uint32_t ah[4];
            ldsm4(ah[0], ah[1], ah[2], ah[3], QH + qrow + co_a);
#pragma unroll
            for (int nt = 0; nt < 4; nt++) {   // consume K frags immediately
                int r = nt * 16 + l15;
                uint32_t co = (uint32_t)(((2 * kc + hi16) ^ (r & 7)) << 4);
                uint32_t t0, t1, t2, t3;
                ldsm4(t0, t1, t2, t3, sb + r * 128 + co);
                mma16816(sa[2 * nt],     ah, t0, t2);
                mma16816(sa[2 * nt + 1], ah, t1, t3);
            }
        }

        // ---- online softmax ---------------------------------------------------
#pragma unroll
        for (int half = 0; half < 2; half++) {
            float mx = -1e30f;
#pragma unroll
            for (int j = 0; j < 8; j++) {
                sa[j][2 * half]     *= 0.125f;
                sa[j][2 * half + 1] *= 0.125f;
                mx = fmaxf(mx, fmaxf(sa[j][2 * half], sa[j][2 * half + 1]));
            }
            mx = fmaxf(mx, __shfl_xor_sync(0xffffffffu, mx, 1));
            mx = fmaxf(mx, __shfl_xor_sync(0xffffffffu, mx, 2));
            float nm    = fmaxf(m2[half], mx);
            float alpha = __expf(m2[half] - nm);
            float rs = 0.f;
#pragma unroll
            for (int j = 0; j < 8; j++) {
                sa[j][2 * half]     = __expf(sa[j][2 * half]     - nm);
                sa[j][2 * half + 1] = __expf(sa[j][2 * half + 1] - nm);
                rs += sa[j][2 * half] + sa[j][2 * half + 1];
            }
            rs += __shfl_xor_sync(0xffffffffu, rs, 1);
            rs += __shfl_xor_sync(0xffffffffu, rs, 2);
            l2[half] = l2[half] * alpha + rs;
            m2[half] = nm;
#pragma unroll
            for (int j = 0; j < 8; j++) {
                oa[j][2 * half]     *= alpha;
                oa[j][2 * half + 1] *= alpha;
            }
        }

        // ---- O += P V; P frags built per-kc, V frags consumed immediately -------
#pragma unroll
        for (int kc = 0; kc < 4; kc++) {
            uint32_t ph[4];
            int j0 = 2 * kc, j1 = 2 * kc + 1;
            ph[0] = pack2h(sa[j0][0], sa[j0][1]);
            ph[1] = pack2h(sa[j0][2], sa[j0][3]);
            ph[2] = pack2h(sa[j1][0], sa[j1][1]);
            ph[3] = pack2h(sa[j1][2], sa[j1][3]);
            int rowt = kc * 16 + rsel;
#pragma unroll
            for (int jt = 0; jt < 4; jt++) {
                int c8 = jt * 2 + b3;
                uint32_t ad = sb + 8192 + rowt * 128 + (uint32_t)((c8 ^ (rowt & 7)) << 4);
                uint32_t t0, t1, t2, t3;
                ldsm4t(t0, t1, t2, t3, ad);
                mma16816(oa[2 * jt],     ph, t0, t2);
                mma16816(oa[2 * jt + 1], ph, t1, t3);
            }
        }
    }

    // ---- epilogue ---------------------------------------------------------------
    float inv0 = 1.f / l2[0];
    float inv1 = 1.f / l2[1];
    int r0 = q0 + wq * 16 + (lane >> 2);
#pragma unroll
    for (int j = 0; j < 8; j++) {
        int col = h * 64 + j * 8 + (lane & 3) * 2;
        size_t g0 = (tokbase + r0) * 1024 + col;
        size_t g1 = (tokbase + r0 + 8) * 1024 + col;
        *reinterpret_cast<uint32_t*>(oh + g0) = pack2h(oa[j][0] * inv0, oa[j][1] * inv0);
        *reinterpret_cast<uint32_t*>(oh + g1) = pack2h(oa[j][2] * inv1, oa[j][3] * inv1);
    }
}

// ---------------- layernorm -----------------------------------------------------
__global__ __launch_bounds__(256) void ln_kernel(const float* __restrict__ in,
                                                 const float* __restrict__ gamma,
                                                 const float* __restrict__ beta,
                                                 float* __restrict__ outF,
                                                 __half* __restrict__ outH)
{
    const int row = blockIdx.x, tid = threadIdx.x;
    const float* p = in + (size_t)row * 1024;
    float4 v = *(const float4*)(p + tid * 4);
    float s  = v.x + v.y + v.z + v.w;
    float ss = v.x * v.x + v.y * v.y + v.z * v.z + v.w * v.w;
#pragma unroll
    for (int off = 16; off > 0; off >>= 1) {
        s  += __shfl_xor_sync(0xffffffffu, s,  off);
        ss += __shfl_xor_sync(0xffffffffu, ss, off);
    }
    __shared__ float sb[8], ssb[8];
    __shared__ float smu, sinv;
    if ((tid & 31) == 0) { sb[tid >> 5] = s; ssb[tid >> 5] = ss; }
    __syncthreads();
    if (tid == 0) {
        float S = 0.f, SS = 0.f;
#pragma unroll
        for (int i = 0; i < 8; i++) { S += sb[i]; SS += ssb[i]; }
        float mu  = S * (1.f / 1024.f);
        float var = SS * (1.f / 1024.f) - mu * mu;
        smu = mu; sinv = rsqrtf(var + 1e-5f);
    }
    __syncthreads();
    float mu = smu, inv = sinv;
    float4 g = *(const float4*)(gamma + tid * 4);
    float4 b = *(const float4*)(beta  + tid * 4);
    float4 o;
    o.x = (v.x - mu) * inv * g.x + b.x;
    o.y = (v.y - mu) * inv * g.y + b.y;
    o.z = (v.z - mu) * inv * g.z + b.z;
    o.w = (v.w - mu) * inv * g.w + b.w;
    size_t idx = (size_t)row * 1024 + tid * 4;
    *(float4*)&outF[idx] = o;
    if (outH) {
        *reinterpret_cast<uint32_t*>(outH + idx)     = pack2h(o.x, o.y);
        *reinterpret_cast<uint32_t*>(outH + idx + 2) = pack2h(o.z, o.w);
    }
}

// ---------------- launch ----------------------------------------------------------
extern "C" void kernel_launch(void* const* d_in, const int* in_sizes, int n_in,
                              void* d_out, int out_size)
{
    const float* x     = (const float*)d_in[0];
    const float* Wq    = (const float*)d_in[1];
    const float* Wk    = (const float*)d_in[2];
    const float* Wv    = (const float*)d_in[3];
    const float* Wo    = (const float*)d_in[4];
    const float* ln1_g = (const float*)d_in[5];
    const float* ln1_b = (const float*)d_in[6];
    const float* W1    = (const float*)d_in[7];
    const float* b1    = (const float*)d_in[8];
    const float* W2    = (const float*)d_in[9];
    const float* b2    = (const float*)d_in[10];
    const float* ln2_g = (const float*)d_in[11];
    const float* ln2_b = (const float*)d_in[12];
    float* out = (float*)d_out;

    cudaFuncSetAttribute(gemm_mma,   cudaFuncAttributeMaxDynamicSharedMemorySize, GEMM_SMEM);
    cudaFuncSetAttribute(flash_hmma, cudaFuncAttributeMaxDynamicSharedMemorySize, ATT_SMEM);

    float *t1, *x1, *t2;
    __half *wqkvh, *xh, *qkvh, *oh, *woh, *x1h, *w1h, *hh, *w2h;
    cudaGetSymbolAddress((void**)&t1,    g_t1);
    cudaGetSymbolAddress((void**)&x1,    g_x1);
    cudaGetSymbolAddress((void**)&t2,    g_t2);
    cudaGetSymbolAddress((void**)&wqkvh, g_wqkvh);
    cudaGetSymbolAddress((void**)&xh,    g_xh);
    cudaGetSymbolAddress((void**)&qkvh,  g_qkvh);
    cudaGetSymbolAddress((void**)&oh,    g_oh);
    cudaGetSymbolAddress((void**)&woh,   g_woh);
    cudaGetSymbolAddress((void**)&x1h,   g_x1h);
    cudaGetSymbolAddress((void**)&w1h,   g_w1h);
    cudaGetSymbolAddress((void**)&hh,    g_hh);
    cudaGetSymbolAddress((void**)&w2h,   g_w2h);

    // 0. fused weight/activation prep (one launch)
    prep_all<<<12800, 256>>>(Wq, Wk, Wv, wqkvh, Wo, woh, W1, w1h, W2, w2h, x, xh);

    // 1. QKV projection -> qkv fp16
    gemm_mma<<<dim3(24, 32), 256, GEMM_SMEM>>>(xh, wqkvh, 4096, 3072, 1024,
                                               nullptr, nullptr, 0, nullptr, qkvh);
    // 2. flash attention -> o fp16 (64-row Q tiles, occ4)
    flash_hmma<<<dim3(32, NH, BATCH), 128, ATT_SMEM>>>(qkvh, oh);
    // 3. output projection + residual x -> t1 fp32
    gemm_mma<<<dim3(8, 32), 256, GEMM_SMEM>>>(oh, woh, 4096, 1024, 1024,
                                              nullptr, x, 0, t1, nullptr);
    // 4. LN1 -> x1 fp32 + fp16
    ln_kernel<<<4096, 256>>>(t1, ln1_g, ln1_b, x1, x1h);
    // 5. FFN up + bias + relu -> h fp16
    gemm_mma<<<dim3(32, 32), 256, GEMM_SMEM>>>(x1h, w1h, 4096, 4096, 1024,
                                               b1, nullptr, 1, nullptr, hh);
    // 6. FFN down + bias + residual x1 -> t2 fp32
    gemm_mma<<<dim3(8, 32), 256, GEMM_SMEM>>>(hh, w2h, 4096, 1024, 4096,
                                              b2, x1, 0, t2, nullptr);
    // 7. LN2 -> out
    ln_kernel<<<4096, 256>>>(t2, ln2_g, ln2_b, out, nullptr);
}